// round 5
// baseline (speedup 1.0000x reference)
#include <cuda_runtime.h>
#include <cuda_bf16.h>
#include <stdint.h>
#include <math.h>

// Problem constants
#define TT 2048      // tokens (B*S)
#define HH 768       // hidden
#define II 1536      // intermediate
#define EE 8         // experts
#define KK 2         // top-k
#define CAP 768      // capacity
#define SLOTS (KK*CAP)   // 1536 slot rows per expert

// ---------------- scratch (device globals; allocation-free) ----------------
__device__ float g_importance[EE];
__device__ int   g_topk_idx[TT * KK];
__device__ float g_topk_w[TT * KK];
__device__ int   g_slot[TT * KK];
__device__ int   g_list[EE * SLOTS];
__device__ int   g_cnt[KK * EE];
__device__ int   g_keptcnt[EE];
__device__ float g_dropped;
__device__ float g_hbuf[EE * SLOTS * II];        // SwiGLU intermediate, tf32 bits (~75MB)
__device__ float g_ybuf[EE * SLOTS * HH];        // expert outputs    (~38MB)

// ---------------- PTX helpers ----------------
__device__ __forceinline__ uint32_t s2u(const void* p) {
    uint32_t a;
    asm("{ .reg .u64 t; cvta.to.shared.u64 t, %1; cvt.u32.u64 %0, t; }" : "=r"(a) : "l"(p));
    return a;
}
__device__ __forceinline__ void cpa16(uint32_t dst, const void* src) {
    asm volatile("cp.async.cg.shared.global [%0], [%1], 16;" :: "r"(dst), "l"(src));
}
__device__ __forceinline__ void cpa_commit() { asm volatile("cp.async.commit_group;" ::: "memory"); }
template<int N> __device__ __forceinline__ void cpa_wait() {
    asm volatile("cp.async.wait_group %0;" :: "n"(N) : "memory");
}
__device__ __forceinline__ uint32_t f2tf(float f) {
    uint32_t r; asm("cvt.rna.tf32.f32 %0, %1;" : "=r"(r) : "f"(f)); return r;
}
__device__ __forceinline__ float ubits(float f) { return f; }
__device__ __forceinline__ void mma8(float* d, const uint32_t* a, const uint32_t* b) {
    asm volatile(
        "mma.sync.aligned.m16n8k8.row.col.f32.tf32.tf32.f32 "
        "{%0,%1,%2,%3}, {%4,%5,%6,%7}, {%8,%9}, {%0,%1,%2,%3};"
        : "+f"(d[0]), "+f"(d[1]), "+f"(d[2]), "+f"(d[3])
        : "r"(a[0]), "r"(a[1]), "r"(a[2]), "r"(a[3]), "r"(b[0]), "r"(b[1]));
}

// convert a float4 in SMEM to tf32 bits in place
__device__ __forceinline__ void cvt4_inplace(float* p) {
    float4 v = *(float4*)p;
    uint4 o;
    o.x = f2tf(v.x); o.y = f2tf(v.y); o.z = f2tf(v.z); o.w = f2tf(v.w);
    *(uint4*)p = o;
}

// ---------------- zero ----------------
__global__ void zero_kernel() {
    if (threadIdx.x < EE) g_importance[threadIdx.x] = 0.0f;
}

// ---------------- routing ----------------
__global__ void routing_kernel(const float* __restrict__ x,
                               const float* __restrict__ wg) {
    int t = blockIdx.x;
    __shared__ float sx[HH];
    __shared__ float slog[EE];
    int tid = threadIdx.x;
    for (int i = tid; i < HH; i += 256) sx[i] = x[t * HH + i];
    __syncthreads();
    int warp = tid >> 5, lane = tid & 31;
    float sum = 0.0f;
    for (int j = lane; j < HH; j += 32) sum += sx[j] * wg[j * EE + warp];
    for (int o = 16; o; o >>= 1) sum += __shfl_xor_sync(0xffffffffu, sum, o);
    if (lane == 0) slog[warp] = sum;
    __syncthreads();
    if (tid == 0) {
        float mx = slog[0];
        for (int e = 1; e < EE; e++) mx = fmaxf(mx, slog[e]);
        float p[EE], s = 0.0f;
        for (int e = 0; e < EE; e++) { p[e] = expf(slog[e] - mx); s += p[e]; }
        for (int e = 0; e < EE; e++) p[e] /= s;
        int e0 = 0;
        for (int e = 1; e < EE; e++) if (p[e] > p[e0]) e0 = e;
        int e1 = -1;
        for (int e = 0; e < EE; e++) {
            if (e == e0) continue;
            if (e1 < 0 || p[e] > p[e1]) e1 = e;
        }
        float ps = p[e0] + p[e1] + 1e-8f;
        float w0 = fminf(fmaxf(p[e0] / ps, 1e-8f), 10.0f);
        float w1 = fminf(fmaxf(p[e1] / ps, 1e-8f), 10.0f);
        g_topk_idx[t * 2 + 0] = e0;
        g_topk_idx[t * 2 + 1] = e1;
        g_topk_w[t * 2 + 0] = w0;
        g_topk_w[t * 2 + 1] = w1;
        for (int e = 0; e < EE; e++) atomicAdd(&g_importance[e], p[e]);
    }
}

// ---------------- scan ----------------
__global__ void scan_kernel() {
    __shared__ int warp_cnt[32][EE];
    __shared__ int warp_pref[32][EE];
    __shared__ int running[EE];
    __shared__ int chunk_tot[EE];
    __shared__ int tot[KK][EE];
    int tid = threadIdx.x, lane = tid & 31, warp = tid >> 5;

    for (int k = 0; k < KK; k++) {
        if (tid < EE) running[tid] = 0;
        __syncthreads();
        for (int chunk = 0; chunk < TT / 1024; chunk++) {
            int t = chunk * 1024 + tid;
            int e = g_topk_idx[t * 2 + k];
            unsigned mask = __match_any_sync(0xffffffffu, e);
            int lane_pref = __popc(mask & ((1u << lane) - 1));
            int warp_total = __popc(mask);
            if (tid < 32 * EE) warp_cnt[tid / EE][tid % EE] = 0;
            __syncthreads();
            if (lane_pref == 0) warp_cnt[warp][e] = warp_total;
            __syncthreads();
            if (tid < 32 * EE) {
                int w = tid / EE, ee = tid % EE;
                int p = 0;
                for (int ww = 0; ww < w; ww++) p += warp_cnt[ww][ee];
                warp_pref[w][ee] = p;
                if (w == 31) chunk_tot[ee] = p + warp_cnt[31][ee];
            }
            __syncthreads();
            int rank = running[e] + warp_pref[warp][e] + lane_pref + 1;
            bool kept = (rank <= CAP);
            int slot = kept ? (k * CAP + rank - 1) : -1;
            g_slot[t * 2 + k] = slot;
            if (kept) g_list[e * SLOTS + slot] = t;
            __syncthreads();
            if (tid < EE) running[tid] += chunk_tot[tid];
            __syncthreads();
        }
        if (tid < EE) tot[k][tid] = running[tid];
        __syncthreads();
    }
    if (tid == 0) {
        int drop = 0;
        for (int e = 0; e < EE; e++) {
            int c0 = min(tot[0][e], CAP), c1 = min(tot[1][e], CAP);
            g_cnt[0 * EE + e] = c0;
            g_cnt[1 * EE + e] = c1;
            g_keptcnt[e] = c0 + c1;
            drop += (tot[0][e] - c0) + (tot[1][e] - c1);
        }
        g_dropped = (float)drop;
    }
}

// ================ GEMM1: mma.sync tf32, fused SwiGLU ================
// CTA: M=128 slots x N=256 (128 w1-cols + 128 w3-cols). 512 threads, 16 warps.
// warpM = w>>3 (2), warpN = w&7 (8). Warp: 64 rows x (16 G-cols + 16 U-cols).
// SMEM floats: As[2][128*36], Bs[2][32*264], stok[128]
#define APITCH 36
#define BPITCH 264
#define G1_SMEM ((2*128*APITCH + 2*32*BPITCH) * 4 + 512)
__global__ void __launch_bounds__(512, 1) gemm1_mma(const float* __restrict__ x,
                                                    const float* __restrict__ w1,
                                                    const float* __restrict__ w3) {
    extern __shared__ float s[];
    float* As = s;                        // 2 x 4608
    float* Bs = s + 2 * 128 * APITCH;     // 2 x 8448
    int* stok = (int*)(Bs + 2 * 32 * BPITCH);

    int e = blockIdx.z, by = blockIdx.y, bx = blockIdx.x;
    int kslot = (by >= 6) ? 1 : 0;
    int cnt = g_cnt[kslot * EE + e];
    int tile0 = (by - kslot * 6) * 128;
    if (tile0 >= cnt) return;
    int valid = min(128, cnt - tile0);
    int slot0 = by * 128;
    int tid = threadIdx.x;
    int lane = tid & 31, w = tid >> 5;
    int warpM = w >> 3, warpN = w & 7;

    if (tid < 128)
        stok[tid] = (tid < valid) ? g_list[e * SLOTS + slot0 + tid]
                                  : g_list[e * SLOTS + slot0];
    __syncthreads();

    const float* w1b = w1 + (size_t)e * HH * II + bx * 128;
    const float* w3b = w3 + (size_t)e * HH * II + bx * 128;

    auto fill = [&](int buf, int c) {
        uint32_t au = s2u(As + buf * 128 * APITCH);
        uint32_t bu_ = s2u(Bs + buf * 32 * BPITCH);
        int k0 = c * 32;
#pragma unroll
        for (int i = tid; i < 1024; i += 512) {
            int row = i >> 3, seg = i & 7;
            cpa16(au + (uint32_t)(row * APITCH + seg * 4) * 4,
                  x + (size_t)stok[row] * HH + k0 + seg * 4);
        }
#pragma unroll
        for (int i = tid; i < 2048; i += 512) {
            int k = i >> 6, seg = i & 63;
            const float* src = (seg < 32) ? (w1b + (size_t)(k0 + k) * II + seg * 4)
                                          : (w3b + (size_t)(k0 + k) * II + (seg - 32) * 4);
            int dc = (seg < 32) ? seg * 4 : 128 + (seg - 32) * 4;
            cpa16(bu_ + (uint32_t)(k * BPITCH + dc) * 4, src);
        }
    };

    // in-SMEM tf32 conversion for buffer `buf`
    auto cvtbuf = [&](int buf) {
        float* A = As + buf * 128 * APITCH;
        float* B = Bs + buf * 32 * BPITCH;
#pragma unroll
        for (int i = tid; i < 1024; i += 512) {
            int row = i >> 3, seg = i & 7;
            cvt4_inplace(A + row * APITCH + seg * 4);
        }
#pragma unroll
        for (int i = tid; i < 2048; i += 512) {
            int k = i >> 6, seg = i & 63;
            cvt4_inplace(B + k * BPITCH + seg * 4);
        }
    };

    fill(0, 0); cpa_commit();
    float accG[4][2][4] = {}, accU[4][2][4] = {};
    const int NC = HH / 32; // 24
    for (int c = 0; c < NC; c++) {
        int b = c & 1;
        if (c + 1 < NC) { fill(b ^ 1, c + 1); cpa_commit(); cpa_wait<1>(); }
        else { cpa_wait<0>(); }
        __syncthreads();
        cvtbuf(b);
        __syncthreads();
        const float* A = As + b * 128 * APITCH;
        const float* B = Bs + b * 32 * BPITCH;
#pragma unroll
        for (int ks = 0; ks < 4; ks++) {
            int kc = ks * 8 + (lane & 3);
            int r0 = warpM * 64 + (lane >> 2);
            uint32_t af[4][4];
#pragma unroll
            for (int mf = 0; mf < 4; mf++) {
                int r = r0 + mf * 16;
                af[mf][0] = __float_as_uint(A[r * APITCH + kc]);
                af[mf][1] = __float_as_uint(A[(r + 8) * APITCH + kc]);
                af[mf][2] = __float_as_uint(A[r * APITCH + kc + 4]);
                af[mf][3] = __float_as_uint(A[(r + 8) * APITCH + kc + 4]);
            }
            int bn = warpN * 16 + (lane >> 2);
            uint32_t bg[2][2], bu2[2][2];
#pragma unroll
            for (int nf = 0; nf < 2; nf++) {
                bg[nf][0]  = __float_as_uint(B[kc * BPITCH + bn + nf * 8]);
                bg[nf][1]  = __float_as_uint(B[(kc + 4) * BPITCH + bn + nf * 8]);
                bu2[nf][0] = __float_as_uint(B[kc * BPITCH + 128 + bn + nf * 8]);
                bu2[nf][1] = __float_as_uint(B[(kc + 4) * BPITCH + 128 + bn + nf * 8]);
            }
#pragma unroll
            for (int mf = 0; mf < 4; mf++)
#pragma unroll
                for (int nf = 0; nf < 2; nf++) {
                    mma8(accG[mf][nf], af[mf], bg[nf]);
                    mma8(accU[mf][nf], af[mf], bu2[nf]);
                }
        }
        __syncthreads();
    }

    // epilogue: SwiGLU, write hbuf as tf32 bits (gemm2 consumes bits directly)
#pragma unroll
    for (int mf = 0; mf < 4; mf++) {
        int rbase = warpM * 64 + mf * 16 + (lane >> 2);
#pragma unroll
        for (int nf = 0; nf < 2; nf++) {
            int col = bx * 128 + warpN * 16 + nf * 8 + 2 * (lane & 3);
#pragma unroll
            for (int h = 0; h < 2; h++) {
                int r = rbase + h * 8;
                if (r < valid) {
                    float g0 = accG[mf][nf][h * 2 + 0], g1 = accG[mf][nf][h * 2 + 1];
                    float u0 = accU[mf][nf][h * 2 + 0], u1 = accU[mf][nf][h * 2 + 1];
                    float2 o;
                    o.x = __uint_as_float(f2tf(g0 / (1.0f + expf(-g0)) * u0));
                    o.y = __uint_as_float(f2tf(g1 / (1.0f + expf(-g1)) * u1));
                    *(float2*)&g_hbuf[((size_t)e * SLOTS + slot0 + r) * II + col] = o;
                }
            }
        }
    }
}

// ================ GEMM2: mma.sync tf32 ================
// CTA: M=128 slots x N=256 H-cols. 512 threads. warp: 64 x 32.
// A (hbuf) already holds tf32 bits; only B needs conversion.
#define G2_SMEM ((2*128*APITCH + 2*32*BPITCH) * 4)
__global__ void __launch_bounds__(512, 1) gemm2_mma(const float* __restrict__ w2) {
    extern __shared__ float s[];
    float* As = s;
    float* Bs = s + 2 * 128 * APITCH;

    int e = blockIdx.z, by = blockIdx.y, bx = blockIdx.x; // bx 0..2
    int kslot = (by >= 6) ? 1 : 0;
    int cnt = g_cnt[kslot * EE + e];
    int tile0 = (by - kslot * 6) * 128;
    if (tile0 >= cnt) return;
    int valid = min(128, cnt - tile0);
    int slot0 = by * 128;
    int tid = threadIdx.x;
    int lane = tid & 31, w = tid >> 5;
    int warpM = w >> 3, warpN = w & 7;

    const float* Ab = g_hbuf + ((size_t)e * SLOTS + slot0) * II;
    const float* Bb = w2 + (size_t)e * II * HH + bx * 256;

    auto fill = [&](int buf, int c) {
        uint32_t au = s2u(As + buf * 128 * APITCH);
        uint32_t bu_ = s2u(Bs + buf * 32 * BPITCH);
        int k0 = c * 32;
#pragma unroll
        for (int i = tid; i < 1024; i += 512) {
            int row = i >> 3, seg = i & 7;
            cpa16(au + (uint32_t)(row * APITCH + seg * 4) * 4,
                  Ab + (size_t)row * II + k0 + seg * 4);
        }
#pragma unroll
        for (int i = tid; i < 2048; i += 512) {
            int k = i >> 6, seg = i & 63;
            cpa16(bu_ + (uint32_t)(k * BPITCH + seg * 4) * 4,
                  Bb + (size_t)(k0 + k) * HH + seg * 4);
        }
    };

    auto cvtbufB = [&](int buf) {
        float* B = Bs + buf * 32 * BPITCH;
#pragma unroll
        for (int i = tid; i < 2048; i += 512) {
            int k = i >> 6, seg = i & 63;
            cvt4_inplace(B + k * BPITCH + seg * 4);
        }
    };

    fill(0, 0); cpa_commit();
    float acc[4][4][4] = {};
    const int NC = II / 32; // 48
    for (int c = 0; c < NC; c++) {
        int b = c & 1;
        if (c + 1 < NC) { fill(b ^ 1, c + 1); cpa_commit(); cpa_wait<1>(); }
        else { cpa_wait<0>(); }
        __syncthreads();
        cvtbufB(b);
        __syncthreads();
        const float* A = As + b * 128 * APITCH;
        const float* B = Bs + b * 32 * BPITCH;
#pragma unroll
        for (int ks = 0; ks < 4; ks++) {
            int kc = ks * 8 + (lane & 3);
            int r0 = warpM * 64 + (lane >> 2);
            uint32_t af[4][4];
#pragma unroll
            for (int mf = 0; mf < 4; mf++) {
                int r = r0 + mf * 16;
                af[mf][0] = __float_as_uint(A[r * APITCH + kc]);
                af[mf][1] = __float_as_uint(A[(r + 8) * APITCH + kc]);
                af[mf][2] = __float_as_uint(A[r * APITCH + kc + 4]);
                af[mf][3] = __float_as_uint(A[(r + 8) * APITCH + kc + 4]);
            }
            int bn = warpN * 32 + (lane >> 2);
            uint32_t bf[4][2];
#pragma unroll
            for (int nf = 0; nf < 4; nf++) {
                bf[nf][0] = __float_as_uint(B[kc * BPITCH + bn + nf * 8]);
                bf[nf][1] = __float_as_uint(B[(kc + 4) * BPITCH + bn + nf * 8]);
            }
#pragma unroll
            for (int mf = 0; mf < 4; mf++)
#pragma unroll
                for (int nf = 0; nf < 4; nf++)
                    mma8(acc[mf][nf], af[mf], bf[nf]);
        }
        __syncthreads();
    }

#pragma unroll
    for (int mf = 0; mf < 4; mf++) {
        int rbase = warpM * 64 + mf * 16 + (lane >> 2);
#pragma unroll
        for (int nf = 0; nf < 4; nf++) {
            int col = bx * 256 + warpN * 32 + nf * 8 + 2 * (lane & 3);
#pragma unroll
            for (int h = 0; h < 2; h++) {
                int r = rbase + h * 8;
                if (r < valid) {
                    float2 o;
                    o.x = acc[mf][nf][h * 2 + 0];
                    o.y = acc[mf][nf][h * 2 + 1];
                    *(float2*)&g_ybuf[((size_t)e * SLOTS + slot0 + r) * HH + col] = o;
                }
            }
        }
    }
}

// ---------------- combine ----------------
__global__ void combine_kernel(float* __restrict__ out) {
    int t = blockIdx.x;
    __shared__ int se[2], ss[2];
    __shared__ float sw[2];
    if (threadIdx.x < 2) {
        se[threadIdx.x] = g_topk_idx[t * 2 + threadIdx.x];
        ss[threadIdx.x] = g_slot[t * 2 + threadIdx.x];
        sw[threadIdx.x] = g_topk_w[t * 2 + threadIdx.x];
    }
    __syncthreads();
    for (int h = threadIdx.x; h < HH; h += 256) {
        float v = 0.0f;
        if (ss[0] >= 0) v += sw[0] * g_ybuf[((size_t)se[0] * SLOTS + ss[0]) * HH + h];
        if (ss[1] >= 0) v += sw[1] * g_ybuf[((size_t)se[1] * SLOTS + ss[1]) * HH + h];
        out[(size_t)t * HH + h] = v;
    }
}

// ---------------- aux ----------------
__global__ void aux_kernel(float* __restrict__ out, int out_size) {
    if (out_size < TT * HH + 1) return;
    float a = 0.0f;
    for (int e = 0; e < EE; e++) {
        float usage = (float)g_keptcnt[e] / (float)(TT * KK);
        float imp = g_importance[e] / (float)TT;
        a += usage * imp;
    }
    a *= (float)EE;
    if (g_dropped > 0.0f) a += g_dropped / (float)TT * 0.1f;
    a = fminf(a, 1.0f) * 0.001f;
    out[TT * HH] = a;
}

// ---------------- launch ----------------
extern "C" void kernel_launch(void* const* d_in, const int* in_sizes, int n_in,
                              void* d_out, int out_size) {
    const float* x      = (const float*)d_in[0];
    const float* w_gate = (const float*)d_in[1];
    const float* w1     = (const float*)d_in[2];
    const float* w3     = (const float*)d_in[3];
    const float* w2     = (const float*)d_in[4];
    float* out = (float*)d_out;

    cudaFuncSetAttribute(gemm1_mma, cudaFuncAttributeMaxDynamicSharedMemorySize, G1_SMEM);
    cudaFuncSetAttribute(gemm2_mma, cudaFuncAttributeMaxDynamicSharedMemorySize, G2_SMEM);

    zero_kernel<<<1, 32>>>();
    routing_kernel<<<TT, 256>>>(x, w_gate);
    scan_kernel<<<1, 1024>>>();
    gemm1_mma<<<dim3(II / 128, SLOTS / 128, EE), 512, G1_SMEM>>>(x, w1, w3);
    gemm2_mma<<<dim3(HH / 256, SLOTS / 128, EE), 512, G2_SMEM>>>(w2);
    combine_kernel<<<TT, 256>>>(out);
    aux_kernel<<<1, 1>>>(out, out_size);
}

// round 6
// speedup vs baseline: 1.0785x; 1.0785x over previous
#include <cuda_runtime.h>
#include <cuda_bf16.h>
#include <stdint.h>
#include <math.h>

// Problem constants
#define TT 2048      // tokens (B*S)
#define HH 768       // hidden
#define II 1536      // intermediate
#define EE 8         // experts
#define KK 2         // top-k
#define CAP 768      // capacity
#define SLOTS (KK*CAP)   // 1536 slot rows per expert

// ---------------- scratch (device globals; allocation-free) ----------------
__device__ float g_importance[EE];
__device__ int   g_topk_idx[TT * KK];
__device__ float g_topk_w[TT * KK];
__device__ int   g_slot[TT * KK];
__device__ int   g_list[EE * SLOTS];
__device__ int   g_cnt[KK * EE];
__device__ int   g_keptcnt[EE];
__device__ float g_dropped;
__device__ float g_xtf[TT * HH];                 // x as tf32 bits (6MB)
__device__ float g_w1tf[EE * HH * II];           // w1 as tf32 bits (~38MB)
__device__ float g_w3tf[EE * HH * II];           // w3 as tf32 bits (~38MB)
__device__ float g_w2tf[EE * II * HH];           // w2 as tf32 bits (~38MB)
__device__ float g_hbuf[EE * SLOTS * II];        // SwiGLU intermediate, tf32 bits (~75MB)
__device__ float g_ybuf[EE * SLOTS * HH];        // expert outputs    (~38MB)

// ---------------- PTX helpers ----------------
__device__ __forceinline__ uint32_t s2u(const void* p) {
    uint32_t a;
    asm("{ .reg .u64 t; cvta.to.shared.u64 t, %1; cvt.u32.u64 %0, t; }" : "=r"(a) : "l"(p));
    return a;
}
__device__ __forceinline__ void cpa16(uint32_t dst, const void* src) {
    asm volatile("cp.async.cg.shared.global [%0], [%1], 16;" :: "r"(dst), "l"(src));
}
__device__ __forceinline__ void cpa_commit() { asm volatile("cp.async.commit_group;" ::: "memory"); }
template<int N> __device__ __forceinline__ void cpa_wait() {
    asm volatile("cp.async.wait_group %0;" :: "n"(N) : "memory");
}
__device__ __forceinline__ uint32_t f2tf(float f) {
    uint32_t r; asm("cvt.rna.tf32.f32 %0, %1;" : "=r"(r) : "f"(f)); return r;
}
__device__ __forceinline__ void mma8(float* d, const uint32_t* a, const uint32_t* b) {
    asm volatile(
        "mma.sync.aligned.m16n8k8.row.col.f32.tf32.tf32.f32 "
        "{%0,%1,%2,%3}, {%4,%5,%6,%7}, {%8,%9}, {%0,%1,%2,%3};"
        : "+f"(d[0]), "+f"(d[1]), "+f"(d[2]), "+f"(d[3])
        : "r"(a[0]), "r"(a[1]), "r"(a[2]), "r"(a[3]), "r"(b[0]), "r"(b[1]));
}

// ---------------- tf32 pre-convert (memory-bound, float4) ----------------
__global__ void cvt_kernel(const float4* __restrict__ src, float4* __restrict__ dst, int n4) {
    int i = blockIdx.x * blockDim.x + threadIdx.x;
    if (i < n4) {
        float4 v = src[i];
        uint4 o;
        o.x = f2tf(v.x); o.y = f2tf(v.y); o.z = f2tf(v.z); o.w = f2tf(v.w);
        dst[i] = *(float4*)&o;
    }
}

// ---------------- zero ----------------
__global__ void zero_kernel() {
    if (threadIdx.x < EE) g_importance[threadIdx.x] = 0.0f;
}

// ---------------- routing ----------------
__global__ void routing_kernel(const float* __restrict__ x,
                               const float* __restrict__ wg) {
    int t = blockIdx.x;
    __shared__ float sx[HH];
    __shared__ float slog[EE];
    int tid = threadIdx.x;
    for (int i = tid; i < HH; i += 256) sx[i] = x[t * HH + i];
    __syncthreads();
    int warp = tid >> 5, lane = tid & 31;
    float sum = 0.0f;
    for (int j = lane; j < HH; j += 32) sum += sx[j] * wg[j * EE + warp];
    for (int o = 16; o; o >>= 1) sum += __shfl_xor_sync(0xffffffffu, sum, o);
    if (lane == 0) slog[warp] = sum;
    __syncthreads();
    if (tid == 0) {
        float mx = slog[0];
        for (int e = 1; e < EE; e++) mx = fmaxf(mx, slog[e]);
        float p[EE], s = 0.0f;
        for (int e = 0; e < EE; e++) { p[e] = expf(slog[e] - mx); s += p[e]; }
        for (int e = 0; e < EE; e++) p[e] /= s;
        int e0 = 0;
        for (int e = 1; e < EE; e++) if (p[e] > p[e0]) e0 = e;
        int e1 = -1;
        for (int e = 0; e < EE; e++) {
            if (e == e0) continue;
            if (e1 < 0 || p[e] > p[e1]) e1 = e;
        }
        float ps = p[e0] + p[e1] + 1e-8f;
        float w0 = fminf(fmaxf(p[e0] / ps, 1e-8f), 10.0f);
        float w1 = fminf(fmaxf(p[e1] / ps, 1e-8f), 10.0f);
        g_topk_idx[t * 2 + 0] = e0;
        g_topk_idx[t * 2 + 1] = e1;
        g_topk_w[t * 2 + 0] = w0;
        g_topk_w[t * 2 + 1] = w1;
        for (int e = 0; e < EE; e++) atomicAdd(&g_importance[e], p[e]);
    }
}

// ---------------- scan ----------------
__global__ void scan_kernel() {
    __shared__ int warp_cnt[32][EE];
    __shared__ int warp_pref[32][EE];
    __shared__ int running[EE];
    __shared__ int chunk_tot[EE];
    __shared__ int tot[KK][EE];
    int tid = threadIdx.x, lane = tid & 31, warp = tid >> 5;

    for (int k = 0; k < KK; k++) {
        if (tid < EE) running[tid] = 0;
        __syncthreads();
        for (int chunk = 0; chunk < TT / 1024; chunk++) {
            int t = chunk * 1024 + tid;
            int e = g_topk_idx[t * 2 + k];
            unsigned mask = __match_any_sync(0xffffffffu, e);
            int lane_pref = __popc(mask & ((1u << lane) - 1));
            int warp_total = __popc(mask);
            if (tid < 32 * EE) warp_cnt[tid / EE][tid % EE] = 0;
            __syncthreads();
            if (lane_pref == 0) warp_cnt[warp][e] = warp_total;
            __syncthreads();
            if (tid < 32 * EE) {
                int w = tid / EE, ee = tid % EE;
                int p = 0;
                for (int ww = 0; ww < w; ww++) p += warp_cnt[ww][ee];
                warp_pref[w][ee] = p;
                if (w == 31) chunk_tot[ee] = p + warp_cnt[31][ee];
            }
            __syncthreads();
            int rank = running[e] + warp_pref[warp][e] + lane_pref + 1;
            bool kept = (rank <= CAP);
            int slot = kept ? (k * CAP + rank - 1) : -1;
            g_slot[t * 2 + k] = slot;
            if (kept) g_list[e * SLOTS + slot] = t;
            __syncthreads();
            if (tid < EE) running[tid] += chunk_tot[tid];
            __syncthreads();
        }
        if (tid < EE) tot[k][tid] = running[tid];
        __syncthreads();
    }
    if (tid == 0) {
        int drop = 0;
        for (int e = 0; e < EE; e++) {
            int c0 = min(tot[0][e], CAP), c1 = min(tot[1][e], CAP);
            g_cnt[0 * EE + e] = c0;
            g_cnt[1 * EE + e] = c1;
            g_keptcnt[e] = c0 + c1;
            drop += (tot[0][e] - c0) + (tot[1][e] - c1);
        }
        g_dropped = (float)drop;
    }
}

// ================ GEMM1: mma.sync tf32, fused SwiGLU ================
// Operands already tf32 bits in global; hot loop is LDS->MMA only.
// CTA: M=128 slots x N=256 (128 w1-cols + 128 w3-cols). 512 threads, 16 warps.
#define APITCH 36
#define BPITCH 264
#define G1_SMEM ((2*128*APITCH + 2*32*BPITCH) * 4 + 512)
__global__ void __launch_bounds__(512, 1) gemm1_mma() {
    extern __shared__ float s[];
    float* As = s;                        // 2 x 4608
    float* Bs = s + 2 * 128 * APITCH;     // 2 x 8448
    int* stok = (int*)(Bs + 2 * 32 * BPITCH);

    int e = blockIdx.z, by = blockIdx.y, bx = blockIdx.x;
    int kslot = (by >= 6) ? 1 : 0;
    int cnt = g_cnt[kslot * EE + e];
    int tile0 = (by - kslot * 6) * 128;
    if (tile0 >= cnt) return;
    int valid = min(128, cnt - tile0);
    int slot0 = by * 128;
    int tid = threadIdx.x;
    int lane = tid & 31, w = tid >> 5;
    int warpM = w >> 3, warpN = w & 7;

    if (tid < 128)
        stok[tid] = (tid < valid) ? g_list[e * SLOTS + slot0 + tid]
                                  : g_list[e * SLOTS + slot0];
    __syncthreads();

    const float* w1b = g_w1tf + (size_t)e * HH * II + bx * 128;
    const float* w3b = g_w3tf + (size_t)e * HH * II + bx * 128;

    auto fill = [&](int buf, int c) {
        uint32_t au = s2u(As + buf * 128 * APITCH);
        uint32_t bu_ = s2u(Bs + buf * 32 * BPITCH);
        int k0 = c * 32;
#pragma unroll
        for (int i = tid; i < 1024; i += 512) {
            int row = i >> 3, seg = i & 7;
            cpa16(au + (uint32_t)(row * APITCH + seg * 4) * 4,
                  g_xtf + (size_t)stok[row] * HH + k0 + seg * 4);
        }
#pragma unroll
        for (int i = tid; i < 2048; i += 512) {
            int k = i >> 6, seg = i & 63;
            const float* src = (seg < 32) ? (w1b + (size_t)(k0 + k) * II + seg * 4)
                                          : (w3b + (size_t)(k0 + k) * II + (seg - 32) * 4);
            int dc = (seg < 32) ? seg * 4 : 128 + (seg - 32) * 4;
            cpa16(bu_ + (uint32_t)(k * BPITCH + dc) * 4, src);
        }
    };

    fill(0, 0); cpa_commit();
    float accG[4][2][4] = {}, accU[4][2][4] = {};
    const int NC = HH / 32; // 24
    for (int c = 0; c < NC; c++) {
        int b = c & 1;
        if (c + 1 < NC) { fill(b ^ 1, c + 1); cpa_commit(); cpa_wait<1>(); }
        else { cpa_wait<0>(); }
        __syncthreads();
        const float* A = As + b * 128 * APITCH;
        const float* B = Bs + b * 32 * BPITCH;
#pragma unroll
        for (int ks = 0; ks < 4; ks++) {
            int kc = ks * 8 + (lane & 3);
            int r0 = warpM * 64 + (lane >> 2);
            uint32_t af[4][4];
#pragma unroll
            for (int mf = 0; mf < 4; mf++) {
                int r = r0 + mf * 16;
                af[mf][0] = __float_as_uint(A[r * APITCH + kc]);
                af[mf][1] = __float_as_uint(A[(r + 8) * APITCH + kc]);
                af[mf][2] = __float_as_uint(A[r * APITCH + kc + 4]);
                af[mf][3] = __float_as_uint(A[(r + 8) * APITCH + kc + 4]);
            }
            int bn = warpN * 16 + (lane >> 2);
            uint32_t bg[2][2], bu2[2][2];
#pragma unroll
            for (int nf = 0; nf < 2; nf++) {
                bg[nf][0]  = __float_as_uint(B[kc * BPITCH + bn + nf * 8]);
                bg[nf][1]  = __float_as_uint(B[(kc + 4) * BPITCH + bn + nf * 8]);
                bu2[nf][0] = __float_as_uint(B[kc * BPITCH + 128 + bn + nf * 8]);
                bu2[nf][1] = __float_as_uint(B[(kc + 4) * BPITCH + 128 + bn + nf * 8]);
            }
#pragma unroll
            for (int mf = 0; mf < 4; mf++)
#pragma unroll
                for (int nf = 0; nf < 2; nf++) {
                    mma8(accG[mf][nf], af[mf], bg[nf]);
                    mma8(accU[mf][nf], af[mf], bu2[nf]);
                }
        }
        __syncthreads();
    }

    // epilogue: SwiGLU, write hbuf as tf32 bits (gemm2 consumes bits directly)
#pragma unroll
    for (int mf = 0; mf < 4; mf++) {
        int rbase = warpM * 64 + mf * 16 + (lane >> 2);
#pragma unroll
        for (int nf = 0; nf < 2; nf++) {
            int col = bx * 128 + warpN * 16 + nf * 8 + 2 * (lane & 3);
#pragma unroll
            for (int h = 0; h < 2; h++) {
                int r = rbase + h * 8;
                if (r < valid) {
                    float g0 = accG[mf][nf][h * 2 + 0], g1 = accG[mf][nf][h * 2 + 1];
                    float u0 = accU[mf][nf][h * 2 + 0], u1 = accU[mf][nf][h * 2 + 1];
                    float2 o;
                    o.x = __uint_as_float(f2tf(g0 / (1.0f + expf(-g0)) * u0));
                    o.y = __uint_as_float(f2tf(g1 / (1.0f + expf(-g1)) * u1));
                    *(float2*)&g_hbuf[((size_t)e * SLOTS + slot0 + r) * II + col] = o;
                }
            }
        }
    }
}

// ================ GEMM2: mma.sync tf32 (both operands pre-converted) ========
// CTA: M=128 slots x N=256 H-cols. 512 threads. warp: 64 x 32.
#define G2_SMEM ((2*128*APITCH + 2*32*BPITCH) * 4)
__global__ void __launch_bounds__(512, 1) gemm2_mma() {
    extern __shared__ float s[];
    float* As = s;
    float* Bs = s + 2 * 128 * APITCH;

    int e = blockIdx.z, by = blockIdx.y, bx = blockIdx.x; // bx 0..2
    int kslot = (by >= 6) ? 1 : 0;
    int cnt = g_cnt[kslot * EE + e];
    int tile0 = (by - kslot * 6) * 128;
    if (tile0 >= cnt) return;
    int valid = min(128, cnt - tile0);
    int slot0 = by * 128;
    int tid = threadIdx.x;
    int lane = tid & 31, w = tid >> 5;
    int warpM = w >> 3, warpN = w & 7;

    const float* Ab = g_hbuf + ((size_t)e * SLOTS + slot0) * II;
    const float* Bb = g_w2tf + (size_t)e * II * HH + bx * 256;

    auto fill = [&](int buf, int c) {
        uint32_t au = s2u(As + buf * 128 * APITCH);
        uint32_t bu_ = s2u(Bs + buf * 32 * BPITCH);
        int k0 = c * 32;
#pragma unroll
        for (int i = tid; i < 1024; i += 512) {
            int row = i >> 3, seg = i & 7;
            cpa16(au + (uint32_t)(row * APITCH + seg * 4) * 4,
                  Ab + (size_t)row * II + k0 + seg * 4);
        }
#pragma unroll
        for (int i = tid; i < 2048; i += 512) {
            int k = i >> 6, seg = i & 63;
            cpa16(bu_ + (uint32_t)(k * BPITCH + seg * 4) * 4,
                  Bb + (size_t)(k0 + k) * HH + seg * 4);
        }
    };

    fill(0, 0); cpa_commit();
    float acc[4][4][4] = {};
    const int NC = II / 32; // 48
    for (int c = 0; c < NC; c++) {
        int b = c & 1;
        if (c + 1 < NC) { fill(b ^ 1, c + 1); cpa_commit(); cpa_wait<1>(); }
        else { cpa_wait<0>(); }
        __syncthreads();
        const float* A = As + b * 128 * APITCH;
        const float* B = Bs + b * 32 * BPITCH;
#pragma unroll
        for (int ks = 0; ks < 4; ks++) {
            int kc = ks * 8 + (lane & 3);
            int r0 = warpM * 64 + (lane >> 2);
            uint32_t af[4][4];
#pragma unroll
            for (int mf = 0; mf < 4; mf++) {
                int r = r0 + mf * 16;
                af[mf][0] = __float_as_uint(A[r * APITCH + kc]);
                af[mf][1] = __float_as_uint(A[(r + 8) * APITCH + kc]);
                af[mf][2] = __float_as_uint(A[r * APITCH + kc + 4]);
                af[mf][3] = __float_as_uint(A[(r + 8) * APITCH + kc + 4]);
            }
            int bn = warpN * 32 + (lane >> 2);
            uint32_t bf[4][2];
#pragma unroll
            for (int nf = 0; nf < 4; nf++) {
                bf[nf][0] = __float_as_uint(B[kc * BPITCH + bn + nf * 8]);
                bf[nf][1] = __float_as_uint(B[(kc + 4) * BPITCH + bn + nf * 8]);
            }
#pragma unroll
            for (int mf = 0; mf < 4; mf++)
#pragma unroll
                for (int nf = 0; nf < 4; nf++)
                    mma8(acc[mf][nf], af[mf], bf[nf]);
        }
        __syncthreads();
    }

#pragma unroll
    for (int mf = 0; mf < 4; mf++) {
        int rbase = warpM * 64 + mf * 16 + (lane >> 2);
#pragma unroll
        for (int nf = 0; nf < 4; nf++) {
            int col = bx * 256 + warpN * 32 + nf * 8 + 2 * (lane & 3);
#pragma unroll
            for (int h = 0; h < 2; h++) {
                int r = rbase + h * 8;
                if (r < valid) {
                    float2 o;
                    o.x = acc[mf][nf][h * 2 + 0];
                    o.y = acc[mf][nf][h * 2 + 1];
                    *(float2*)&g_ybuf[((size_t)e * SLOTS + slot0 + r) * HH + col] = o;
                }
            }
        }
    }
}

// ---------------- combine ----------------
__global__ void combine_kernel(float* __restrict__ out) {
    int t = blockIdx.x;
    __shared__ int se[2], ss[2];
    __shared__ float sw[2];
    if (threadIdx.x < 2) {
        se[threadIdx.x] = g_topk_idx[t * 2 + threadIdx.x];
        ss[threadIdx.x] = g_slot[t * 2 + threadIdx.x];
        sw[threadIdx.x] = g_topk_w[t * 2 + threadIdx.x];
    }
    __syncthreads();
    for (int h = threadIdx.x; h < HH; h += 256) {
        float v = 0.0f;
        if (ss[0] >= 0) v += sw[0] * g_ybuf[((size_t)se[0] * SLOTS + ss[0]) * HH + h];
        if (ss[1] >= 0) v += sw[1] * g_ybuf[((size_t)se[1] * SLOTS + ss[1]) * HH + h];
        out[(size_t)t * HH + h] = v;
    }
}

// ---------------- aux ----------------
__global__ void aux_kernel(float* __restrict__ out, int out_size) {
    if (out_size < TT * HH + 1) return;
    float a = 0.0f;
    for (int e = 0; e < EE; e++) {
        float usage = (float)g_keptcnt[e] / (float)(TT * KK);
        float imp = g_importance[e] / (float)TT;
        a += usage * imp;
    }
    a *= (float)EE;
    if (g_dropped > 0.0f) a += g_dropped / (float)TT * 0.1f;
    a = fminf(a, 1.0f) * 0.001f;
    out[TT * HH] = a;
}

// ---------------- launch ----------------
extern "C" void kernel_launch(void* const* d_in, const int* in_sizes, int n_in,
                              void* d_out, int out_size) {
    const float* x      = (const float*)d_in[0];
    const float* w_gate = (const float*)d_in[1];
    const float* w1     = (const float*)d_in[2];
    const float* w3     = (const float*)d_in[3];
    const float* w2     = (const float*)d_in[4];
    float* out = (float*)d_out;

    cudaFuncSetAttribute(gemm1_mma, cudaFuncAttributeMaxDynamicSharedMemorySize, G1_SMEM);
    cudaFuncSetAttribute(gemm2_mma, cudaFuncAttributeMaxDynamicSharedMemorySize, G2_SMEM);

    float* xtf_p;  cudaGetSymbolAddress((void**)&xtf_p,  g_xtf);
    float* w1tf_p; cudaGetSymbolAddress((void**)&w1tf_p, g_w1tf);
    float* w3tf_p; cudaGetSymbolAddress((void**)&w3tf_p, g_w3tf);
    float* w2tf_p; cudaGetSymbolAddress((void**)&w2tf_p, g_w2tf);

    const int NW4 = (EE * HH * II) / 4;   // 2359296
    const int NX4 = (TT * HH) / 4;        // 393216

    zero_kernel<<<1, 32>>>();
    cvt_kernel<<<(NX4 + 255) / 256, 256>>>((const float4*)x,  (float4*)xtf_p,  NX4);
    cvt_kernel<<<(NW4 + 255) / 256, 256>>>((const float4*)w1, (float4*)w1tf_p, NW4);
    cvt_kernel<<<(NW4 + 255) / 256, 256>>>((const float4*)w3, (float4*)w3tf_p, NW4);
    cvt_kernel<<<(NW4 + 255) / 256, 256>>>((const float4*)w2, (float4*)w2tf_p, NW4);
    routing_kernel<<<TT, 256>>>(x, w_gate);
    scan_kernel<<<1, 1024>>>();
    gemm1_mma<<<dim3(II / 128, SLOTS / 128, EE), 512, G1_SMEM>>>();
    gemm2_mma<<<dim3(HH / 256, SLOTS / 128, EE), 512, G2_SMEM>>>();
    combine_kernel<<<TT, 256>>>(out);
    aux_kernel<<<1, 1>>>(out, out_size);
}

// round 7
// speedup vs baseline: 1.0795x; 1.0009x over previous
#include <cuda_runtime.h>
#include <cuda_bf16.h>
#include <stdint.h>
#include <math.h>

// Problem constants
#define TT 2048      // tokens (B*S)
#define HH 768       // hidden
#define II 1536      // intermediate
#define EE 8         // experts
#define KK 2         // top-k
#define CAP 768      // capacity
#define SLOTS (KK*CAP)   // 1536 slot rows per expert

// ---------------- scratch (device globals; allocation-free) ----------------
__device__ float g_importance[EE];
__device__ int   g_topk_idx[TT * KK];
__device__ float g_topk_w[TT * KK];
__device__ int   g_slot[TT * KK];
__device__ int   g_list[EE * SLOTS];
__device__ int   g_cnt[KK * EE];
__device__ int   g_keptcnt[EE];
__device__ float g_dropped;
__device__ float g_xtf[TT * HH];                 // x as tf32 bits (6MB)
__device__ float g_w1tf[EE * HH * II];           // w1 as tf32 bits (~38MB)
__device__ float g_w3tf[EE * HH * II];           // w3 as tf32 bits (~38MB)
__device__ float g_w2tf[EE * II * HH];           // w2 as tf32 bits (~38MB)
__device__ float g_hbuf[EE * SLOTS * II];        // SwiGLU intermediate, tf32 bits (~75MB)
__device__ float g_ybuf[EE * SLOTS * HH];        // expert outputs    (~38MB)

// ---------------- PTX helpers ----------------
__device__ __forceinline__ uint32_t s2u(const void* p) {
    uint32_t a;
    asm("{ .reg .u64 t; cvta.to.shared.u64 t, %1; cvt.u32.u64 %0, t; }" : "=r"(a) : "l"(p));
    return a;
}
__device__ __forceinline__ void cpa16(uint32_t dst, const void* src) {
    asm volatile("cp.async.cg.shared.global [%0], [%1], 16;" :: "r"(dst), "l"(src));
}
__device__ __forceinline__ void cpa_commit() { asm volatile("cp.async.commit_group;" ::: "memory"); }
template<int N> __device__ __forceinline__ void cpa_wait() {
    asm volatile("cp.async.wait_group %0;" :: "n"(N) : "memory");
}
__device__ __forceinline__ uint32_t f2tf(float f) {
    uint32_t r; asm("cvt.rna.tf32.f32 %0, %1;" : "=r"(r) : "f"(f)); return r;
}
__device__ __forceinline__ void mma8(float* d, const uint32_t* a, const uint32_t* b) {
    asm volatile(
        "mma.sync.aligned.m16n8k8.row.col.f32.tf32.tf32.f32 "
        "{%0,%1,%2,%3}, {%4,%5,%6,%7}, {%8,%9}, {%0,%1,%2,%3};"
        : "+f"(d[0]), "+f"(d[1]), "+f"(d[2]), "+f"(d[3])
        : "r"(a[0]), "r"(a[1]), "r"(a[2]), "r"(a[3]), "r"(b[0]), "r"(b[1]));
}

// ---------------- tf32 pre-convert (memory-bound, float4) ----------------
__global__ void cvt_kernel(const float4* __restrict__ src, float4* __restrict__ dst, int n4) {
    int i = blockIdx.x * blockDim.x + threadIdx.x;
    if (i < n4) {
        float4 v = src[i];
        uint4 o;
        o.x = f2tf(v.x); o.y = f2tf(v.y); o.z = f2tf(v.z); o.w = f2tf(v.w);
        dst[i] = *(float4*)&o;
    }
}

// ---------------- zero ----------------
__global__ void zero_kernel() {
    if (threadIdx.x < EE) g_importance[threadIdx.x] = 0.0f;
}

// ---------------- routing ----------------
__global__ void routing_kernel(const float* __restrict__ x,
                               const float* __restrict__ wg) {
    int t = blockIdx.x;
    __shared__ float sx[HH];
    __shared__ float slog[EE];
    int tid = threadIdx.x;
    for (int i = tid; i < HH; i += 256) sx[i] = x[t * HH + i];
    __syncthreads();
    int warp = tid >> 5, lane = tid & 31;
    float sum = 0.0f;
    for (int j = lane; j < HH; j += 32) sum += sx[j] * wg[j * EE + warp];
    for (int o = 16; o; o >>= 1) sum += __shfl_xor_sync(0xffffffffu, sum, o);
    if (lane == 0) slog[warp] = sum;
    __syncthreads();
    if (tid == 0) {
        float mx = slog[0];
        for (int e = 1; e < EE; e++) mx = fmaxf(mx, slog[e]);
        float p[EE], s = 0.0f;
        for (int e = 0; e < EE; e++) { p[e] = expf(slog[e] - mx); s += p[e]; }
        for (int e = 0; e < EE; e++) p[e] /= s;
        int e0 = 0;
        for (int e = 1; e < EE; e++) if (p[e] > p[e0]) e0 = e;
        int e1 = -1;
        for (int e = 0; e < EE; e++) {
            if (e == e0) continue;
            if (e1 < 0 || p[e] > p[e1]) e1 = e;
        }
        float ps = p[e0] + p[e1] + 1e-8f;
        float w0 = fminf(fmaxf(p[e0] / ps, 1e-8f), 10.0f);
        float w1 = fminf(fmaxf(p[e1] / ps, 1e-8f), 10.0f);
        g_topk_idx[t * 2 + 0] = e0;
        g_topk_idx[t * 2 + 1] = e1;
        g_topk_w[t * 2 + 0] = w0;
        g_topk_w[t * 2 + 1] = w1;
        for (int e = 0; e < EE; e++) atomicAdd(&g_importance[e], p[e]);
    }
}

// ---------------- scan ----------------
__global__ void scan_kernel() {
    __shared__ int warp_cnt[32][EE];
    __shared__ int warp_pref[32][EE];
    __shared__ int running[EE];
    __shared__ int chunk_tot[EE];
    __shared__ int tot[KK][EE];
    int tid = threadIdx.x, lane = tid & 31, warp = tid >> 5;

    for (int k = 0; k < KK; k++) {
        if (tid < EE) running[tid] = 0;
        __syncthreads();
        for (int chunk = 0; chunk < TT / 1024; chunk++) {
            int t = chunk * 1024 + tid;
            int e = g_topk_idx[t * 2 + k];
            unsigned mask = __match_any_sync(0xffffffffu, e);
            int lane_pref = __popc(mask & ((1u << lane) - 1));
            int warp_total = __popc(mask);
            if (tid < 32 * EE) warp_cnt[tid / EE][tid % EE] = 0;
            __syncthreads();
            if (lane_pref == 0) warp_cnt[warp][e] = warp_total;
            __syncthreads();
            if (tid < 32 * EE) {
                int w = tid / EE, ee = tid % EE;
                int p = 0;
                for (int ww = 0; ww < w; ww++) p += warp_cnt[ww][ee];
                warp_pref[w][ee] = p;
                if (w == 31) chunk_tot[ee] = p + warp_cnt[31][ee];
            }
            __syncthreads();
            int rank = running[e] + warp_pref[warp][e] + lane_pref + 1;
            bool kept = (rank <= CAP);
            int slot = kept ? (k * CAP + rank - 1) : -1;
            g_slot[t * 2 + k] = slot;
            if (kept) g_list[e * SLOTS + slot] = t;
            __syncthreads();
            if (tid < EE) running[tid] += chunk_tot[tid];
            __syncthreads();
        }
        if (tid < EE) tot[k][tid] = running[tid];
        __syncthreads();
    }
    if (tid == 0) {
        int drop = 0;
        for (int e = 0; e < EE; e++) {
            int c0 = min(tot[0][e], CAP), c1 = min(tot[1][e], CAP);
            g_cnt[0 * EE + e] = c0;
            g_cnt[1 * EE + e] = c1;
            g_keptcnt[e] = c0 + c1;
            drop += (tot[0][e] - c0) + (tot[1][e] - c1);
        }
        g_dropped = (float)drop;
    }
}

// ================ GEMM1: mma.sync tf32, fused SwiGLU, 3-stage pipeline =====
// CTA: M=128 slots x N=256 (128 w1-cols + 128 w3-cols). 512 threads, 16 warps.
#define APITCH 36
#define BPITCH 264
#define ABUF (128*APITCH)
#define BBUF (32*BPITCH)
#define G1_SMEM ((3*ABUF + 3*BBUF) * 4 + 512)
__global__ void __launch_bounds__(512, 1) gemm1_mma() {
    extern __shared__ float s[];
    float* As = s;                        // 3 x ABUF
    float* Bs = s + 3 * ABUF;             // 3 x BBUF
    int* stok = (int*)(Bs + 3 * BBUF);

    int e = blockIdx.z, by = blockIdx.y, bx = blockIdx.x;
    int kslot = (by >= 6) ? 1 : 0;
    int cnt = g_cnt[kslot * EE + e];
    int tile0 = (by - kslot * 6) * 128;
    if (tile0 >= cnt) return;
    int valid = min(128, cnt - tile0);
    int slot0 = by * 128;
    int tid = threadIdx.x;
    int lane = tid & 31, w = tid >> 5;
    int warpM = w >> 3, warpN = w & 7;

    if (tid < 128)
        stok[tid] = (tid < valid) ? g_list[e * SLOTS + slot0 + tid]
                                  : g_list[e * SLOTS + slot0];
    __syncthreads();

    const float* w1b = g_w1tf + (size_t)e * HH * II + bx * 128;
    const float* w3b = g_w3tf + (size_t)e * HH * II + bx * 128;

    auto fill = [&](int buf, int c) {
        uint32_t au = s2u(As + buf * ABUF);
        uint32_t bu_ = s2u(Bs + buf * BBUF);
        int k0 = c * 32;
#pragma unroll
        for (int i = tid; i < 1024; i += 512) {
            int row = i >> 3, seg = i & 7;
            cpa16(au + (uint32_t)(row * APITCH + seg * 4) * 4,
                  g_xtf + (size_t)stok[row] * HH + k0 + seg * 4);
        }
#pragma unroll
        for (int i = tid; i < 2048; i += 512) {
            int k = i >> 6, seg = i & 63;
            const float* src = (seg < 32) ? (w1b + (size_t)(k0 + k) * II + seg * 4)
                                          : (w3b + (size_t)(k0 + k) * II + (seg - 32) * 4);
            int dc = (seg < 32) ? seg * 4 : 128 + (seg - 32) * 4;
            cpa16(bu_ + (uint32_t)(k * BPITCH + dc) * 4, src);
        }
        cpa_commit();
    };

    const int NC = HH / 32; // 24
    fill(0, 0);
    fill(1, 1);

    float accG[4][2][4] = {}, accU[4][2][4] = {};
    int r0 = warpM * 64 + (lane >> 2);
    int bn = warpN * 16 + (lane >> 2);

    for (int c = 0; c < NC; c++) {
        if (c + 1 < NC) cpa_wait<1>(); else cpa_wait<0>();
        __syncthreads();
        // prefetch chunk c+2 into buffer (c+2)%3 (freed by barrier: compute c-1 done)
        if (c + 2 < NC) fill((c + 2) % 3, c + 2);

        const float* A = As + (c % 3) * ABUF;
        const float* B = Bs + (c % 3) * BBUF;
#pragma unroll
        for (int ks = 0; ks < 4; ks++) {
            int kc = ks * 8 + (lane & 3);
            uint32_t af[4][4];
#pragma unroll
            for (int mf = 0; mf < 4; mf++) {
                int r = r0 + mf * 16;
                af[mf][0] = __float_as_uint(A[r * APITCH + kc]);
                af[mf][1] = __float_as_uint(A[(r + 8) * APITCH + kc]);
                af[mf][2] = __float_as_uint(A[r * APITCH + kc + 4]);
                af[mf][3] = __float_as_uint(A[(r + 8) * APITCH + kc + 4]);
            }
            uint32_t bg[2][2], bu2[2][2];
#pragma unroll
            for (int nf = 0; nf < 2; nf++) {
                bg[nf][0]  = __float_as_uint(B[kc * BPITCH + bn + nf * 8]);
                bg[nf][1]  = __float_as_uint(B[(kc + 4) * BPITCH + bn + nf * 8]);
                bu2[nf][0] = __float_as_uint(B[kc * BPITCH + 128 + bn + nf * 8]);
                bu2[nf][1] = __float_as_uint(B[(kc + 4) * BPITCH + 128 + bn + nf * 8]);
            }
#pragma unroll
            for (int mf = 0; mf < 4; mf++)
#pragma unroll
                for (int nf = 0; nf < 2; nf++) {
                    mma8(accG[mf][nf], af[mf], bg[nf]);
                    mma8(accU[mf][nf], af[mf], bu2[nf]);
                }
        }
    }

    // epilogue: SwiGLU, write hbuf as tf32 bits (gemm2 consumes bits directly)
#pragma unroll
    for (int mf = 0; mf < 4; mf++) {
        int rbase = warpM * 64 + mf * 16 + (lane >> 2);
#pragma unroll
        for (int nf = 0; nf < 2; nf++) {
            int col = bx * 128 + warpN * 16 + nf * 8 + 2 * (lane & 3);
#pragma unroll
            for (int h = 0; h < 2; h++) {
                int r = rbase + h * 8;
                if (r < valid) {
                    float g0 = accG[mf][nf][h * 2 + 0], g1 = accG[mf][nf][h * 2 + 1];
                    float u0 = accU[mf][nf][h * 2 + 0], u1 = accU[mf][nf][h * 2 + 1];
                    float2 o;
                    o.x = __uint_as_float(f2tf(g0 / (1.0f + expf(-g0)) * u0));
                    o.y = __uint_as_float(f2tf(g1 / (1.0f + expf(-g1)) * u1));
                    *(float2*)&g_hbuf[((size_t)e * SLOTS + slot0 + r) * II + col] = o;
                }
            }
        }
    }
}

// ================ GEMM2: mma.sync tf32, 3-stage pipeline ================
// CTA: M=128 slots x N=256 H-cols. 512 threads. warp: 64 x 32.
#define G2_SMEM ((3*ABUF + 3*BBUF) * 4)
__global__ void __launch_bounds__(512, 1) gemm2_mma() {
    extern __shared__ float s[];
    float* As = s;
    float* Bs = s + 3 * ABUF;

    int e = blockIdx.z, by = blockIdx.y, bx = blockIdx.x; // bx 0..2
    int kslot = (by >= 6) ? 1 : 0;
    int cnt = g_cnt[kslot * EE + e];
    int tile0 = (by - kslot * 6) * 128;
    if (tile0 >= cnt) return;
    int valid = min(128, cnt - tile0);
    int slot0 = by * 128;
    int tid = threadIdx.x;
    int lane = tid & 31, w = tid >> 5;
    int warpM = w >> 3, warpN = w & 7;

    const float* Ab = g_hbuf + ((size_t)e * SLOTS + slot0) * II;
    const float* Bb = g_w2tf + (size_t)e * II * HH + bx * 256;

    auto fill = [&](int buf, int c) {
        uint32_t au = s2u(As + buf * ABUF);
        uint32_t bu_ = s2u(Bs + buf * BBUF);
        int k0 = c * 32;
#pragma unroll
        for (int i = tid; i < 1024; i += 512) {
            int row = i >> 3, seg = i & 7;
            cpa16(au + (uint32_t)(row * APITCH + seg * 4) * 4,
                  Ab + (size_t)row * II + k0 + seg * 4);
        }
#pragma unroll
        for (int i = tid; i < 2048; i += 512) {
            int k = i >> 6, seg = i & 63;
            cpa16(bu_ + (uint32_t)(k * BPITCH + seg * 4) * 4,
                  Bb + (size_t)(k0 + k) * HH + seg * 4);
        }
        cpa_commit();
    };

    const int NC = II / 32; // 48
    fill(0, 0);
    fill(1, 1);

    float acc[4][4][4] = {};
    int r0 = warpM * 64 + (lane >> 2);
    int bn = warpN * 32 + (lane >> 2);

    for (int c = 0; c < NC; c++) {
        if (c + 1 < NC) cpa_wait<1>(); else cpa_wait<0>();
        __syncthreads();
        if (c + 2 < NC) fill((c + 2) % 3, c + 2);

        const float* A = As + (c % 3) * ABUF;
        const float* B = Bs + (c % 3) * BBUF;
#pragma unroll
        for (int ks = 0; ks < 4; ks++) {
            int kc = ks * 8 + (lane & 3);
            uint32_t af[4][4];
#pragma unroll
            for (int mf = 0; mf < 4; mf++) {
                int r = r0 + mf * 16;
                af[mf][0] = __float_as_uint(A[r * APITCH + kc]);
                af[mf][1] = __float_as_uint(A[(r + 8) * APITCH + kc]);
                af[mf][2] = __float_as_uint(A[r * APITCH + kc + 4]);
                af[mf][3] = __float_as_uint(A[(r + 8) * APITCH + kc + 4]);
            }
            uint32_t bf[4][2];
#pragma unroll
            for (int nf = 0; nf < 4; nf++) {
                bf[nf][0] = __float_as_uint(B[kc * BPITCH + bn + nf * 8]);
                bf[nf][1] = __float_as_uint(B[(kc + 4) * BPITCH + bn + nf * 8]);
            }
#pragma unroll
            for (int mf = 0; mf < 4; mf++)
#pragma unroll
                for (int nf = 0; nf < 4; nf++)
                    mma8(acc[mf][nf], af[mf], bf[nf]);
        }
    }

#pragma unroll
    for (int mf = 0; mf < 4; mf++) {
        int rbase = warpM * 64 + mf * 16 + (lane >> 2);
#pragma unroll
        for (int nf = 0; nf < 4; nf++) {
            int col = bx * 256 + warpN * 32 + nf * 8 + 2 * (lane & 3);
#pragma unroll
            for (int h = 0; h < 2; h++) {
                int r = rbase + h * 8;
                if (r < valid) {
                    float2 o;
                    o.x = acc[mf][nf][h * 2 + 0];
                    o.y = acc[mf][nf][h * 2 + 1];
                    *(float2*)&g_ybuf[((size_t)e * SLOTS + slot0 + r) * HH + col] = o;
                }
            }
        }
    }
}

// ---------------- combine ----------------
__global__ void combine_kernel(float* __restrict__ out) {
    int t = blockIdx.x;
    __shared__ int se[2], ss[2];
    __shared__ float sw[2];
    if (threadIdx.x < 2) {
        se[threadIdx.x] = g_topk_idx[t * 2 + threadIdx.x];
        ss[threadIdx.x] = g_slot[t * 2 + threadIdx.x];
        sw[threadIdx.x] = g_topk_w[t * 2 + threadIdx.x];
    }
    __syncthreads();
    for (int h = threadIdx.x; h < HH; h += 256) {
        float v = 0.0f;
        if (ss[0] >= 0) v += sw[0] * g_ybuf[((size_t)se[0] * SLOTS + ss[0]) * HH + h];
        if (ss[1] >= 0) v += sw[1] * g_ybuf[((size_t)se[1] * SLOTS + ss[1]) * HH + h];
        out[(size_t)t * HH + h] = v;
    }
}

// ---------------- aux ----------------
__global__ void aux_kernel(float* __restrict__ out, int out_size) {
    if (out_size < TT * HH + 1) return;
    float a = 0.0f;
    for (int e = 0; e < EE; e++) {
        float usage = (float)g_keptcnt[e] / (float)(TT * KK);
        float imp = g_importance[e] / (float)TT;
        a += usage * imp;
    }
    a *= (float)EE;
    if (g_dropped > 0.0f) a += g_dropped / (float)TT * 0.1f;
    a = fminf(a, 1.0f) * 0.001f;
    out[TT * HH] = a;
}

// ---------------- launch ----------------
extern "C" void kernel_launch(void* const* d_in, const int* in_sizes, int n_in,
                              void* d_out, int out_size) {
    const float* x      = (const float*)d_in[0];
    const float* w_gate = (const float*)d_in[1];
    const float* w1     = (const float*)d_in[2];
    const float* w3     = (const float*)d_in[3];
    const float* w2     = (const float*)d_in[4];
    float* out = (float*)d_out;

    cudaFuncSetAttribute(gemm1_mma, cudaFuncAttributeMaxDynamicSharedMemorySize, G1_SMEM);
    cudaFuncSetAttribute(gemm2_mma, cudaFuncAttributeMaxDynamicSharedMemorySize, G2_SMEM);

    float* xtf_p;  cudaGetSymbolAddress((void**)&xtf_p,  g_xtf);
    float* w1tf_p; cudaGetSymbolAddress((void**)&w1tf_p, g_w1tf);
    float* w3tf_p; cudaGetSymbolAddress((void**)&w3tf_p, g_w3tf);
    float* w2tf_p; cudaGetSymbolAddress((void**)&w2tf_p, g_w2tf);

    const int NW4 = (EE * HH * II) / 4;   // 2359296
    const int NX4 = (TT * HH) / 4;        // 393216

    zero_kernel<<<1, 32>>>();
    cvt_kernel<<<(NX4 + 255) / 256, 256>>>((const float4*)x,  (float4*)xtf_p,  NX4);
    cvt_kernel<<<(NW4 + 255) / 256, 256>>>((const float4*)w1, (float4*)w1tf_p, NW4);
    cvt_kernel<<<(NW4 + 255) / 256, 256>>>((const float4*)w3, (float4*)w3tf_p, NW4);
    cvt_kernel<<<(NW4 + 255) / 256, 256>>>((const float4*)w2, (float4*)w2tf_p, NW4);
    routing_kernel<<<TT, 256>>>(x, w_gate);
    scan_kernel<<<1, 1024>>>();
    gemm1_mma<<<dim3(II / 128, SLOTS / 128, EE), 512, G1_SMEM>>>();
    gemm2_mma<<<dim3(HH / 256, SLOTS / 128, EE), 512, G2_SMEM>>>();
    combine_kernel<<<TT, 256>>>(out);
    aux_kernel<<<1, 1>>>(out, out_size);
}

// round 9
// speedup vs baseline: 1.5709x; 1.4552x over previous
#include <cuda_runtime.h>
#include <cuda_bf16.h>
#include <cuda_fp16.h>
#include <stdint.h>
#include <math.h>

// Problem constants
#define TT 2048      // tokens (B*S)
#define HH 768       // hidden
#define II 1536      // intermediate
#define EE 8         // experts
#define KK 2         // top-k
#define CAP 768      // capacity
#define SLOTS (KK*CAP)   // 1536 slot rows per expert

// ---------------- scratch (device globals; allocation-free) ----------------
__device__ float g_importance[EE];
__device__ int   g_topk_idx[TT * KK];
__device__ float g_topk_w[TT * KK];
__device__ int   g_slot[TT * KK];
__device__ int   g_list[EE * SLOTS];
__device__ int   g_cnt[KK * EE];
__device__ int   g_keptcnt[EE];
__device__ float g_dropped;
__device__ __half g_xh[TT * HH];                  // x as fp16 (3MB)
__device__ __half g_w1h[EE * HH * II];            // w1 fp16 (~19MB)
__device__ __half g_w3h[EE * HH * II];            // w3 fp16 (~19MB)
__device__ __half g_w2h[EE * II * HH];            // w2 fp16 (~19MB)
__device__ __half g_hbufh[EE * SLOTS * II];       // SwiGLU intermediate fp16 (~38MB)
__device__ float  g_ybuf[EE * SLOTS * HH];        // expert outputs f32 (~75MB)

// ---------------- PTX helpers ----------------
__device__ __forceinline__ uint32_t s2u(const void* p) {
    uint32_t a;
    asm("{ .reg .u64 t; cvta.to.shared.u64 t, %1; cvt.u32.u64 %0, t; }" : "=r"(a) : "l"(p));
    return a;
}
__device__ __forceinline__ void cpa16(uint32_t dst, const void* src) {
    asm volatile("cp.async.cg.shared.global [%0], [%1], 16;" :: "r"(dst), "l"(src));
}
__device__ __forceinline__ void cpa_commit() { asm volatile("cp.async.commit_group;" ::: "memory"); }
template<int N> __device__ __forceinline__ void cpa_wait() {
    asm volatile("cp.async.wait_group %0;" :: "n"(N) : "memory");
}
__device__ __forceinline__ void ldsm4(uint32_t* r, uint32_t addr) {
    asm volatile("ldmatrix.sync.aligned.m8n8.x4.shared.b16 {%0,%1,%2,%3}, [%4];"
        : "=r"(r[0]), "=r"(r[1]), "=r"(r[2]), "=r"(r[3]) : "r"(addr));
}
__device__ __forceinline__ void ldsm4t(uint32_t* r, uint32_t addr) {
    asm volatile("ldmatrix.sync.aligned.m8n8.x4.trans.shared.b16 {%0,%1,%2,%3}, [%4];"
        : "=r"(r[0]), "=r"(r[1]), "=r"(r[2]), "=r"(r[3]) : "r"(addr));
}
__device__ __forceinline__ void mma16(float* d, const uint32_t* a, const uint32_t* b) {
    asm volatile(
        "mma.sync.aligned.m16n8k16.row.col.f32.f16.f16.f32 "
        "{%0,%1,%2,%3}, {%4,%5,%6,%7}, {%8,%9}, {%0,%1,%2,%3};"
        : "+f"(d[0]), "+f"(d[1]), "+f"(d[2]), "+f"(d[3])
        : "r"(a[0]), "r"(a[1]), "r"(a[2]), "r"(a[3]), "r"(b[0]), "r"(b[1]));
}

// ---------------- fp16 pre-convert (memory-bound) ----------------
__global__ void cvth_kernel(const float4* __restrict__ src, uint2* __restrict__ dst, int n4) {
    int i = blockIdx.x * blockDim.x + threadIdx.x;
    if (i < n4) {
        float4 v = src[i];
        __half2 h0 = __floats2half2_rn(v.x, v.y);
        __half2 h1 = __floats2half2_rn(v.z, v.w);
        uint2 o;
        o.x = *(uint32_t*)&h0;
        o.y = *(uint32_t*)&h1;
        dst[i] = o;
    }
}

// ---------------- zero ----------------
__global__ void zero_kernel() {
    if (threadIdx.x < EE) g_importance[threadIdx.x] = 0.0f;
}

// ---------------- routing (also emits x in fp16) ----------------
__global__ void routing_kernel(const float* __restrict__ x,
                               const float* __restrict__ wg) {
    int t = blockIdx.x;
    __shared__ float sx[HH];
    __shared__ float slog[EE];
    int tid = threadIdx.x;
    for (int i = tid; i < HH; i += 256) sx[i] = x[t * HH + i];
    __syncthreads();
    // emit fp16 copy of this token row
    for (int i = tid; i < HH / 2; i += 256) {
        __half2 hv = __floats2half2_rn(sx[2 * i], sx[2 * i + 1]);
        *((__half2*)g_xh + (size_t)t * (HH / 2) + i) = hv;
    }
    int warp = tid >> 5, lane = tid & 31;
    float sum = 0.0f;
    for (int j = lane; j < HH; j += 32) sum += sx[j] * wg[j * EE + warp];
    for (int o = 16; o; o >>= 1) sum += __shfl_xor_sync(0xffffffffu, sum, o);
    if (lane == 0) slog[warp] = sum;
    __syncthreads();
    if (tid == 0) {
        float mx = slog[0];
        for (int e = 1; e < EE; e++) mx = fmaxf(mx, slog[e]);
        float p[EE], s = 0.0f;
        for (int e = 0; e < EE; e++) { p[e] = expf(slog[e] - mx); s += p[e]; }
        for (int e = 0; e < EE; e++) p[e] /= s;
        int e0 = 0;
        for (int e = 1; e < EE; e++) if (p[e] > p[e0]) e0 = e;
        int e1 = -1;
        for (int e = 0; e < EE; e++) {
            if (e == e0) continue;
            if (e1 < 0 || p[e] > p[e1]) e1 = e;
        }
        float ps = p[e0] + p[e1] + 1e-8f;
        float w0 = fminf(fmaxf(p[e0] / ps, 1e-8f), 10.0f);
        float w1 = fminf(fmaxf(p[e1] / ps, 1e-8f), 10.0f);
        g_topk_idx[t * 2 + 0] = e0;
        g_topk_idx[t * 2 + 1] = e1;
        g_topk_w[t * 2 + 0] = w0;
        g_topk_w[t * 2 + 1] = w1;
        for (int e = 0; e < EE; e++) atomicAdd(&g_importance[e], p[e]);
    }
}

// ---------------- scan ----------------
__global__ void scan_kernel() {
    __shared__ int warp_cnt[32][EE];
    __shared__ int warp_pref[32][EE];
    __shared__ int running[EE];
    __shared__ int chunk_tot[EE];
    __shared__ int tot[KK][EE];
    int tid = threadIdx.x, lane = tid & 31, warp = tid >> 5;

    for (int k = 0; k < KK; k++) {
        if (tid < EE) running[tid] = 0;
        __syncthreads();
        for (int chunk = 0; chunk < TT / 1024; chunk++) {
            int t = chunk * 1024 + tid;
            int e = g_topk_idx[t * 2 + k];
            unsigned mask = __match_any_sync(0xffffffffu, e);
            int lane_pref = __popc(mask & ((1u << lane) - 1));
            int warp_total = __popc(mask);
            if (tid < 32 * EE) warp_cnt[tid / EE][tid % EE] = 0;
            __syncthreads();
            if (lane_pref == 0) warp_cnt[warp][e] = warp_total;
            __syncthreads();
            if (tid < 32 * EE) {
                int w = tid / EE, ee = tid % EE;
                int p = 0;
                for (int ww = 0; ww < w; ww++) p += warp_cnt[ww][ee];
                warp_pref[w][ee] = p;
                if (w == 31) chunk_tot[ee] = p + warp_cnt[31][ee];
            }
            __syncthreads();
            int rank = running[e] + warp_pref[warp][e] + lane_pref + 1;
            bool kept = (rank <= CAP);
            int slot = kept ? (k * CAP + rank - 1) : -1;
            g_slot[t * 2 + k] = slot;
            if (kept) g_list[e * SLOTS + slot] = t;
            __syncthreads();
            if (tid < EE) running[tid] += chunk_tot[tid];
            __syncthreads();
        }
        if (tid < EE) tot[k][tid] = running[tid];
        __syncthreads();
    }
    if (tid == 0) {
        int drop = 0;
        for (int e = 0; e < EE; e++) {
            int c0 = min(tot[0][e], CAP), c1 = min(tot[1][e], CAP);
            g_cnt[0 * EE + e] = c0;
            g_cnt[1 * EE + e] = c1;
            g_keptcnt[e] = c0 + c1;
            drop += (tot[0][e] - c0) + (tot[1][e] - c1);
        }
        g_dropped = (float)drop;
    }
}

// ================ GEMM1: fp16 mma.m16n8k16 + ldmatrix, fused SwiGLU ========
// CTA: M=128 slots x N=256 (128 w1-cols + 128 w3-cols). 512 threads, 16 warps.
// warpM = w>>3 (2), warpN = w&7 (8). Warp: 64 rows x (16 G-cols + 16 U-cols).
#define APITCH 40              // halves per A row (32 data + 8 pad) = 80B
#define BPITCH 264             // halves per B k-row (256 data + 8 pad) = 528B
#define ABUF (128*APITCH)      // halves
#define BBUF (32*BPITCH)       // halves
#define G1_SMEM ((3*ABUF + 3*BBUF) * 2 + 512)
__global__ void __launch_bounds__(512, 1) gemm1_mma() {
    extern __shared__ __half sh[];
    __half* Ash = sh;                 // 3 x ABUF
    __half* Bsh = sh + 3 * ABUF;      // 3 x BBUF
    int* stok = (int*)(Bsh + 3 * BBUF);

    int e = blockIdx.z, by = blockIdx.y, bx = blockIdx.x;
    int kslot = (by >= 6) ? 1 : 0;
    int cnt = g_cnt[kslot * EE + e];
    int tile0 = (by - kslot * 6) * 128;
    if (tile0 >= cnt) return;
    int valid = min(128, cnt - tile0);
    int slot0 = by * 128;
    int tid = threadIdx.x;
    int lane = tid & 31, w = tid >> 5;
    int warpM = w >> 3, warpN = w & 7;

    if (tid < 128)
        stok[tid] = (tid < valid) ? g_list[e * SLOTS + slot0 + tid]
                                  : g_list[e * SLOTS + slot0];
    __syncthreads();

    const __half* w1b = g_w1h + (size_t)e * HH * II + bx * 128;
    const __half* w3b = g_w3h + (size_t)e * HH * II + bx * 128;

    auto fill = [&](int buf, int c) {
        uint32_t au = s2u(Ash + buf * ABUF);
        uint32_t bu_ = s2u(Bsh + buf * BBUF);
        int k0 = c * 32;
        {   // A: 128 rows x 32 halves = 512 x 16B, one per thread
            int row = tid >> 2, seg = tid & 3;
            cpa16(au + (uint32_t)(row * APITCH + seg * 8) * 2,
                  g_xh + (size_t)stok[row] * HH + k0 + seg * 8);
        }
#pragma unroll
        for (int i = tid; i < 1024; i += 512) {  // B: 32 k-rows x 256 halves
            int k = i >> 5, seg = i & 31;
            const __half* src = (seg < 16) ? (w1b + (size_t)(k0 + k) * II + seg * 8)
                                           : (w3b + (size_t)(k0 + k) * II + (seg - 16) * 8);
            cpa16(bu_ + (uint32_t)(k * BPITCH + seg * 8) * 2, src);
        }
        cpa_commit();
    };

    const int NC = HH / 32; // 24
    fill(0, 0);
    fill(1, 1);

    float accG[4][2][4] = {}, accU[4][2][4] = {};
    int l15 = lane & 15;
    int lhi = (lane & 16) ? 8 : 0;

    for (int c = 0; c < NC; c++) {
        if (c + 1 < NC) cpa_wait<1>(); else cpa_wait<0>();
        __syncthreads();
        if (c + 2 < NC) fill((c + 2) % 3, c + 2);

        uint32_t au = s2u(Ash + (c % 3) * ABUF);
        uint32_t bu_ = s2u(Bsh + (c % 3) * BBUF);
#pragma unroll
        for (int ks = 0; ks < 2; ks++) {
            uint32_t af[4][4];
#pragma unroll
            for (int mf = 0; mf < 4; mf++) {
                int row = warpM * 64 + mf * 16 + l15;
                int col = ks * 16 + lhi;
                ldsm4(af[mf], au + (uint32_t)(row * APITCH + col) * 2);
            }
            int k = ks * 16 + l15;
            int nG = warpN * 16 + lhi;
            uint32_t bg[4], bu2[4];
            ldsm4t(bg,  bu_ + (uint32_t)(k * BPITCH + nG) * 2);
            ldsm4t(bu2, bu_ + (uint32_t)(k * BPITCH + 128 + nG) * 2);
#pragma unroll
            for (int mf = 0; mf < 4; mf++) {
                mma16(accG[mf][0], af[mf], bg);
                mma16(accG[mf][1], af[mf], bg + 2);
                mma16(accU[mf][0], af[mf], bu2);
                mma16(accU[mf][1], af[mf], bu2 + 2);
            }
        }
    }

    // epilogue: SwiGLU, write hbuf as fp16
#pragma unroll
    for (int mf = 0; mf < 4; mf++) {
        int rbase = warpM * 64 + mf * 16 + (lane >> 2);
#pragma unroll
        for (int nf = 0; nf < 2; nf++) {
            int col = bx * 128 + warpN * 16 + nf * 8 + 2 * (lane & 3);
#pragma unroll
            for (int h = 0; h < 2; h++) {
                int r = rbase + h * 8;
                if (r < valid) {
                    float g0 = accG[mf][nf][h * 2 + 0], g1 = accG[mf][nf][h * 2 + 1];
                    float u0 = accU[mf][nf][h * 2 + 0], u1 = accU[mf][nf][h * 2 + 1];
                    __half2 hv = __floats2half2_rn(g0 / (1.0f + expf(-g0)) * u0,
                                                   g1 / (1.0f + expf(-g1)) * u1);
                    *(__half2*)&g_hbufh[((size_t)e * SLOTS + slot0 + r) * II + col] = hv;
                }
            }
        }
    }
}

// ================ GEMM2: fp16 mma.m16n8k16 + ldmatrix ================
// CTA: M=128 slots x N=256 H-cols. 512 threads. warp: 64 x 32.
#define G2_SMEM ((3*ABUF + 3*BBUF) * 2)
__global__ void __launch_bounds__(512, 1) gemm2_mma() {
    extern __shared__ __half sh[];
    __half* Ash = sh;
    __half* Bsh = sh + 3 * ABUF;

    int e = blockIdx.z, by = blockIdx.y, bx = blockIdx.x; // bx 0..2
    int kslot = (by >= 6) ? 1 : 0;
    int cnt = g_cnt[kslot * EE + e];
    int tile0 = (by - kslot * 6) * 128;
    if (tile0 >= cnt) return;
    int valid = min(128, cnt - tile0);
    int slot0 = by * 128;
    int tid = threadIdx.x;
    int lane = tid & 31, w = tid >> 5;
    int warpM = w >> 3, warpN = w & 7;

    const __half* Ab = g_hbufh + ((size_t)e * SLOTS + slot0) * II;
    const __half* Bb = g_w2h + (size_t)e * II * HH + bx * 256;

    auto fill = [&](int buf, int c) {
        uint32_t au = s2u(Ash + buf * ABUF);
        uint32_t bu_ = s2u(Bsh + buf * BBUF);
        int k0 = c * 32;
        {
            int row = tid >> 2, seg = tid & 3;
            cpa16(au + (uint32_t)(row * APITCH + seg * 8) * 2,
                  Ab + (size_t)row * II + k0 + seg * 8);
        }
#pragma unroll
        for (int i = tid; i < 1024; i += 512) {
            int k = i >> 5, seg = i & 31;
            cpa16(bu_ + (uint32_t)(k * BPITCH + seg * 8) * 2,
                  Bb + (size_t)(k0 + k) * HH + seg * 8);
        }
        cpa_commit();
    };

    const int NC = II / 32; // 48
    fill(0, 0);
    fill(1, 1);

    float acc[4][4][4] = {};
    int l15 = lane & 15;
    int lhi = (lane & 16) ? 8 : 0;

    for (int c = 0; c < NC; c++) {
        if (c + 1 < NC) cpa_wait<1>(); else cpa_wait<0>();
        __syncthreads();
        if (c + 2 < NC) fill((c + 2) % 3, c + 2);

        uint32_t au = s2u(Ash + (c % 3) * ABUF);
        uint32_t bu_ = s2u(Bsh + (c % 3) * BBUF);
#pragma unroll
        for (int ks = 0; ks < 2; ks++) {
            uint32_t af[4][4];
#pragma unroll
            for (int mf = 0; mf < 4; mf++) {
                int row = warpM * 64 + mf * 16 + l15;
                int col = ks * 16 + lhi;
                ldsm4(af[mf], au + (uint32_t)(row * APITCH + col) * 2);
            }
            int k = ks * 16 + l15;
            int nB = warpN * 32 + lhi;
            uint32_t bf[8];
            ldsm4t(bf,     bu_ + (uint32_t)(k * BPITCH + nB) * 2);
            ldsm4t(bf + 4, bu_ + (uint32_t)(k * BPITCH + nB + 16) * 2);
#pragma unroll
            for (int mf = 0; mf < 4; mf++) {
                mma16(acc[mf][0], af[mf], bf);
                mma16(acc[mf][1], af[mf], bf + 2);
                mma16(acc[mf][2], af[mf], bf + 4);
                mma16(acc[mf][3], af[mf], bf + 6);
            }
        }
    }

#pragma unroll
    for (int mf = 0; mf < 4; mf++) {
        int rbase = warpM * 64 + mf * 16 + (lane >> 2);
#pragma unroll
        for (int nf = 0; nf < 4; nf++) {
            int col = bx * 256 + warpN * 32 + nf * 8 + 2 * (lane & 3);
#pragma unroll
            for (int h = 0; h < 2; h++) {
                int r = rbase + h * 8;
                if (r < valid) {
                    float2 o;
                    o.x = acc[mf][nf][h * 2 + 0];
                    o.y = acc[mf][nf][h * 2 + 1];
                    *(float2*)&g_ybuf[((size_t)e * SLOTS + slot0 + r) * HH + col] = o;
                }
            }
        }
    }
}

// ---------------- combine ----------------
__global__ void combine_kernel(float* __restrict__ out) {
    int t = blockIdx.x;
    __shared__ int se[2], ss[2];
    __shared__ float sw[2];
    if (threadIdx.x < 2) {
        se[threadIdx.x] = g_topk_idx[t * 2 + threadIdx.x];
        ss[threadIdx.x] = g_slot[t * 2 + threadIdx.x];
        sw[threadIdx.x] = g_topk_w[t * 2 + threadIdx.x];
    }
    __syncthreads();
    for (int h = threadIdx.x; h < HH; h += 256) {
        float v = 0.0f;
        if (ss[0] >= 0) v += sw[0] * g_ybuf[((size_t)se[0] * SLOTS + ss[0]) * HH + h];
        if (ss[1] >= 0) v += sw[1] * g_ybuf[((size_t)se[1] * SLOTS + ss[1]) * HH + h];
        out[(size_t)t * HH + h] = v;
    }
}

// ---------------- aux ----------------
__global__ void aux_kernel(float* __restrict__ out, int out_size) {
    if (out_size < TT * HH + 1) return;
    float a = 0.0f;
    for (int e = 0; e < EE; e++) {
        float usage = (float)g_keptcnt[e] / (float)(TT * KK);
        float imp = g_importance[e] / (float)TT;
        a += usage * imp;
    }
    a *= (float)EE;
    if (g_dropped > 0.0f) a += g_dropped / (float)TT * 0.1f;
    a = fminf(a, 1.0f) * 0.001f;
    out[TT * HH] = a;
}

// ---------------- launch ----------------
extern "C" void kernel_launch(void* const* d_in, const int* in_sizes, int n_in,
                              void* d_out, int out_size) {
    const float* x      = (const float*)d_in[0];
    const float* w_gate = (const float*)d_in[1];
    const float* w1     = (const float*)d_in[2];
    const float* w3     = (const float*)d_in[3];
    const float* w2     = (const float*)d_in[4];
    float* out = (float*)d_out;

    cudaFuncSetAttribute(gemm1_mma, cudaFuncAttributeMaxDynamicSharedMemorySize, G1_SMEM);
    cudaFuncSetAttribute(gemm2_mma, cudaFuncAttributeMaxDynamicSharedMemorySize, G2_SMEM);

    __half* w1h_p; cudaGetSymbolAddress((void**)&w1h_p, g_w1h);
    __half* w3h_p; cudaGetSymbolAddress((void**)&w3h_p, g_w3h);
    __half* w2h_p; cudaGetSymbolAddress((void**)&w2h_p, g_w2h);

    const int NW4 = (EE * HH * II) / 4;   // 2359296

    zero_kernel<<<1, 32>>>();
    cvth_kernel<<<(NW4 + 255) / 256, 256>>>((const float4*)w1, (uint2*)w1h_p, NW4);
    cvth_kernel<<<(NW4 + 255) / 256, 256>>>((const float4*)w3, (uint2*)w3h_p, NW4);
    cvth_kernel<<<(NW4 + 255) / 256, 256>>>((const float4*)w2, (uint2*)w2h_p, NW4);
    routing_kernel<<<TT, 256>>>(x, w_gate);
    scan_kernel<<<1, 1024>>>();
    gemm1_mma<<<dim3(II / 128, SLOTS / 128, EE), 512, G1_SMEM>>>();
    gemm2_mma<<<dim3(HH / 256, SLOTS / 128, EE), 512, G2_SMEM>>>();
    combine_kernel<<<TT, 256>>>(out);
    aux_kernel<<<1, 1>>>(out, out_size);
}

// round 10
// speedup vs baseline: 1.6794x; 1.0691x over previous
#include <cuda_runtime.h>
#include <cuda_bf16.h>
#include <cuda_fp16.h>
#include <stdint.h>
#include <math.h>

// Problem constants
#define TT 2048      // tokens (B*S)
#define HH 768       // hidden
#define II 1536      // intermediate
#define EE 8         // experts
#define KK 2         // top-k
#define CAP 768      // capacity
#define SLOTS (KK*CAP)   // 1536 slot rows per expert

// ---------------- scratch (device globals; allocation-free) ----------------
__device__ float g_importance[EE];
__device__ int   g_topk_idx[TT * KK];
__device__ float g_topk_w[TT * KK];
__device__ int   g_slot[TT * KK];
__device__ int   g_list[EE * SLOTS];
__device__ int   g_cnt[KK * EE];
__device__ int   g_keptcnt[EE];
__device__ float g_dropped;
__device__ __half g_xh[TT * HH];                  // x as fp16 (3MB)
__device__ __half g_w1h[EE * HH * II];            // w1 fp16 (~19MB)
__device__ __half g_w3h[EE * HH * II];            // w3 fp16 (~19MB)
__device__ __half g_w2h[EE * II * HH];            // w2 fp16 (~19MB)
__device__ __half g_hbufh[EE * SLOTS * II];       // SwiGLU intermediate fp16 (~38MB)
__device__ float  g_ybuf[EE * SLOTS * HH];        // expert outputs f32 (~75MB)

// ---------------- PTX helpers ----------------
__device__ __forceinline__ uint32_t s2u(const void* p) {
    uint32_t a;
    asm("{ .reg .u64 t; cvta.to.shared.u64 t, %1; cvt.u32.u64 %0, t; }" : "=r"(a) : "l"(p));
    return a;
}
__device__ __forceinline__ void cpa16(uint32_t dst, const void* src) {
    asm volatile("cp.async.cg.shared.global [%0], [%1], 16;" :: "r"(dst), "l"(src));
}
__device__ __forceinline__ void cpa_commit() { asm volatile("cp.async.commit_group;" ::: "memory"); }
template<int N> __device__ __forceinline__ void cpa_wait() {
    asm volatile("cp.async.wait_group %0;" :: "n"(N) : "memory");
}
__device__ __forceinline__ void ldsm4(uint32_t* r, uint32_t addr) {
    asm volatile("ldmatrix.sync.aligned.m8n8.x4.shared.b16 {%0,%1,%2,%3}, [%4];"
        : "=r"(r[0]), "=r"(r[1]), "=r"(r[2]), "=r"(r[3]) : "r"(addr));
}
__device__ __forceinline__ void ldsm4t(uint32_t* r, uint32_t addr) {
    asm volatile("ldmatrix.sync.aligned.m8n8.x4.trans.shared.b16 {%0,%1,%2,%3}, [%4];"
        : "=r"(r[0]), "=r"(r[1]), "=r"(r[2]), "=r"(r[3]) : "r"(addr));
}
__device__ __forceinline__ void mma16(float* d, const uint32_t* a, const uint32_t* b) {
    asm volatile(
        "mma.sync.aligned.m16n8k16.row.col.f32.f16.f16.f32 "
        "{%0,%1,%2,%3}, {%4,%5,%6,%7}, {%8,%9}, {%0,%1,%2,%3};"
        : "+f"(d[0]), "+f"(d[1]), "+f"(d[2]), "+f"(d[3])
        : "r"(a[0]), "r"(a[1]), "r"(a[2]), "r"(a[3]), "r"(b[0]), "r"(b[1]));
}

// ---------------- fp16 pre-convert (memory-bound) ----------------
__global__ void cvth_kernel(const float4* __restrict__ src, uint2* __restrict__ dst, int n4) {
    int i = blockIdx.x * blockDim.x + threadIdx.x;
    if (i < n4) {
        float4 v = src[i];
        __half2 h0 = __floats2half2_rn(v.x, v.y);
        __half2 h1 = __floats2half2_rn(v.z, v.w);
        uint2 o;
        o.x = *(uint32_t*)&h0;
        o.y = *(uint32_t*)&h1;
        dst[i] = o;
    }
}

// ---------------- zero ----------------
__global__ void zero_kernel() {
    if (threadIdx.x < EE) g_importance[threadIdx.x] = 0.0f;
}

// ---------------- routing (also emits x in fp16) ----------------
__global__ void routing_kernel(const float* __restrict__ x,
                               const float* __restrict__ wg) {
    int t = blockIdx.x;
    __shared__ float sx[HH];
    __shared__ float slog[EE];
    int tid = threadIdx.x;
    for (int i = tid; i < HH; i += 256) sx[i] = x[t * HH + i];
    __syncthreads();
    for (int i = tid; i < HH / 2; i += 256) {
        __half2 hv = __floats2half2_rn(sx[2 * i], sx[2 * i + 1]);
        *((__half2*)g_xh + (size_t)t * (HH / 2) + i) = hv;
    }
    int warp = tid >> 5, lane = tid & 31;
    float sum = 0.0f;
    for (int j = lane; j < HH; j += 32) sum += sx[j] * wg[j * EE + warp];
    for (int o = 16; o; o >>= 1) sum += __shfl_xor_sync(0xffffffffu, sum, o);
    if (lane == 0) slog[warp] = sum;
    __syncthreads();
    if (tid == 0) {
        float mx = slog[0];
        for (int e = 1; e < EE; e++) mx = fmaxf(mx, slog[e]);
        float p[EE], s = 0.0f;
        for (int e = 0; e < EE; e++) { p[e] = expf(slog[e] - mx); s += p[e]; }
        for (int e = 0; e < EE; e++) p[e] /= s;
        int e0 = 0;
        for (int e = 1; e < EE; e++) if (p[e] > p[e0]) e0 = e;
        int e1 = -1;
        for (int e = 0; e < EE; e++) {
            if (e == e0) continue;
            if (e1 < 0 || p[e] > p[e1]) e1 = e;
        }
        float ps = p[e0] + p[e1] + 1e-8f;
        float w0 = fminf(fmaxf(p[e0] / ps, 1e-8f), 10.0f);
        float w1 = fminf(fmaxf(p[e1] / ps, 1e-8f), 10.0f);
        g_topk_idx[t * 2 + 0] = e0;
        g_topk_idx[t * 2 + 1] = e1;
        g_topk_w[t * 2 + 0] = w0;
        g_topk_w[t * 2 + 1] = w1;
        for (int e = 0; e < EE; e++) atomicAdd(&g_importance[e], p[e]);
    }
}

// ---------------- scan ----------------
__global__ void scan_kernel() {
    __shared__ int warp_cnt[32][EE];
    __shared__ int warp_pref[32][EE];
    __shared__ int running[EE];
    __shared__ int chunk_tot[EE];
    __shared__ int tot[KK][EE];
    int tid = threadIdx.x, lane = tid & 31, warp = tid >> 5;

    for (int k = 0; k < KK; k++) {
        if (tid < EE) running[tid] = 0;
        __syncthreads();
        for (int chunk = 0; chunk < TT / 1024; chunk++) {
            int t = chunk * 1024 + tid;
            int e = g_topk_idx[t * 2 + k];
            unsigned mask = __match_any_sync(0xffffffffu, e);
            int lane_pref = __popc(mask & ((1u << lane) - 1));
            int warp_total = __popc(mask);
            if (tid < 32 * EE) warp_cnt[tid / EE][tid % EE] = 0;
            __syncthreads();
            if (lane_pref == 0) warp_cnt[warp][e] = warp_total;
            __syncthreads();
            if (tid < 32 * EE) {
                int w = tid / EE, ee = tid % EE;
                int p = 0;
                for (int ww = 0; ww < w; ww++) p += warp_cnt[ww][ee];
                warp_pref[w][ee] = p;
                if (w == 31) chunk_tot[ee] = p + warp_cnt[31][ee];
            }
            __syncthreads();
            int rank = running[e] + warp_pref[warp][e] + lane_pref + 1;
            bool kept = (rank <= CAP);
            int slot = kept ? (k * CAP + rank - 1) : -1;
            g_slot[t * 2 + k] = slot;
            if (kept) g_list[e * SLOTS + slot] = t;
            __syncthreads();
            if (tid < EE) running[tid] += chunk_tot[tid];
            __syncthreads();
        }
        if (tid < EE) tot[k][tid] = running[tid];
        __syncthreads();
    }
    if (tid == 0) {
        int drop = 0;
        for (int e = 0; e < EE; e++) {
            int c0 = min(tot[0][e], CAP), c1 = min(tot[1][e], CAP);
            g_cnt[0 * EE + e] = c0;
            g_cnt[1 * EE + e] = c1;
            g_keptcnt[e] = c0 + c1;
            drop += (tot[0][e] - c0) + (tot[1][e] - c1);
        }
        g_dropped = (float)drop;
    }
}

// ================ GEMM1: fp16 mma + ldmatrix, 128x128, 2 CTAs/SM ==========
// CTA: M=128 slots x N=128 (64 w1-cols + 64 w3-cols). 256 threads, 8 warps.
// warpM = w>>2 (2), warpN = w&3 (4). Warp: 64 rows x (16 G-cols + 16 U-cols).
#define APITCH 40              // halves per A row (32 data + 8 pad) = 80B
#define BPITCH 136             // halves per B k-row (128 data + 8 pad) = 272B
#define ABUF (128*APITCH)      // halves
#define BBUF (32*BPITCH)       // halves
#define G1_SMEM ((3*ABUF + 3*BBUF) * 2 + 512)
__global__ void __launch_bounds__(256, 2) gemm1_mma() {
    extern __shared__ __half sh[];
    __half* Ash = sh;                 // 3 x ABUF
    __half* Bsh = sh + 3 * ABUF;      // 3 x BBUF
    int* stok = (int*)(Bsh + 3 * BBUF);

    int e = blockIdx.z, by = blockIdx.y, bx = blockIdx.x; // bx 0..23
    int kslot = (by >= 6) ? 1 : 0;
    int cnt = g_cnt[kslot * EE + e];
    int tile0 = (by - kslot * 6) * 128;
    if (tile0 >= cnt) return;
    int valid = min(128, cnt - tile0);
    int slot0 = by * 128;
    int tid = threadIdx.x;
    int lane = tid & 31, w = tid >> 5;
    int warpM = w >> 2, warpN = w & 3;

    if (tid < 128)
        stok[tid] = (tid < valid) ? g_list[e * SLOTS + slot0 + tid]
                                  : g_list[e * SLOTS + slot0];
    __syncthreads();

    const __half* w1b = g_w1h + (size_t)e * HH * II + bx * 64;
    const __half* w3b = g_w3h + (size_t)e * HH * II + bx * 64;

    auto fill = [&](int buf, int c) {
        uint32_t au = s2u(Ash + buf * ABUF);
        uint32_t bu_ = s2u(Bsh + buf * BBUF);
        int k0 = c * 32;
#pragma unroll
        for (int i = tid; i < 512; i += 256) {   // A: 128 rows x 32 halves
            int row = i >> 2, seg = i & 3;
            cpa16(au + (uint32_t)(row * APITCH + seg * 8) * 2,
                  g_xh + (size_t)stok[row] * HH + k0 + seg * 8);
        }
#pragma unroll
        for (int i = tid; i < 512; i += 256) {   // B: 32 k-rows x (64 G + 64 U)
            int k = i >> 4, seg = i & 15;
            const __half* src = (seg < 8) ? (w1b + (size_t)(k0 + k) * II + seg * 8)
                                          : (w3b + (size_t)(k0 + k) * II + (seg - 8) * 8);
            int dc = (seg < 8) ? seg * 8 : 64 + (seg - 8) * 8;
            cpa16(bu_ + (uint32_t)(k * BPITCH + dc) * 2, src);
        }
        cpa_commit();
    };

    const int NC = HH / 32; // 24
    fill(0, 0);
    fill(1, 1);

    float accG[4][2][4] = {}, accU[4][2][4] = {};
    int l15 = lane & 15;
    int lhi = (lane & 16) ? 8 : 0;

    for (int c = 0; c < NC; c++) {
        if (c + 1 < NC) cpa_wait<1>(); else cpa_wait<0>();
        __syncthreads();
        if (c + 2 < NC) fill((c + 2) % 3, c + 2);

        uint32_t au = s2u(Ash + (c % 3) * ABUF);
        uint32_t bu_ = s2u(Bsh + (c % 3) * BBUF);
#pragma unroll
        for (int ks = 0; ks < 2; ks++) {
            uint32_t af[4][4];
#pragma unroll
            for (int mf = 0; mf < 4; mf++) {
                int row = warpM * 64 + mf * 16 + l15;
                int col = ks * 16 + lhi;
                ldsm4(af[mf], au + (uint32_t)(row * APITCH + col) * 2);
            }
            int k = ks * 16 + l15;
            int nG = warpN * 16 + lhi;
            uint32_t bg[4], bu2[4];
            ldsm4t(bg,  bu_ + (uint32_t)(k * BPITCH + nG) * 2);
            ldsm4t(bu2, bu_ + (uint32_t)(k * BPITCH + 64 + nG) * 2);
#pragma unroll
            for (int mf = 0; mf < 4; mf++) {
                mma16(accG[mf][0], af[mf], bg);
                mma16(accG[mf][1], af[mf], bg + 2);
                mma16(accU[mf][0], af[mf], bu2);
                mma16(accU[mf][1], af[mf], bu2 + 2);
            }
        }
    }

    // epilogue: SwiGLU, write hbuf as fp16
#pragma unroll
    for (int mf = 0; mf < 4; mf++) {
        int rbase = warpM * 64 + mf * 16 + (lane >> 2);
#pragma unroll
        for (int nf = 0; nf < 2; nf++) {
            int col = bx * 64 + warpN * 16 + nf * 8 + 2 * (lane & 3);
#pragma unroll
            for (int h = 0; h < 2; h++) {
                int r = rbase + h * 8;
                if (r < valid) {
                    float g0 = accG[mf][nf][h * 2 + 0], g1 = accG[mf][nf][h * 2 + 1];
                    float u0 = accU[mf][nf][h * 2 + 0], u1 = accU[mf][nf][h * 2 + 1];
                    __half2 hv = __floats2half2_rn(g0 / (1.0f + expf(-g0)) * u0,
                                                   g1 / (1.0f + expf(-g1)) * u1);
                    *(__half2*)&g_hbufh[((size_t)e * SLOTS + slot0 + r) * II + col] = hv;
                }
            }
        }
    }
}

// ================ GEMM2: fp16 mma + ldmatrix, 128x128, 2 CTAs/SM ==========
// CTA: M=128 slots x N=128 H-cols. 256 threads. warp: 64 x 32.
#define G2_SMEM ((3*ABUF + 3*BBUF) * 2)
__global__ void __launch_bounds__(256, 2) gemm2_mma() {
    extern __shared__ __half sh[];
    __half* Ash = sh;
    __half* Bsh = sh + 3 * ABUF;

    int e = blockIdx.z, by = blockIdx.y, bx = blockIdx.x; // bx 0..5
    int kslot = (by >= 6) ? 1 : 0;
    int cnt = g_cnt[kslot * EE + e];
    int tile0 = (by - kslot * 6) * 128;
    if (tile0 >= cnt) return;
    int valid = min(128, cnt - tile0);
    int slot0 = by * 128;
    int tid = threadIdx.x;
    int lane = tid & 31, w = tid >> 5;
    int warpM = w >> 2, warpN = w & 3;

    const __half* Ab = g_hbufh + ((size_t)e * SLOTS + slot0) * II;
    const __half* Bb = g_w2h + (size_t)e * II * HH + bx * 128;

    auto fill = [&](int buf, int c) {
        uint32_t au = s2u(Ash + buf * ABUF);
        uint32_t bu_ = s2u(Bsh + buf * BBUF);
        int k0 = c * 32;
#pragma unroll
        for (int i = tid; i < 512; i += 256) {
            int row = i >> 2, seg = i & 3;
            cpa16(au + (uint32_t)(row * APITCH + seg * 8) * 2,
                  Ab + (size_t)row * II + k0 + seg * 8);
        }
#pragma unroll
        for (int i = tid; i < 512; i += 256) {
            int k = i >> 4, seg = i & 15;
            cpa16(bu_ + (uint32_t)(k * BPITCH + seg * 8) * 2,
                  Bb + (size_t)(k0 + k) * HH + seg * 8);
        }
        cpa_commit();
    };

    const int NC = II / 32; // 48
    fill(0, 0);
    fill(1, 1);

    float acc[4][4][4] = {};
    int l15 = lane & 15;
    int lhi = (lane & 16) ? 8 : 0;

    for (int c = 0; c < NC; c++) {
        if (c + 1 < NC) cpa_wait<1>(); else cpa_wait<0>();
        __syncthreads();
        if (c + 2 < NC) fill((c + 2) % 3, c + 2);

        uint32_t au = s2u(Ash + (c % 3) * ABUF);
        uint32_t bu_ = s2u(Bsh + (c % 3) * BBUF);
#pragma unroll
        for (int ks = 0; ks < 2; ks++) {
            uint32_t af[4][4];
#pragma unroll
            for (int mf = 0; mf < 4; mf++) {
                int row = warpM * 64 + mf * 16 + l15;
                int col = ks * 16 + lhi;
                ldsm4(af[mf], au + (uint32_t)(row * APITCH + col) * 2);
            }
            int k = ks * 16 + l15;
            int nB = warpN * 32 + lhi;
            uint32_t bf[8];
            ldsm4t(bf,     bu_ + (uint32_t)(k * BPITCH + nB) * 2);
            ldsm4t(bf + 4, bu_ + (uint32_t)(k * BPITCH + nB + 16) * 2);
#pragma unroll
            for (int mf = 0; mf < 4; mf++) {
                mma16(acc[mf][0], af[mf], bf);
                mma16(acc[mf][1], af[mf], bf + 2);
                mma16(acc[mf][2], af[mf], bf + 4);
                mma16(acc[mf][3], af[mf], bf + 6);
            }
        }
    }

#pragma unroll
    for (int mf = 0; mf < 4; mf++) {
        int rbase = warpM * 64 + mf * 16 + (lane >> 2);
#pragma unroll
        for (int nf = 0; nf < 4; nf++) {
            int col = bx * 128 + warpN * 32 + nf * 8 + 2 * (lane & 3);
#pragma unroll
            for (int h = 0; h < 2; h++) {
                int r = rbase + h * 8;
                if (r < valid) {
                    float2 o;
                    o.x = acc[mf][nf][h * 2 + 0];
                    o.y = acc[mf][nf][h * 2 + 1];
                    *(float2*)&g_ybuf[((size_t)e * SLOTS + slot0 + r) * HH + col] = o;
                }
            }
        }
    }
}

// ---------------- combine ----------------
__global__ void combine_kernel(float* __restrict__ out) {
    int t = blockIdx.x;
    __shared__ int se[2], ss[2];
    __shared__ float sw[2];
    if (threadIdx.x < 2) {
        se[threadIdx.x] = g_topk_idx[t * 2 + threadIdx.x];
        ss[threadIdx.x] = g_slot[t * 2 + threadIdx.x];
        sw[threadIdx.x] = g_topk_w[t * 2 + threadIdx.x];
    }
    __syncthreads();
    for (int h = threadIdx.x; h < HH; h += 256) {
        float v = 0.0f;
        if (ss[0] >= 0) v += sw[0] * g_ybuf[((size_t)se[0] * SLOTS + ss[0]) * HH + h];
        if (ss[1] >= 0) v += sw[1] * g_ybuf[((size_t)se[1] * SLOTS + ss[1]) * HH + h];
        out[(size_t)t * HH + h] = v;
    }
}

// ---------------- aux ----------------
__global__ void aux_kernel(float* __restrict__ out, int out_size) {
    if (out_size < TT * HH + 1) return;
    float a = 0.0f;
    for (int e = 0; e < EE; e++) {
        float usage = (float)g_keptcnt[e] / (float)(TT * KK);
        float imp = g_importance[e] / (float)TT;
        a += usage * imp;
    }
    a *= (float)EE;
    if (g_dropped > 0.0f) a += g_dropped / (float)TT * 0.1f;
    a = fminf(a, 1.0f) * 0.001f;
    out[TT * HH] = a;
}

// ---------------- launch ----------------
extern "C" void kernel_launch(void* const* d_in, const int* in_sizes, int n_in,
                              void* d_out, int out_size) {
    const float* x      = (const float*)d_in[0];
    const float* w_gate = (const float*)d_in[1];
    const float* w1     = (const float*)d_in[2];
    const float* w3     = (const float*)d_in[3];
    const float* w2     = (const float*)d_in[4];
    float* out = (float*)d_out;

    cudaFuncSetAttribute(gemm1_mma, cudaFuncAttributeMaxDynamicSharedMemorySize, G1_SMEM);
    cudaFuncSetAttribute(gemm2_mma, cudaFuncAttributeMaxDynamicSharedMemorySize, G2_SMEM);

    __half* w1h_p; cudaGetSymbolAddress((void**)&w1h_p, g_w1h);
    __half* w3h_p; cudaGetSymbolAddress((void**)&w3h_p, g_w3h);
    __half* w2h_p; cudaGetSymbolAddress((void**)&w2h_p, g_w2h);

    const int NW4 = (EE * HH * II) / 4;   // 2359296

    zero_kernel<<<1, 32>>>();
    cvth_kernel<<<(NW4 + 255) / 256, 256>>>((const float4*)w1, (uint2*)w1h_p, NW4);
    cvth_kernel<<<(NW4 + 255) / 256, 256>>>((const float4*)w3, (uint2*)w3h_p, NW4);
    cvth_kernel<<<(NW4 + 255) / 256, 256>>>((const float4*)w2, (uint2*)w2h_p, NW4);
    routing_kernel<<<TT, 256>>>(x, w_gate);
    scan_kernel<<<1, 1024>>>();
    gemm1_mma<<<dim3(II / 64, SLOTS / 128, EE), 256, G1_SMEM>>>();
    gemm2_mma<<<dim3(HH / 128, SLOTS / 128, EE), 256, G2_SMEM>>>();
    combine_kernel<<<TT, 256>>>(out);
    aux_kernel<<<1, 1>>>(out, out_size);
}

// round 11
// speedup vs baseline: 1.7758x; 1.0574x over previous
#include <cuda_runtime.h>
#include <cuda_bf16.h>
#include <cuda_fp16.h>
#include <stdint.h>
#include <math.h>

// Problem constants
#define TT 2048      // tokens (B*S)
#define HH 768       // hidden
#define II 1536      // intermediate
#define EE 8         // experts
#define KK 2         // top-k
#define CAP 768      // capacity
#define SLOTS (KK*CAP)   // 1536 slot rows per expert

// ---------------- scratch (device globals; allocation-free) ----------------
__device__ float g_importance[EE];
__device__ int   g_topk_idx[TT * KK];
__device__ float g_topk_w[TT * KK];
__device__ int   g_slot[TT * KK];
__device__ int   g_list[EE * SLOTS];
__device__ float g_wslot[EE * SLOTS];             // combine weight per (e,slot)
__device__ int   g_cnt[KK * EE];
__device__ int   g_keptcnt[EE];
__device__ float g_dropped;
__device__ __half g_xh[TT * HH];                  // x as fp16 (3MB)
__device__ __half g_w1h[EE * HH * II];            // w1 fp16 (~19MB)
__device__ __half g_w3h[EE * HH * II];            // w3 fp16 (~19MB)
__device__ __half g_w2h[EE * II * HH];            // w2 fp16 (~19MB)
__device__ __half g_hbufh[EE * SLOTS * II];       // SwiGLU intermediate fp16 (~38MB)

// ---------------- PTX helpers ----------------
__device__ __forceinline__ uint32_t s2u(const void* p) {
    uint32_t a;
    asm("{ .reg .u64 t; cvta.to.shared.u64 t, %1; cvt.u32.u64 %0, t; }" : "=r"(a) : "l"(p));
    return a;
}
__device__ __forceinline__ void cpa16(uint32_t dst, const void* src) {
    asm volatile("cp.async.cg.shared.global [%0], [%1], 16;" :: "r"(dst), "l"(src));
}
__device__ __forceinline__ void cpa_commit() { asm volatile("cp.async.commit_group;" ::: "memory"); }
template<int N> __device__ __forceinline__ void cpa_wait() {
    asm volatile("cp.async.wait_group %0;" :: "n"(N) : "memory");
}
__device__ __forceinline__ void ldsm4(uint32_t* r, uint32_t addr) {
    asm volatile("ldmatrix.sync.aligned.m8n8.x4.shared.b16 {%0,%1,%2,%3}, [%4];"
        : "=r"(r[0]), "=r"(r[1]), "=r"(r[2]), "=r"(r[3]) : "r"(addr));
}
__device__ __forceinline__ void ldsm4t(uint32_t* r, uint32_t addr) {
    asm volatile("ldmatrix.sync.aligned.m8n8.x4.trans.shared.b16 {%0,%1,%2,%3}, [%4];"
        : "=r"(r[0]), "=r"(r[1]), "=r"(r[2]), "=r"(r[3]) : "r"(addr));
}
__device__ __forceinline__ void mma16(float* d, const uint32_t* a, const uint32_t* b) {
    asm volatile(
        "mma.sync.aligned.m16n8k16.row.col.f32.f16.f16.f32 "
        "{%0,%1,%2,%3}, {%4,%5,%6,%7}, {%8,%9}, {%0,%1,%2,%3};"
        : "+f"(d[0]), "+f"(d[1]), "+f"(d[2]), "+f"(d[3])
        : "r"(a[0]), "r"(a[1]), "r"(a[2]), "r"(a[3]), "r"(b[0]), "r"(b[1]));
}

// ---------------- fp16 pre-convert (memory-bound) ----------------
__global__ void cvth_kernel(const float4* __restrict__ src, uint2* __restrict__ dst, int n4) {
    int i = blockIdx.x * blockDim.x + threadIdx.x;
    if (i < n4) {
        float4 v = src[i];
        __half2 h0 = __floats2half2_rn(v.x, v.y);
        __half2 h1 = __floats2half2_rn(v.z, v.w);
        uint2 o;
        o.x = *(uint32_t*)&h0;
        o.y = *(uint32_t*)&h1;
        dst[i] = o;
    }
}

// ---------------- zero helpers ----------------
__global__ void zero_kernel() {
    if (threadIdx.x < EE) g_importance[threadIdx.x] = 0.0f;
}
__global__ void zero_out_kernel(float* __restrict__ out, int n) {
    int i = blockIdx.x * blockDim.x + threadIdx.x;
    if (i < n) out[i] = 0.0f;
}

// ---------------- routing (also emits x in fp16) ----------------
__global__ void routing_kernel(const float* __restrict__ x,
                               const float* __restrict__ wg) {
    int t = blockIdx.x;
    __shared__ float sx[HH];
    __shared__ float slog[EE];
    int tid = threadIdx.x;
    for (int i = tid; i < HH; i += 256) sx[i] = x[t * HH + i];
    __syncthreads();
    for (int i = tid; i < HH / 2; i += 256) {
        __half2 hv = __floats2half2_rn(sx[2 * i], sx[2 * i + 1]);
        *((__half2*)g_xh + (size_t)t * (HH / 2) + i) = hv;
    }
    int warp = tid >> 5, lane = tid & 31;
    float sum = 0.0f;
    for (int j = lane; j < HH; j += 32) sum += sx[j] * wg[j * EE + warp];
    for (int o = 16; o; o >>= 1) sum += __shfl_xor_sync(0xffffffffu, sum, o);
    if (lane == 0) slog[warp] = sum;
    __syncthreads();
    if (tid == 0) {
        float mx = slog[0];
        for (int e = 1; e < EE; e++) mx = fmaxf(mx, slog[e]);
        float p[EE], s = 0.0f;
        for (int e = 0; e < EE; e++) { p[e] = expf(slog[e] - mx); s += p[e]; }
        for (int e = 0; e < EE; e++) p[e] /= s;
        int e0 = 0;
        for (int e = 1; e < EE; e++) if (p[e] > p[e0]) e0 = e;
        int e1 = -1;
        for (int e = 0; e < EE; e++) {
            if (e == e0) continue;
            if (e1 < 0 || p[e] > p[e1]) e1 = e;
        }
        float ps = p[e0] + p[e1] + 1e-8f;
        float w0 = fminf(fmaxf(p[e0] / ps, 1e-8f), 10.0f);
        float w1 = fminf(fmaxf(p[e1] / ps, 1e-8f), 10.0f);
        g_topk_idx[t * 2 + 0] = e0;
        g_topk_idx[t * 2 + 1] = e1;
        g_topk_w[t * 2 + 0] = w0;
        g_topk_w[t * 2 + 1] = w1;
        for (int e = 0; e < EE; e++) atomicAdd(&g_importance[e], p[e]);
    }
}

// ---------------- scan ----------------
__global__ void scan_kernel() {
    __shared__ int warp_cnt[32][EE];
    __shared__ int warp_pref[32][EE];
    __shared__ int running[EE];
    __shared__ int chunk_tot[EE];
    __shared__ int tot[KK][EE];
    int tid = threadIdx.x, lane = tid & 31, warp = tid >> 5;

    for (int k = 0; k < KK; k++) {
        if (tid < EE) running[tid] = 0;
        __syncthreads();
        for (int chunk = 0; chunk < TT / 1024; chunk++) {
            int t = chunk * 1024 + tid;
            int e = g_topk_idx[t * 2 + k];
            unsigned mask = __match_any_sync(0xffffffffu, e);
            int lane_pref = __popc(mask & ((1u << lane) - 1));
            int warp_total = __popc(mask);
            if (tid < 32 * EE) warp_cnt[tid / EE][tid % EE] = 0;
            __syncthreads();
            if (lane_pref == 0) warp_cnt[warp][e] = warp_total;
            __syncthreads();
            if (tid < 32 * EE) {
                int w = tid / EE, ee = tid % EE;
                int p = 0;
                for (int ww = 0; ww < w; ww++) p += warp_cnt[ww][ee];
                warp_pref[w][ee] = p;
                if (w == 31) chunk_tot[ee] = p + warp_cnt[31][ee];
            }
            __syncthreads();
            int rank = running[e] + warp_pref[warp][e] + lane_pref + 1;
            bool kept = (rank <= CAP);
            int slot = kept ? (k * CAP + rank - 1) : -1;
            g_slot[t * 2 + k] = slot;
            if (kept) {
                g_list[e * SLOTS + slot] = t;
                g_wslot[e * SLOTS + slot] = g_topk_w[t * 2 + k];
            }
            __syncthreads();
            if (tid < EE) running[tid] += chunk_tot[tid];
            __syncthreads();
        }
        if (tid < EE) tot[k][tid] = running[tid];
        __syncthreads();
    }
    if (tid == 0) {
        int drop = 0;
        for (int e = 0; e < EE; e++) {
            int c0 = min(tot[0][e], CAP), c1 = min(tot[1][e], CAP);
            g_cnt[0 * EE + e] = c0;
            g_cnt[1 * EE + e] = c1;
            g_keptcnt[e] = c0 + c1;
            drop += (tot[0][e] - c0) + (tot[1][e] - c1);
        }
        g_dropped = (float)drop;
    }
}

// ================ GEMM1: fp16 mma + ldmatrix, K-chunk 64, 2-stage ==========
// CTA: M=128 slots x N=128 (64 w1-cols + 64 w3-cols). 256 threads, 8 warps.
// warpM = w>>2 (2), warpN = w&3 (4). Warp: 64 rows x (16 G-cols + 16 U-cols).
#define KC 64                   // K elements per chunk
#define APITCH 72               // halves per A row (64 data + 8 pad) = 144B
#define BPITCH 136              // halves per B k-row (128 data + 8 pad) = 272B
#define ABUF (128*APITCH)       // halves
#define BBUF (KC*BPITCH)        // halves
#define G1_SMEM ((2*ABUF + 2*BBUF) * 2 + 512)
__global__ void __launch_bounds__(256, 2) gemm1_mma() {
    extern __shared__ __half sh[];
    __half* Ash = sh;                 // 2 x ABUF
    __half* Bsh = sh + 2 * ABUF;      // 2 x BBUF
    int* stok = (int*)(Bsh + 2 * BBUF);

    int e = blockIdx.z, by = blockIdx.y, bx = blockIdx.x; // bx 0..23
    int kslot = (by >= 6) ? 1 : 0;
    int cnt = g_cnt[kslot * EE + e];
    int tile0 = (by - kslot * 6) * 128;
    if (tile0 >= cnt) return;
    int valid = min(128, cnt - tile0);
    int slot0 = by * 128;
    int tid = threadIdx.x;
    int lane = tid & 31, w = tid >> 5;
    int warpM = w >> 2, warpN = w & 3;

    if (tid < 128)
        stok[tid] = (tid < valid) ? g_list[e * SLOTS + slot0 + tid]
                                  : g_list[e * SLOTS + slot0];
    __syncthreads();

    const __half* w1b = g_w1h + (size_t)e * HH * II + bx * 64;
    const __half* w3b = g_w3h + (size_t)e * HH * II + bx * 64;

    auto fill = [&](int buf, int c) {
        uint32_t au = s2u(Ash + buf * ABUF);
        uint32_t bu_ = s2u(Bsh + buf * BBUF);
        int k0 = c * KC;
#pragma unroll
        for (int i = tid; i < 1024; i += 256) {   // A: 128 rows x 64 halves
            int row = i >> 3, seg = i & 7;
            cpa16(au + (uint32_t)(row * APITCH + seg * 8) * 2,
                  g_xh + (size_t)stok[row] * HH + k0 + seg * 8);
        }
#pragma unroll
        for (int i = tid; i < 1024; i += 256) {   // B: 64 k-rows x (64 G + 64 U)
            int k = i >> 4, seg = i & 15;
            const __half* src = (seg < 8) ? (w1b + (size_t)(k0 + k) * II + seg * 8)
                                          : (w3b + (size_t)(k0 + k) * II + (seg - 8) * 8);
            int dc = (seg < 8) ? seg * 8 : 64 + (seg - 8) * 8;
            cpa16(bu_ + (uint32_t)(k * BPITCH + dc) * 2, src);
        }
        cpa_commit();
    };

    const int NC = HH / KC; // 12
    fill(0, 0);

    float accG[4][2][4] = {}, accU[4][2][4] = {};
    int l15 = lane & 15;
    int lhi = (lane & 16) ? 8 : 0;

    for (int c = 0; c < NC; c++) {
        cpa_wait<0>();
        __syncthreads();                // fill(c) visible; all warps done with c-1
        if (c + 1 < NC) fill((c + 1) & 1, c + 1);

        uint32_t au = s2u(Ash + (c & 1) * ABUF);
        uint32_t bu_ = s2u(Bsh + (c & 1) * BBUF);
#pragma unroll
        for (int ks = 0; ks < KC / 16; ks++) {
            uint32_t af[4][4];
#pragma unroll
            for (int mf = 0; mf < 4; mf++) {
                int row = warpM * 64 + mf * 16 + l15;
                int col = ks * 16 + lhi;
                ldsm4(af[mf], au + (uint32_t)(row * APITCH + col) * 2);
            }
            int k = ks * 16 + l15;
            int nG = warpN * 16 + lhi;
            uint32_t bg[4], bu2[4];
            ldsm4t(bg,  bu_ + (uint32_t)(k * BPITCH + nG) * 2);
            ldsm4t(bu2, bu_ + (uint32_t)(k * BPITCH + 64 + nG) * 2);
#pragma unroll
            for (int mf = 0; mf < 4; mf++) {
                mma16(accG[mf][0], af[mf], bg);
                mma16(accG[mf][1], af[mf], bg + 2);
                mma16(accU[mf][0], af[mf], bu2);
                mma16(accU[mf][1], af[mf], bu2 + 2);
            }
        }
    }

    // epilogue: SwiGLU, write hbuf as fp16
#pragma unroll
    for (int mf = 0; mf < 4; mf++) {
        int rbase = warpM * 64 + mf * 16 + (lane >> 2);
#pragma unroll
        for (int nf = 0; nf < 2; nf++) {
            int col = bx * 64 + warpN * 16 + nf * 8 + 2 * (lane & 3);
#pragma unroll
            for (int h = 0; h < 2; h++) {
                int r = rbase + h * 8;
                if (r < valid) {
                    float g0 = accG[mf][nf][h * 2 + 0], g1 = accG[mf][nf][h * 2 + 1];
                    float u0 = accU[mf][nf][h * 2 + 0], u1 = accU[mf][nf][h * 2 + 1];
                    __half2 hv = __floats2half2_rn(g0 / (1.0f + expf(-g0)) * u0,
                                                   g1 / (1.0f + expf(-g1)) * u1);
                    *(__half2*)&g_hbufh[((size_t)e * SLOTS + slot0 + r) * II + col] = hv;
                }
            }
        }
    }
}

// ================ GEMM2: fp16 mma + ldmatrix, K-chunk 64, fused combine ====
// CTA: M=128 slots x N=128 H-cols. 256 threads. warp: 64 x 32.
// Epilogue scatters w * acc into out[token] via atomicAdd (combine fused).
#define G2_SMEM ((2*ABUF + 2*BBUF) * 2 + 128*4 + 128*4)
__global__ void __launch_bounds__(256, 2) gemm2_mma(float* __restrict__ out) {
    extern __shared__ __half sh[];
    __half* Ash = sh;
    __half* Bsh = sh + 2 * ABUF;
    int* tok2 = (int*)(Bsh + 2 * BBUF);
    float* wt2 = (float*)(tok2 + 128);

    int e = blockIdx.z, by = blockIdx.y, bx = blockIdx.x; // bx 0..5
    int kslot = (by >= 6) ? 1 : 0;
    int cnt = g_cnt[kslot * EE + e];
    int tile0 = (by - kslot * 6) * 128;
    if (tile0 >= cnt) return;
    int valid = min(128, cnt - tile0);
    int slot0 = by * 128;
    int tid = threadIdx.x;
    int lane = tid & 31, w = tid >> 5;
    int warpM = w >> 2, warpN = w & 3;

    if (tid < 128) {
        bool v = tid < valid;
        tok2[tid] = v ? g_list[e * SLOTS + slot0 + tid] : 0;
        wt2[tid]  = v ? g_wslot[e * SLOTS + slot0 + tid] : 0.0f;
    }
    __syncthreads();

    const __half* Ab = g_hbufh + ((size_t)e * SLOTS + slot0) * II;
    const __half* Bb = g_w2h + (size_t)e * II * HH + bx * 128;

    auto fill = [&](int buf, int c) {
        uint32_t au = s2u(Ash + buf * ABUF);
        uint32_t bu_ = s2u(Bsh + buf * BBUF);
        int k0 = c * KC;
#pragma unroll
        for (int i = tid; i < 1024; i += 256) {
            int row = i >> 3, seg = i & 7;
            cpa16(au + (uint32_t)(row * APITCH + seg * 8) * 2,
                  Ab + (size_t)row * II + k0 + seg * 8);
        }
#pragma unroll
        for (int i = tid; i < 1024; i += 256) {
            int k = i >> 4, seg = i & 15;
            cpa16(bu_ + (uint32_t)(k * BPITCH + seg * 8) * 2,
                  Bb + (size_t)(k0 + k) * HH + seg * 8);
        }
        cpa_commit();
    };

    const int NC = II / KC; // 24
    fill(0, 0);

    float acc[4][4][4] = {};
    int l15 = lane & 15;
    int lhi = (lane & 16) ? 8 : 0;

    for (int c = 0; c < NC; c++) {
        cpa_wait<0>();
        __syncthreads();
        if (c + 1 < NC) fill((c + 1) & 1, c + 1);

        uint32_t au = s2u(Ash + (c & 1) * ABUF);
        uint32_t bu_ = s2u(Bsh + (c & 1) * BBUF);
#pragma unroll
        for (int ks = 0; ks < KC / 16; ks++) {
            uint32_t af[4][4];
#pragma unroll
            for (int mf = 0; mf < 4; mf++) {
                int row = warpM * 64 + mf * 16 + l15;
                int col = ks * 16 + lhi;
                ldsm4(af[mf], au + (uint32_t)(row * APITCH + col) * 2);
            }
            int k = ks * 16 + l15;
            int nB = warpN * 32 + lhi;
            uint32_t bf[8];
            ldsm4t(bf,     bu_ + (uint32_t)(k * BPITCH + nB) * 2);
            ldsm4t(bf + 4, bu_ + (uint32_t)(k * BPITCH + nB + 16) * 2);
#pragma unroll
            for (int mf = 0; mf < 4; mf++) {
                mma16(acc[mf][0], af[mf], bf);
                mma16(acc[mf][1], af[mf], bf + 2);
                mma16(acc[mf][2], af[mf], bf + 4);
                mma16(acc[mf][3], af[mf], bf + 6);
            }
        }
    }

    // fused combine: out[token] += w * acc
#pragma unroll
    for (int mf = 0; mf < 4; mf++) {
        int rbase = warpM * 64 + mf * 16 + (lane >> 2);
#pragma unroll
        for (int nf = 0; nf < 4; nf++) {
            int col = bx * 128 + warpN * 32 + nf * 8 + 2 * (lane & 3);
#pragma unroll
            for (int h = 0; h < 2; h++) {
                int r = rbase + h * 8;
                if (r < valid) {
                    float wv = wt2[r];
                    float* op = out + (size_t)tok2[r] * HH + col;
                    atomicAdd(op,     wv * acc[mf][nf][h * 2 + 0]);
                    atomicAdd(op + 1, wv * acc[mf][nf][h * 2 + 1]);
                }
            }
        }
    }
}

// ---------------- aux ----------------
__global__ void aux_kernel(float* __restrict__ out, int out_size) {
    if (out_size < TT * HH + 1) return;
    float a = 0.0f;
    for (int e = 0; e < EE; e++) {
        float usage = (float)g_keptcnt[e] / (float)(TT * KK);
        float imp = g_importance[e] / (float)TT;
        a += usage * imp;
    }
    a *= (float)EE;
    if (g_dropped > 0.0f) a += g_dropped / (float)TT * 0.1f;
    a = fminf(a, 1.0f) * 0.001f;
    out[TT * HH] = a;
}

// ---------------- launch ----------------
extern "C" void kernel_launch(void* const* d_in, const int* in_sizes, int n_in,
                              void* d_out, int out_size) {
    const float* x      = (const float*)d_in[0];
    const float* w_gate = (const float*)d_in[1];
    const float* w1     = (const float*)d_in[2];
    const float* w3     = (const float*)d_in[3];
    const float* w2     = (const float*)d_in[4];
    float* out = (float*)d_out;

    cudaFuncSetAttribute(gemm1_mma, cudaFuncAttributeMaxDynamicSharedMemorySize, G1_SMEM);
    cudaFuncSetAttribute(gemm2_mma, cudaFuncAttributeMaxDynamicSharedMemorySize, G2_SMEM);

    __half* w1h_p; cudaGetSymbolAddress((void**)&w1h_p, g_w1h);
    __half* w3h_p; cudaGetSymbolAddress((void**)&w3h_p, g_w3h);
    __half* w2h_p; cudaGetSymbolAddress((void**)&w2h_p, g_w2h);

    const int NW4 = (EE * HH * II) / 4;   // 2359296

    zero_kernel<<<1, 32>>>();
    zero_out_kernel<<<(out_size + 255) / 256, 256>>>(out, out_size);
    cvth_kernel<<<(NW4 + 255) / 256, 256>>>((const float4*)w1, (uint2*)w1h_p, NW4);
    cvth_kernel<<<(NW4 + 255) / 256, 256>>>((const float4*)w3, (uint2*)w3h_p, NW4);
    cvth_kernel<<<(NW4 + 255) / 256, 256>>>((const float4*)w2, (uint2*)w2h_p, NW4);
    routing_kernel<<<TT, 256>>>(x, w_gate);
    scan_kernel<<<1, 1024>>>();
    gemm1_mma<<<dim3(II / 64, SLOTS / 128, EE), 256, G1_SMEM>>>();
    gemm2_mma<<<dim3(HH / 128, SLOTS / 128, EE), 256, G2_SMEM>>>(out);
    aux_kernel<<<1, 1>>>(out, out_size);
}

// round 12
// speedup vs baseline: 1.8365x; 1.0342x over previous
#include <cuda_runtime.h>
#include <cuda_bf16.h>
#include <cuda_fp16.h>
#include <stdint.h>
#include <math.h>

// Problem constants
#define TT 2048      // tokens (B*S)
#define HH 768       // hidden
#define II 1536      // intermediate
#define EE 8         // experts
#define KK 2         // top-k
#define CAP 768      // capacity
#define SLOTS (KK*CAP)   // 1536 slot rows per expert

// ---------------- scratch (device globals; allocation-free) ----------------
__device__ float g_importance[EE];
__device__ int   g_topk_idx[TT * KK];
__device__ float g_topk_w[TT * KK];
__device__ int   g_slot[TT * KK];
__device__ int   g_list[EE * SLOTS];
__device__ float g_wslot[EE * SLOTS];             // combine weight per (e,slot)
__device__ int   g_cnt[KK * EE];
__device__ int   g_keptcnt[EE];
__device__ float g_dropped;
__device__ __half g_xh[TT * HH];                  // x as fp16 (3MB)
__device__ __half g_w1h[EE * HH * II];            // w1 fp16 (~19MB)
__device__ __half g_w3h[EE * HH * II];            // w3 fp16 (~19MB)
__device__ __half g_w2h[EE * II * HH];            // w2 fp16 (~19MB)
__device__ __half g_hbufh[EE * SLOTS * II];       // SwiGLU intermediate fp16 (~38MB)

// ---------------- PTX helpers ----------------
__device__ __forceinline__ uint32_t s2u(const void* p) {
    uint32_t a;
    asm("{ .reg .u64 t; cvta.to.shared.u64 t, %1; cvt.u32.u64 %0, t; }" : "=r"(a) : "l"(p));
    return a;
}
__device__ __forceinline__ void cpa16(uint32_t dst, const void* src) {
    asm volatile("cp.async.cg.shared.global [%0], [%1], 16;" :: "r"(dst), "l"(src));
}
__device__ __forceinline__ void cpa_commit() { asm volatile("cp.async.commit_group;" ::: "memory"); }
template<int N> __device__ __forceinline__ void cpa_wait() {
    asm volatile("cp.async.wait_group %0;" :: "n"(N) : "memory");
}
__device__ __forceinline__ void ldsm4(uint32_t* r, uint32_t addr) {
    asm volatile("ldmatrix.sync.aligned.m8n8.x4.shared.b16 {%0,%1,%2,%3}, [%4];"
        : "=r"(r[0]), "=r"(r[1]), "=r"(r[2]), "=r"(r[3]) : "r"(addr));
}
__device__ __forceinline__ void ldsm4t(uint32_t* r, uint32_t addr) {
    asm volatile("ldmatrix.sync.aligned.m8n8.x4.trans.shared.b16 {%0,%1,%2,%3}, [%4];"
        : "=r"(r[0]), "=r"(r[1]), "=r"(r[2]), "=r"(r[3]) : "r"(addr));
}
__device__ __forceinline__ void mma16(float* d, const uint32_t* a, const uint32_t* b) {
    asm volatile(
        "mma.sync.aligned.m16n8k16.row.col.f32.f16.f16.f32 "
        "{%0,%1,%2,%3}, {%4,%5,%6,%7}, {%8,%9}, {%0,%1,%2,%3};"
        : "+f"(d[0]), "+f"(d[1]), "+f"(d[2]), "+f"(d[3])
        : "r"(a[0]), "r"(a[1]), "r"(a[2]), "r"(a[3]), "r"(b[0]), "r"(b[1]));
}

// ---------------- fp16 pre-convert (all 3 weights, one launch) ------------
__global__ void cvth3_kernel(const float4* __restrict__ w1,
                             const float4* __restrict__ w3,
                             const float4* __restrict__ w2,
                             uint2* __restrict__ d1,
                             uint2* __restrict__ d3,
                             uint2* __restrict__ d2, int n4) {
    int i = blockIdx.x * blockDim.x + threadIdx.x;
    if (i >= n4) return;
    const float4* src = (blockIdx.y == 0) ? w1 : (blockIdx.y == 1) ? w3 : w2;
    uint2* dst = (blockIdx.y == 0) ? d1 : (blockIdx.y == 1) ? d3 : d2;
    float4 v = src[i];
    __half2 h0 = __floats2half2_rn(v.x, v.y);
    __half2 h1 = __floats2half2_rn(v.z, v.w);
    uint2 o;
    o.x = *(uint32_t*)&h0;
    o.y = *(uint32_t*)&h1;
    dst[i] = o;
}

// ---------------- zero helpers ----------------
__global__ void zero_kernel() {
    if (threadIdx.x < EE) g_importance[threadIdx.x] = 0.0f;
}
__global__ void zero_out_kernel(float* __restrict__ out, int n) {
    int i = blockIdx.x * blockDim.x + threadIdx.x;
    if (i < n) out[i] = 0.0f;
}

// ---------------- routing (also emits x in fp16) ----------------
__global__ void routing_kernel(const float* __restrict__ x,
                               const float* __restrict__ wg) {
    int t = blockIdx.x;
    __shared__ float sx[HH];
    __shared__ float slog[EE];
    int tid = threadIdx.x;
    for (int i = tid; i < HH; i += 256) sx[i] = x[t * HH + i];
    __syncthreads();
    for (int i = tid; i < HH / 2; i += 256) {
        __half2 hv = __floats2half2_rn(sx[2 * i], sx[2 * i + 1]);
        *((__half2*)g_xh + (size_t)t * (HH / 2) + i) = hv;
    }
    int warp = tid >> 5, lane = tid & 31;
    float sum = 0.0f;
    for (int j = lane; j < HH; j += 32) sum += sx[j] * wg[j * EE + warp];
    for (int o = 16; o; o >>= 1) sum += __shfl_xor_sync(0xffffffffu, sum, o);
    if (lane == 0) slog[warp] = sum;
    __syncthreads();
    if (tid == 0) {
        float mx = slog[0];
        for (int e = 1; e < EE; e++) mx = fmaxf(mx, slog[e]);
        float p[EE], s = 0.0f;
        for (int e = 0; e < EE; e++) { p[e] = expf(slog[e] - mx); s += p[e]; }
        for (int e = 0; e < EE; e++) p[e] /= s;
        int e0 = 0;
        for (int e = 1; e < EE; e++) if (p[e] > p[e0]) e0 = e;
        int e1 = -1;
        for (int e = 0; e < EE; e++) {
            if (e == e0) continue;
            if (e1 < 0 || p[e] > p[e1]) e1 = e;
        }
        float ps = p[e0] + p[e1] + 1e-8f;
        float w0 = fminf(fmaxf(p[e0] / ps, 1e-8f), 10.0f);
        float w1 = fminf(fmaxf(p[e1] / ps, 1e-8f), 10.0f);
        g_topk_idx[t * 2 + 0] = e0;
        g_topk_idx[t * 2 + 1] = e1;
        g_topk_w[t * 2 + 0] = w0;
        g_topk_w[t * 2 + 1] = w1;
        for (int e = 0; e < EE; e++) atomicAdd(&g_importance[e], p[e]);
    }
}

// ---------------- scan ----------------
__global__ void scan_kernel() {
    __shared__ int warp_cnt[32][EE];
    __shared__ int warp_pref[32][EE];
    __shared__ int running[EE];
    __shared__ int chunk_tot[EE];
    __shared__ int tot[KK][EE];
    int tid = threadIdx.x, lane = tid & 31, warp = tid >> 5;

    for (int k = 0; k < KK; k++) {
        if (tid < EE) running[tid] = 0;
        __syncthreads();
        for (int chunk = 0; chunk < TT / 1024; chunk++) {
            int t = chunk * 1024 + tid;
            int e = g_topk_idx[t * 2 + k];
            unsigned mask = __match_any_sync(0xffffffffu, e);
            int lane_pref = __popc(mask & ((1u << lane) - 1));
            int warp_total = __popc(mask);
            if (tid < 32 * EE) warp_cnt[tid / EE][tid % EE] = 0;
            __syncthreads();
            if (lane_pref == 0) warp_cnt[warp][e] = warp_total;
            __syncthreads();
            if (tid < 32 * EE) {
                int w = tid / EE, ee = tid % EE;
                int p = 0;
                for (int ww = 0; ww < w; ww++) p += warp_cnt[ww][ee];
                warp_pref[w][ee] = p;
                if (w == 31) chunk_tot[ee] = p + warp_cnt[31][ee];
            }
            __syncthreads();
            int rank = running[e] + warp_pref[warp][e] + lane_pref + 1;
            bool kept = (rank <= CAP);
            int slot = kept ? (k * CAP + rank - 1) : -1;
            g_slot[t * 2 + k] = slot;
            if (kept) {
                g_list[e * SLOTS + slot] = t;
                g_wslot[e * SLOTS + slot] = g_topk_w[t * 2 + k];
            }
            __syncthreads();
            if (tid < EE) running[tid] += chunk_tot[tid];
            __syncthreads();
        }
        if (tid < EE) tot[k][tid] = running[tid];
        __syncthreads();
    }
    if (tid == 0) {
        int drop = 0;
        for (int e = 0; e < EE; e++) {
            int c0 = min(tot[0][e], CAP), c1 = min(tot[1][e], CAP);
            g_cnt[0 * EE + e] = c0;
            g_cnt[1 * EE + e] = c1;
            g_keptcnt[e] = c0 + c1;
            drop += (tot[0][e] - c0) + (tot[1][e] - c1);
        }
        g_dropped = (float)drop;
    }
}

// ================ GEMM1: fp16 mma + ldmatrix, KC=64, 3-stage, 2 CTAs/SM ====
// CTA: M=128 slots x N=128 (64 w1-cols + 64 w3-cols). 256 threads, 8 warps.
#define KC 64                   // K elements per chunk
#define APITCH 72               // halves per A row (64 data + 8 pad) = 144B
#define BPITCH 136              // halves per B k-row (128 data + 8 pad) = 272B
#define ABUF (128*APITCH)       // halves
#define BBUF (KC*BPITCH)        // halves
#define G1_SMEM ((3*ABUF + 3*BBUF) * 2 + 512)
__global__ void __launch_bounds__(256, 2) gemm1_mma() {
    extern __shared__ __half sh[];
    __half* Ash = sh;                 // 3 x ABUF
    __half* Bsh = sh + 3 * ABUF;      // 3 x BBUF
    int* stok = (int*)(Bsh + 3 * BBUF);

    int e = blockIdx.z, by = blockIdx.y, bx = blockIdx.x; // bx 0..23
    int kslot = (by >= 6) ? 1 : 0;
    int cnt = g_cnt[kslot * EE + e];
    int tile0 = (by - kslot * 6) * 128;
    if (tile0 >= cnt) return;
    int valid = min(128, cnt - tile0);
    int slot0 = by * 128;
    int tid = threadIdx.x;
    int lane = tid & 31, w = tid >> 5;
    int warpM = w >> 2, warpN = w & 3;

    if (tid < 128)
        stok[tid] = (tid < valid) ? g_list[e * SLOTS + slot0 + tid]
                                  : g_list[e * SLOTS + slot0];
    __syncthreads();

    const __half* w1b = g_w1h + (size_t)e * HH * II + bx * 64;
    const __half* w3b = g_w3h + (size_t)e * HH * II + bx * 64;

    auto fill = [&](int buf, int c) {
        uint32_t au = s2u(Ash + buf * ABUF);
        uint32_t bu_ = s2u(Bsh + buf * BBUF);
        int k0 = c * KC;
#pragma unroll
        for (int i = tid; i < 1024; i += 256) {   // A: 128 rows x 64 halves
            int row = i >> 3, seg = i & 7;
            cpa16(au + (uint32_t)(row * APITCH + seg * 8) * 2,
                  g_xh + (size_t)stok[row] * HH + k0 + seg * 8);
        }
#pragma unroll
        for (int i = tid; i < 1024; i += 256) {   // B: 64 k-rows x (64 G + 64 U)
            int k = i >> 4, seg = i & 15;
            const __half* src = (seg < 8) ? (w1b + (size_t)(k0 + k) * II + seg * 8)
                                          : (w3b + (size_t)(k0 + k) * II + (seg - 8) * 8);
            int dc = (seg < 8) ? seg * 8 : 64 + (seg - 8) * 8;
            cpa16(bu_ + (uint32_t)(k * BPITCH + dc) * 2, src);
        }
        cpa_commit();
    };

    const int NC = HH / KC; // 12
    fill(0, 0);
    fill(1, 1);

    float accG[4][2][4] = {}, accU[4][2][4] = {};
    int l15 = lane & 15;
    int lhi = (lane & 16) ? 8 : 0;

    for (int c = 0; c < NC; c++) {
        if (c + 1 < NC) cpa_wait<1>(); else cpa_wait<0>();
        __syncthreads();                // fill(c) visible; compute(c-1) done
        if (c + 2 < NC) fill((c + 2) % 3, c + 2);

        uint32_t au = s2u(Ash + (c % 3) * ABUF);
        uint32_t bu_ = s2u(Bsh + (c % 3) * BBUF);
#pragma unroll
        for (int ks = 0; ks < KC / 16; ks++) {
            uint32_t af[4][4];
#pragma unroll
            for (int mf = 0; mf < 4; mf++) {
                int row = warpM * 64 + mf * 16 + l15;
                int col = ks * 16 + lhi;
                ldsm4(af[mf], au + (uint32_t)(row * APITCH + col) * 2);
            }
            int k = ks * 16 + l15;
            int nG = warpN * 16 + lhi;
            uint32_t bg[4], bu2[4];
            ldsm4t(bg,  bu_ + (uint32_t)(k * BPITCH + nG) * 2);
            ldsm4t(bu2, bu_ + (uint32_t)(k * BPITCH + 64 + nG) * 2);
#pragma unroll
            for (int mf = 0; mf < 4; mf++) {
                mma16(accG[mf][0], af[mf], bg);
                mma16(accG[mf][1], af[mf], bg + 2);
                mma16(accU[mf][0], af[mf], bu2);
                mma16(accU[mf][1], af[mf], bu2 + 2);
            }
        }
    }

    // epilogue: SwiGLU, write hbuf as fp16
#pragma unroll
    for (int mf = 0; mf < 4; mf++) {
        int rbase = warpM * 64 + mf * 16 + (lane >> 2);
#pragma unroll
        for (int nf = 0; nf < 2; nf++) {
            int col = bx * 64 + warpN * 16 + nf * 8 + 2 * (lane & 3);
#pragma unroll
            for (int h = 0; h < 2; h++) {
                int r = rbase + h * 8;
                if (r < valid) {
                    float g0 = accG[mf][nf][h * 2 + 0], g1 = accG[mf][nf][h * 2 + 1];
                    float u0 = accU[mf][nf][h * 2 + 0], u1 = accU[mf][nf][h * 2 + 1];
                    __half2 hv = __floats2half2_rn(g0 / (1.0f + expf(-g0)) * u0,
                                                   g1 / (1.0f + expf(-g1)) * u1);
                    *(__half2*)&g_hbufh[((size_t)e * SLOTS + slot0 + r) * II + col] = hv;
                }
            }
        }
    }
}

// ================ GEMM2: fp16 mma + ldmatrix, KC=64, 3-stage, fused combine
// CTA: M=128 slots x N=128 H-cols. 256 threads. warp: 64 x 32.
#define G2_SMEM ((3*ABUF + 3*BBUF) * 2 + 128*4 + 128*4)
__global__ void __launch_bounds__(256, 2) gemm2_mma(float* __restrict__ out) {
    extern __shared__ __half sh[];
    __half* Ash = sh;
    __half* Bsh = sh + 3 * ABUF;
    int* tok2 = (int*)(Bsh + 3 * BBUF);
    float* wt2 = (float*)(tok2 + 128);

    int e = blockIdx.z, by = blockIdx.y, bx = blockIdx.x; // bx 0..5
    int kslot = (by >= 6) ? 1 : 0;
    int cnt = g_cnt[kslot * EE + e];
    int tile0 = (by - kslot * 6) * 128;
    if (tile0 >= cnt) return;
    int valid = min(128, cnt - tile0);
    int slot0 = by * 128;
    int tid = threadIdx.x;
    int lane = tid & 31, w = tid >> 5;
    int warpM = w >> 2, warpN = w & 3;

    if (tid < 128) {
        bool v = tid < valid;
        tok2[tid] = v ? g_list[e * SLOTS + slot0 + tid] : 0;
        wt2[tid]  = v ? g_wslot[e * SLOTS + slot0 + tid] : 0.0f;
    }
    __syncthreads();

    const __half* Ab = g_hbufh + ((size_t)e * SLOTS + slot0) * II;
    const __half* Bb = g_w2h + (size_t)e * II * HH + bx * 128;

    auto fill = [&](int buf, int c) {
        uint32_t au = s2u(Ash + buf * ABUF);
        uint32_t bu_ = s2u(Bsh + buf * BBUF);
        int k0 = c * KC;
#pragma unroll
        for (int i = tid; i < 1024; i += 256) {
            int row = i >> 3, seg = i & 7;
            cpa16(au + (uint32_t)(row * APITCH + seg * 8) * 2,
                  Ab + (size_t)row * II + k0 + seg * 8);
        }
#pragma unroll
        for (int i = tid; i < 1024; i += 256) {
            int k = i >> 4, seg = i & 15;
            cpa16(bu_ + (uint32_t)(k * BPITCH + seg * 8) * 2,
                  Bb + (size_t)(k0 + k) * HH + seg * 8);
        }
        cpa_commit();
    };

    const int NC = II / KC; // 24
    fill(0, 0);
    fill(1, 1);

    float acc[4][4][4] = {};
    int l15 = lane & 15;
    int lhi = (lane & 16) ? 8 : 0;

    for (int c = 0; c < NC; c++) {
        if (c + 1 < NC) cpa_wait<1>(); else cpa_wait<0>();
        __syncthreads();
        if (c + 2 < NC) fill((c + 2) % 3, c + 2);

        uint32_t au = s2u(Ash + (c % 3) * ABUF);
        uint32_t bu_ = s2u(Bsh + (c % 3) * BBUF);
#pragma unroll
        for (int ks = 0; ks < KC / 16; ks++) {
            uint32_t af[4][4];
#pragma unroll
            for (int mf = 0; mf < 4; mf++) {
                int row = warpM * 64 + mf * 16 + l15;
                int col = ks * 16 + lhi;
                ldsm4(af[mf], au + (uint32_t)(row * APITCH + col) * 2);
            }
            int k = ks * 16 + l15;
            int nB = warpN * 32 + lhi;
            uint32_t bf[8];
            ldsm4t(bf,     bu_ + (uint32_t)(k * BPITCH + nB) * 2);
            ldsm4t(bf + 4, bu_ + (uint32_t)(k * BPITCH + nB + 16) * 2);
#pragma unroll
            for (int mf = 0; mf < 4; mf++) {
                mma16(acc[mf][0], af[mf], bf);
                mma16(acc[mf][1], af[mf], bf + 2);
                mma16(acc[mf][2], af[mf], bf + 4);
                mma16(acc[mf][3], af[mf], bf + 6);
            }
        }
    }

    // fused combine: out[token] += w * acc
#pragma unroll
    for (int mf = 0; mf < 4; mf++) {
        int rbase = warpM * 64 + mf * 16 + (lane >> 2);
#pragma unroll
        for (int nf = 0; nf < 4; nf++) {
            int col = bx * 128 + warpN * 32 + nf * 8 + 2 * (lane & 3);
#pragma unroll
            for (int h = 0; h < 2; h++) {
                int r = rbase + h * 8;
                if (r < valid) {
                    float wv = wt2[r];
                    float* op = out + (size_t)tok2[r] * HH + col;
                    atomicAdd(op,     wv * acc[mf][nf][h * 2 + 0]);
                    atomicAdd(op + 1, wv * acc[mf][nf][h * 2 + 1]);
                }
            }
        }
    }
}

// ---------------- aux ----------------
__global__ void aux_kernel(float* __restrict__ out, int out_size) {
    if (out_size < TT * HH + 1) return;
    float a = 0.0f;
    for (int e = 0; e < EE; e++) {
        float usage = (float)g_keptcnt[e] / (float)(TT * KK);
        float imp = g_importance[e] / (float)TT;
        a += usage * imp;
    }
    a *= (float)EE;
    if (g_dropped > 0.0f) a += g_dropped / (float)TT * 0.1f;
    a = fminf(a, 1.0f) * 0.001f;
    out[TT * HH] = a;
}

// ---------------- launch ----------------
extern "C" void kernel_launch(void* const* d_in, const int* in_sizes, int n_in,
                              void* d_out, int out_size) {
    const float* x      = (const float*)d_in[0];
    const float* w_gate = (const float*)d_in[1];
    const float* w1     = (const float*)d_in[2];
    const float* w3     = (const float*)d_in[3];
    const float* w2     = (const float*)d_in[4];
    float* out = (float*)d_out;

    cudaFuncSetAttribute(gemm1_mma, cudaFuncAttributeMaxDynamicSharedMemorySize, G1_SMEM);
    cudaFuncSetAttribute(gemm2_mma, cudaFuncAttributeMaxDynamicSharedMemorySize, G2_SMEM);

    __half* w1h_p; cudaGetSymbolAddress((void**)&w1h_p, g_w1h);
    __half* w3h_p; cudaGetSymbolAddress((void**)&w3h_p, g_w3h);
    __half* w2h_p; cudaGetSymbolAddress((void**)&w2h_p, g_w2h);

    const int NW4 = (EE * HH * II) / 4;   // 2359296

    zero_kernel<<<1, 32>>>();
    zero_out_kernel<<<(out_size + 255) / 256, 256>>>(out, out_size);
    cvth3_kernel<<<dim3((NW4 + 255) / 256, 3), 256>>>(
        (const float4*)w1, (const float4*)w3, (const float4*)w2,
        (uint2*)w1h_p, (uint2*)w3h_p, (uint2*)w2h_p, NW4);
    routing_kernel<<<TT, 256>>>(x, w_gate);
    scan_kernel<<<1, 1024>>>();
    gemm1_mma<<<dim3(II / 64, SLOTS / 128, EE), 256, G1_SMEM>>>();
    gemm2_mma<<<dim3(HH / 128, SLOTS / 128, EE), 256, G2_SMEM>>>(out);
    aux_kernel<<<1, 1>>>(out, out_size);
}

// round 13
// speedup vs baseline: 2.0189x; 1.0993x over previous
#include <cuda_runtime.h>
#include <cuda_bf16.h>
#include <cuda_fp16.h>
#include <stdint.h>
#include <math.h>

// Problem constants
#define TT 2048      // tokens (B*S)
#define HH 768       // hidden
#define II 1536      // intermediate
#define EE 8         // experts
#define KK 2         // top-k
#define CAP 768      // capacity
#define SLOTS (KK*CAP)   // 1536 slot rows per expert

// ---------------- scratch (device globals; allocation-free) ----------------
__device__ float g_importance[EE];
__device__ int   g_topk_idx[TT * KK];
__device__ float g_topk_w[TT * KK];
__device__ int   g_slot[TT * KK];
__device__ int   g_list[EE * SLOTS];
__device__ float g_wslot[EE * SLOTS];             // combine weight per (e,slot)
__device__ int   g_cnt[KK * EE];
__device__ int   g_keptcnt[EE];
__device__ float g_dropped;
__device__ __half g_xh[TT * HH];                  // x as fp16 (3MB)
__device__ __half g_w1h[EE * HH * II];            // w1 fp16 (~19MB)
__device__ __half g_w3h[EE * HH * II];            // w3 fp16 (~19MB)
__device__ __half g_w2h[EE * II * HH];            // w2 fp16 (~19MB)
__device__ __half g_hbufh[EE * SLOTS * II];       // SwiGLU intermediate fp16 (~38MB)

// ---------------- PTX helpers ----------------
__device__ __forceinline__ uint32_t s2u(const void* p) {
    uint32_t a;
    asm("{ .reg .u64 t; cvta.to.shared.u64 t, %1; cvt.u32.u64 %0, t; }" : "=r"(a) : "l"(p));
    return a;
}
__device__ __forceinline__ void cpa16(uint32_t dst, const void* src) {
    asm volatile("cp.async.cg.shared.global [%0], [%1], 16;" :: "r"(dst), "l"(src));
}
__device__ __forceinline__ void cpa_commit() { asm volatile("cp.async.commit_group;" ::: "memory"); }
template<int N> __device__ __forceinline__ void cpa_wait() {
    asm volatile("cp.async.wait_group %0;" :: "n"(N) : "memory");
}
__device__ __forceinline__ void ldsm4(uint32_t* r, uint32_t addr) {
    asm volatile("ldmatrix.sync.aligned.m8n8.x4.shared.b16 {%0,%1,%2,%3}, [%4];"
        : "=r"(r[0]), "=r"(r[1]), "=r"(r[2]), "=r"(r[3]) : "r"(addr));
}
__device__ __forceinline__ void ldsm4t(uint32_t* r, uint32_t addr) {
    asm volatile("ldmatrix.sync.aligned.m8n8.x4.trans.shared.b16 {%0,%1,%2,%3}, [%4];"
        : "=r"(r[0]), "=r"(r[1]), "=r"(r[2]), "=r"(r[3]) : "r"(addr));
}
__device__ __forceinline__ void mma16(float* d, const uint32_t* a, const uint32_t* b) {
    asm volatile(
        "mma.sync.aligned.m16n8k16.row.col.f32.f16.f16.f32 "
        "{%0,%1,%2,%3}, {%4,%5,%6,%7}, {%8,%9}, {%0,%1,%2,%3};"
        : "+f"(d[0]), "+f"(d[1]), "+f"(d[2]), "+f"(d[3])
        : "r"(a[0]), "r"(a[1]), "r"(a[2]), "r"(a[3]), "r"(b[0]), "r"(b[1]));
}

// ---------------- fp16 pre-convert (all 3 weights, one launch) ------------
__global__ void cvth3_kernel(const float4* __restrict__ w1,
                             const float4* __restrict__ w3,
                             const float4* __restrict__ w2,
                             uint2* __restrict__ d1,
                             uint2* __restrict__ d3,
                             uint2* __restrict__ d2, int n4) {
    int i = blockIdx.x * blockDim.x + threadIdx.x;
    if (i >= n4) return;
    const float4* src = (blockIdx.y == 0) ? w1 : (blockIdx.y == 1) ? w3 : w2;
    uint2* dst = (blockIdx.y == 0) ? d1 : (blockIdx.y == 1) ? d3 : d2;
    float4 v = src[i];
    __half2 h0 = __floats2half2_rn(v.x, v.y);
    __half2 h1 = __floats2half2_rn(v.z, v.w);
    uint2 o;
    o.x = *(uint32_t*)&h0;
    o.y = *(uint32_t*)&h1;
    dst[i] = o;
}

// ---------------- zero helpers ----------------
__global__ void zero_kernel() {
    if (threadIdx.x < EE) g_importance[threadIdx.x] = 0.0f;
}
__global__ void zero_out_kernel(float* __restrict__ out, int n) {
    int i = blockIdx.x * blockDim.x + threadIdx.x;
    if (i < n) out[i] = 0.0f;
}

// ---------------- routing: warp-per-token (8 tokens/block) -----------------
// Same accumulation order as before (j strided by 32 per lane + butterfly),
// so logits are bit-identical to the block-per-token version.
__global__ void routing_kernel(const float* __restrict__ x,
                               const float* __restrict__ wg) {
    __shared__ float simp[EE];
    int tid = threadIdx.x, lane = tid & 31, w = tid >> 5;
    if (tid < EE) simp[tid] = 0.0f;
    __syncthreads();

    int t = blockIdx.x * 8 + w;
    const float* xr = x + (size_t)t * HH;
    float acc[EE] = {};
    for (int j = lane; j < HH; j += 32) {
        float xv = xr[j];
        g_xh[(size_t)t * HH + j] = __float2half_rn(xv);
        float4 w0 = *(const float4*)(wg + j * EE);
        float4 w1 = *(const float4*)(wg + j * EE + 4);
        acc[0] += xv * w0.x; acc[1] += xv * w0.y;
        acc[2] += xv * w0.z; acc[3] += xv * w0.w;
        acc[4] += xv * w1.x; acc[5] += xv * w1.y;
        acc[6] += xv * w1.z; acc[7] += xv * w1.w;
    }
#pragma unroll
    for (int o = 16; o; o >>= 1)
#pragma unroll
        for (int e = 0; e < EE; e++) acc[e] += __shfl_xor_sync(0xffffffffu, acc[e], o);

    if (lane == 0) {
        float mx = acc[0];
        for (int e = 1; e < EE; e++) mx = fmaxf(mx, acc[e]);
        float p[EE], s = 0.0f;
        for (int e = 0; e < EE; e++) { p[e] = expf(acc[e] - mx); s += p[e]; }
        for (int e = 0; e < EE; e++) p[e] /= s;
        int e0 = 0;
        for (int e = 1; e < EE; e++) if (p[e] > p[e0]) e0 = e;
        int e1 = -1;
        for (int e = 0; e < EE; e++) {
            if (e == e0) continue;
            if (e1 < 0 || p[e] > p[e1]) e1 = e;
        }
        float ps = p[e0] + p[e1] + 1e-8f;
        float w0 = fminf(fmaxf(p[e0] / ps, 1e-8f), 10.0f);
        float w1 = fminf(fmaxf(p[e1] / ps, 1e-8f), 10.0f);
        g_topk_idx[t * 2 + 0] = e0;
        g_topk_idx[t * 2 + 1] = e1;
        g_topk_w[t * 2 + 0] = w0;
        g_topk_w[t * 2 + 1] = w1;
        for (int e = 0; e < EE; e++) atomicAdd(&simp[e], p[e]);
    }
    __syncthreads();
    if (tid < EE) atomicAdd(&g_importance[tid], simp[tid]);
}

// ---------------- scan ----------------
__global__ void scan_kernel() {
    __shared__ int warp_cnt[32][EE];
    __shared__ int warp_pref[32][EE];
    __shared__ int running[EE];
    __shared__ int chunk_tot[EE];
    __shared__ int tot[KK][EE];
    int tid = threadIdx.x, lane = tid & 31, warp = tid >> 5;

    for (int k = 0; k < KK; k++) {
        if (tid < EE) running[tid] = 0;
        __syncthreads();
        for (int chunk = 0; chunk < TT / 1024; chunk++) {
            int t = chunk * 1024 + tid;
            int e = g_topk_idx[t * 2 + k];
            unsigned mask = __match_any_sync(0xffffffffu, e);
            int lane_pref = __popc(mask & ((1u << lane) - 1));
            int warp_total = __popc(mask);
            if (tid < 32 * EE) warp_cnt[tid / EE][tid % EE] = 0;
            __syncthreads();
            if (lane_pref == 0) warp_cnt[warp][e] = warp_total;
            __syncthreads();
            if (tid < 32 * EE) {
                int w = tid / EE, ee = tid % EE;
                int p = 0;
                for (int ww = 0; ww < w; ww++) p += warp_cnt[ww][ee];
                warp_pref[w][ee] = p;
                if (w == 31) chunk_tot[ee] = p + warp_cnt[31][ee];
            }
            __syncthreads();
            int rank = running[e] + warp_pref[warp][e] + lane_pref + 1;
            bool kept = (rank <= CAP);
            int slot = kept ? (k * CAP + rank - 1) : -1;
            g_slot[t * 2 + k] = slot;
            if (kept) {
                g_list[e * SLOTS + slot] = t;
                g_wslot[e * SLOTS + slot] = g_topk_w[t * 2 + k];
            }
            __syncthreads();
            if (tid < EE) running[tid] += chunk_tot[tid];
            __syncthreads();
        }
        if (tid < EE) tot[k][tid] = running[tid];
        __syncthreads();
    }
    if (tid == 0) {
        int drop = 0;
        for (int e = 0; e < EE; e++) {
            int c0 = min(tot[0][e], CAP), c1 = min(tot[1][e], CAP);
            g_cnt[0 * EE + e] = c0;
            g_cnt[1 * EE + e] = c1;
            g_keptcnt[e] = c0 + c1;
            drop += (tot[0][e] - c0) + (tot[1][e] - c1);
        }
        g_dropped = (float)drop;
    }
}

// ================ GEMM1: fp16 mma + ldmatrix, KC=64, 3-stage, 2 CTAs/SM ====
// CTA: M=128 slots x N=128 (64 w1-cols + 64 w3-cols). 256 threads, 8 warps.
#define KC 64                   // K elements per chunk
#define APITCH 72               // halves per A row (64 data + 8 pad) = 144B
#define BPITCH 136              // halves per B k-row (128 data + 8 pad) = 272B
#define ABUF (128*APITCH)       // halves
#define BBUF (KC*BPITCH)        // halves
#define G1_SMEM ((3*ABUF + 3*BBUF) * 2 + 512)
__global__ void __launch_bounds__(256, 2) gemm1_mma() {
    extern __shared__ __half sh[];
    __half* Ash = sh;                 // 3 x ABUF
    __half* Bsh = sh + 3 * ABUF;      // 3 x BBUF
    int* stok = (int*)(Bsh + 3 * BBUF);

    int e = blockIdx.z, by = blockIdx.y, bx = blockIdx.x; // bx 0..23
    int kslot = (by >= 6) ? 1 : 0;
    int cnt = g_cnt[kslot * EE + e];
    int tile0 = (by - kslot * 6) * 128;
    if (tile0 >= cnt) return;
    int valid = min(128, cnt - tile0);
    int slot0 = by * 128;
    int tid = threadIdx.x;
    int lane = tid & 31, w = tid >> 5;
    int warpM = w >> 2, warpN = w & 3;

    if (tid < 128)
        stok[tid] = (tid < valid) ? g_list[e * SLOTS + slot0 + tid]
                                  : g_list[e * SLOTS + slot0];
    __syncthreads();

    const __half* w1b = g_w1h + (size_t)e * HH * II + bx * 64;
    const __half* w3b = g_w3h + (size_t)e * HH * II + bx * 64;

    auto fill = [&](int buf, int c) {
        uint32_t au = s2u(Ash + buf * ABUF);
        uint32_t bu_ = s2u(Bsh + buf * BBUF);
        int k0 = c * KC;
#pragma unroll
        for (int i = tid; i < 1024; i += 256) {   // A: 128 rows x 64 halves
            int row = i >> 3, seg = i & 7;
            cpa16(au + (uint32_t)(row * APITCH + seg * 8) * 2,
                  g_xh + (size_t)stok[row] * HH + k0 + seg * 8);
        }
#pragma unroll
        for (int i = tid; i < 1024; i += 256) {   // B: 64 k-rows x (64 G + 64 U)
            int k = i >> 4, seg = i & 15;
            const __half* src = (seg < 8) ? (w1b + (size_t)(k0 + k) * II + seg * 8)
                                          : (w3b + (size_t)(k0 + k) * II + (seg - 8) * 8);
            int dc = (seg < 8) ? seg * 8 : 64 + (seg - 8) * 8;
            cpa16(bu_ + (uint32_t)(k * BPITCH + dc) * 2, src);
        }
        cpa_commit();
    };

    const int NC = HH / KC; // 12
    fill(0, 0);
    fill(1, 1);

    float accG[4][2][4] = {}, accU[4][2][4] = {};
    int l15 = lane & 15;
    int lhi = (lane & 16) ? 8 : 0;

    for (int c = 0; c < NC; c++) {
        if (c + 1 < NC) cpa_wait<1>(); else cpa_wait<0>();
        __syncthreads();                // fill(c) visible; compute(c-1) done
        if (c + 2 < NC) fill((c + 2) % 3, c + 2);

        uint32_t au = s2u(Ash + (c % 3) * ABUF);
        uint32_t bu_ = s2u(Bsh + (c % 3) * BBUF);
#pragma unroll
        for (int ks = 0; ks < KC / 16; ks++) {
            uint32_t af[4][4];
#pragma unroll
            for (int mf = 0; mf < 4; mf++) {
                int row = warpM * 64 + mf * 16 + l15;
                int col = ks * 16 + lhi;
                ldsm4(af[mf], au + (uint32_t)(row * APITCH + col) * 2);
            }
            int k = ks * 16 + l15;
            int nG = warpN * 16 + lhi;
            uint32_t bg[4], bu2[4];
            ldsm4t(bg,  bu_ + (uint32_t)(k * BPITCH + nG) * 2);
            ldsm4t(bu2, bu_ + (uint32_t)(k * BPITCH + 64 + nG) * 2);
#pragma unroll
            for (int mf = 0; mf < 4; mf++) {
                mma16(accG[mf][0], af[mf], bg);
                mma16(accG[mf][1], af[mf], bg + 2);
                mma16(accU[mf][0], af[mf], bu2);
                mma16(accU[mf][1], af[mf], bu2 + 2);
            }
        }
    }

    // epilogue: SwiGLU, write hbuf as fp16
#pragma unroll
    for (int mf = 0; mf < 4; mf++) {
        int rbase = warpM * 64 + mf * 16 + (lane >> 2);
#pragma unroll
        for (int nf = 0; nf < 2; nf++) {
            int col = bx * 64 + warpN * 16 + nf * 8 + 2 * (lane & 3);
#pragma unroll
            for (int h = 0; h < 2; h++) {
                int r = rbase + h * 8;
                if (r < valid) {
                    float g0 = accG[mf][nf][h * 2 + 0], g1 = accG[mf][nf][h * 2 + 1];
                    float u0 = accU[mf][nf][h * 2 + 0], u1 = accU[mf][nf][h * 2 + 1];
                    __half2 hv = __floats2half2_rn(g0 / (1.0f + expf(-g0)) * u0,
                                                   g1 / (1.0f + expf(-g1)) * u1);
                    *(__half2*)&g_hbufh[((size_t)e * SLOTS + slot0 + r) * II + col] = hv;
                }
            }
        }
    }
}

// ================ GEMM2: fp16 mma + ldmatrix, KC=64, 3-stage, fused combine
// CTA: M=128 slots x N=128 H-cols. 256 threads. warp: 64 x 32.
#define G2_SMEM ((3*ABUF + 3*BBUF) * 2 + 128*4 + 128*4)
__global__ void __launch_bounds__(256, 2) gemm2_mma(float* __restrict__ out) {
    extern __shared__ __half sh[];
    __half* Ash = sh;
    __half* Bsh = sh + 3 * ABUF;
    int* tok2 = (int*)(Bsh + 3 * BBUF);
    float* wt2 = (float*)(tok2 + 128);

    int e = blockIdx.z, by = blockIdx.y, bx = blockIdx.x; // bx 0..5
    int kslot = (by >= 6) ? 1 : 0;
    int cnt = g_cnt[kslot * EE + e];
    int tile0 = (by - kslot * 6) * 128;
    if (tile0 >= cnt) return;
    int valid = min(128, cnt - tile0);
    int slot0 = by * 128;
    int tid = threadIdx.x;
    int lane = tid & 31, w = tid >> 5;
    int warpM = w >> 2, warpN = w & 3;

    if (tid < 128) {
        bool v = tid < valid;
        tok2[tid] = v ? g_list[e * SLOTS + slot0 + tid] : 0;
        wt2[tid]  = v ? g_wslot[e * SLOTS + slot0 + tid] : 0.0f;
    }
    __syncthreads();

    const __half* Ab = g_hbufh + ((size_t)e * SLOTS + slot0) * II;
    const __half* Bb = g_w2h + (size_t)e * II * HH + bx * 128;

    auto fill = [&](int buf, int c) {
        uint32_t au = s2u(Ash + buf * ABUF);
        uint32_t bu_ = s2u(Bsh + buf * BBUF);
        int k0 = c * KC;
#pragma unroll
        for (int i = tid; i < 1024; i += 256) {
            int row = i >> 3, seg = i & 7;
            cpa16(au + (uint32_t)(row * APITCH + seg * 8) * 2,
                  Ab + (size_t)row * II + k0 + seg * 8);
        }
#pragma unroll
        for (int i = tid; i < 1024; i += 256) {
            int k = i >> 4, seg = i & 15;
            cpa16(bu_ + (uint32_t)(k * BPITCH + seg * 8) * 2,
                  Bb + (size_t)(k0 + k) * HH + seg * 8);
        }
        cpa_commit();
    };

    const int NC = II / KC; // 24
    fill(0, 0);
    fill(1, 1);

    float acc[4][4][4] = {};
    int l15 = lane & 15;
    int lhi = (lane & 16) ? 8 : 0;

    for (int c = 0; c < NC; c++) {
        if (c + 1 < NC) cpa_wait<1>(); else cpa_wait<0>();
        __syncthreads();
        if (c + 2 < NC) fill((c + 2) % 3, c + 2);

        uint32_t au = s2u(Ash + (c % 3) * ABUF);
        uint32_t bu_ = s2u(Bsh + (c % 3) * BBUF);
#pragma unroll
        for (int ks = 0; ks < KC / 16; ks++) {
            uint32_t af[4][4];
#pragma unroll
            for (int mf = 0; mf < 4; mf++) {
                int row = warpM * 64 + mf * 16 + l15;
                int col = ks * 16 + lhi;
                ldsm4(af[mf], au + (uint32_t)(row * APITCH + col) * 2);
            }
            int k = ks * 16 + l15;
            int nB = warpN * 32 + lhi;
            uint32_t bf[8];
            ldsm4t(bf,     bu_ + (uint32_t)(k * BPITCH + nB) * 2);
            ldsm4t(bf + 4, bu_ + (uint32_t)(k * BPITCH + nB + 16) * 2);
#pragma unroll
            for (int mf = 0; mf < 4; mf++) {
                mma16(acc[mf][0], af[mf], bf);
                mma16(acc[mf][1], af[mf], bf + 2);
                mma16(acc[mf][2], af[mf], bf + 4);
                mma16(acc[mf][3], af[mf], bf + 6);
            }
        }
    }

    // fused combine: out[token] += w * acc
#pragma unroll
    for (int mf = 0; mf < 4; mf++) {
        int rbase = warpM * 64 + mf * 16 + (lane >> 2);
#pragma unroll
        for (int nf = 0; nf < 4; nf++) {
            int col = bx * 128 + warpN * 32 + nf * 8 + 2 * (lane & 3);
#pragma unroll
            for (int h = 0; h < 2; h++) {
                int r = rbase + h * 8;
                if (r < valid) {
                    float wv = wt2[r];
                    float* op = out + (size_t)tok2[r] * HH + col;
                    atomicAdd(op,     wv * acc[mf][nf][h * 2 + 0]);
                    atomicAdd(op + 1, wv * acc[mf][nf][h * 2 + 1]);
                }
            }
        }
    }
}

// ---------------- aux ----------------
__global__ void aux_kernel(float* __restrict__ out, int out_size) {
    if (out_size < TT * HH + 1) return;
    float a = 0.0f;
    for (int e = 0; e < EE; e++) {
        float usage = (float)g_keptcnt[e] / (float)(TT * KK);
        float imp = g_importance[e] / (float)TT;
        a += usage * imp;
    }
    a *= (float)EE;
    if (g_dropped > 0.0f) a += g_dropped / (float)TT * 0.1f;
    a = fminf(a, 1.0f) * 0.001f;
    out[TT * HH] = a;
}

// ---------------- launch ----------------
extern "C" void kernel_launch(void* const* d_in, const int* in_sizes, int n_in,
                              void* d_out, int out_size) {
    const float* x      = (const float*)d_in[0];
    const float* w_gate = (const float*)d_in[1];
    const float* w1     = (const float*)d_in[2];
    const float* w3     = (const float*)d_in[3];
    const float* w2     = (const float*)d_in[4];
    float* out = (float*)d_out;

    cudaFuncSetAttribute(gemm1_mma, cudaFuncAttributeMaxDynamicSharedMemorySize, G1_SMEM);
    cudaFuncSetAttribute(gemm2_mma, cudaFuncAttributeMaxDynamicSharedMemorySize, G2_SMEM);

    __half* w1h_p; cudaGetSymbolAddress((void**)&w1h_p, g_w1h);
    __half* w3h_p; cudaGetSymbolAddress((void**)&w3h_p, g_w3h);
    __half* w2h_p; cudaGetSymbolAddress((void**)&w2h_p, g_w2h);

    const int NW4 = (EE * HH * II) / 4;   // 2359296

    zero_kernel<<<1, 32>>>();
    zero_out_kernel<<<(out_size + 255) / 256, 256>>>(out, out_size);
    cvth3_kernel<<<dim3((NW4 + 255) / 256, 3), 256>>>(
        (const float4*)w1, (const float4*)w3, (const float4*)w2,
        (uint2*)w1h_p, (uint2*)w3h_p, (uint2*)w2h_p, NW4);
    routing_kernel<<<TT / 8, 256>>>(x, w_gate);
    scan_kernel<<<1, 1024>>>();
    gemm1_mma<<<dim3(II / 64, SLOTS / 128, EE), 256, G1_SMEM>>>();
    gemm2_mma<<<dim3(HH / 128, SLOTS / 128, EE), 256, G2_SMEM>>>(out);
    aux_kernel<<<1, 1>>>(out, out_size);
}

// round 14
// speedup vs baseline: 2.0373x; 1.0091x over previous
#include <cuda_runtime.h>
#include <cuda_bf16.h>
#include <cuda_fp16.h>
#include <stdint.h>
#include <math.h>

// Problem constants
#define TT 2048      // tokens (B*S)
#define HH 768       // hidden
#define II 1536      // intermediate
#define EE 8         // experts
#define KK 2         // top-k
#define CAP 768      // capacity
#define SLOTS (KK*CAP)   // 1536 slot rows per expert

// ---------------- scratch (device globals; allocation-free) ----------------
__device__ float g_importance[EE];
__device__ int   g_topk_idx[TT * KK];
__device__ float g_topk_w[TT * KK];
__device__ int   g_slot[TT * KK];
__device__ int   g_list[EE * SLOTS];
__device__ float g_wslot[EE * SLOTS];             // combine weight per (e,slot)
__device__ int   g_cnt[KK * EE];
__device__ int   g_keptcnt[EE];
__device__ float g_dropped;
__device__ __half g_xh[TT * HH];                  // x as fp16 (3MB)
__device__ __half g_w1h[EE * HH * II];            // w1 fp16 (~19MB)
__device__ __half g_w3h[EE * HH * II];            // w3 fp16 (~19MB)
__device__ __half g_w2h[EE * II * HH];            // w2 fp16 (~19MB)
__device__ __half g_hbufh[EE * SLOTS * II];       // SwiGLU intermediate fp16 (~38MB)

// ---------------- PTX helpers ----------------
__device__ __forceinline__ uint32_t s2u(const void* p) {
    uint32_t a;
    asm("{ .reg .u64 t; cvta.to.shared.u64 t, %1; cvt.u32.u64 %0, t; }" : "=r"(a) : "l"(p));
    return a;
}
__device__ __forceinline__ void cpa16(uint32_t dst, const void* src) {
    asm volatile("cp.async.cg.shared.global [%0], [%1], 16;" :: "r"(dst), "l"(src));
}
__device__ __forceinline__ void cpa_commit() { asm volatile("cp.async.commit_group;" ::: "memory"); }
template<int N> __device__ __forceinline__ void cpa_wait() {
    asm volatile("cp.async.wait_group %0;" :: "n"(N) : "memory");
}
__device__ __forceinline__ void ldsm4(uint32_t* r, uint32_t addr) {
    asm volatile("ldmatrix.sync.aligned.m8n8.x4.shared.b16 {%0,%1,%2,%3}, [%4];"
        : "=r"(r[0]), "=r"(r[1]), "=r"(r[2]), "=r"(r[3]) : "r"(addr));
}
__device__ __forceinline__ void ldsm4t(uint32_t* r, uint32_t addr) {
    asm volatile("ldmatrix.sync.aligned.m8n8.x4.trans.shared.b16 {%0,%1,%2,%3}, [%4];"
        : "=r"(r[0]), "=r"(r[1]), "=r"(r[2]), "=r"(r[3]) : "r"(addr));
}
__device__ __forceinline__ void mma16(float* d, const uint32_t* a, const uint32_t* b) {
    asm volatile(
        "mma.sync.aligned.m16n8k16.row.col.f32.f16.f16.f32 "
        "{%0,%1,%2,%3}, {%4,%5,%6,%7}, {%8,%9}, {%0,%1,%2,%3};"
        : "+f"(d[0]), "+f"(d[1]), "+f"(d[2]), "+f"(d[3])
        : "r"(a[0]), "r"(a[1]), "r"(a[2]), "r"(a[3]), "r"(b[0]), "r"(b[1]));
}

// ---------------- fp16 pre-convert: 8 floats/thread, uint4 store ----------
__global__ void cvth3_kernel(const float4* __restrict__ w1,
                             const float4* __restrict__ w3,
                             const float4* __restrict__ w2,
                             uint4* __restrict__ d1,
                             uint4* __restrict__ d3,
                             uint4* __restrict__ d2, int n8) {
    int i = blockIdx.x * blockDim.x + threadIdx.x;
    if (i >= n8) return;
    const float4* src = (blockIdx.y == 0) ? w1 : (blockIdx.y == 1) ? w3 : w2;
    uint4* dst = (blockIdx.y == 0) ? d1 : (blockIdx.y == 1) ? d3 : d2;
    float4 v0 = src[2 * i];
    float4 v1 = src[2 * i + 1];
    __half2 h0 = __floats2half2_rn(v0.x, v0.y);
    __half2 h1 = __floats2half2_rn(v0.z, v0.w);
    __half2 h2 = __floats2half2_rn(v1.x, v1.y);
    __half2 h3 = __floats2half2_rn(v1.z, v1.w);
    uint4 o;
    o.x = *(uint32_t*)&h0; o.y = *(uint32_t*)&h1;
    o.z = *(uint32_t*)&h2; o.w = *(uint32_t*)&h3;
    dst[i] = o;
}

// ---------------- zero helpers ----------------
__global__ void zero_kernel() {
    if (threadIdx.x < EE) g_importance[threadIdx.x] = 0.0f;
}
__global__ void zero_out_kernel(float* __restrict__ out, int n) {
    int i = blockIdx.x * blockDim.x + threadIdx.x;
    if (i < n) out[i] = 0.0f;
}

// ---------------- routing: warp-per-token, float4 x loads ------------------
__global__ void routing_kernel(const float* __restrict__ x,
                               const float* __restrict__ wg) {
    __shared__ float simp[EE];
    int tid = threadIdx.x, lane = tid & 31, w = tid >> 5;
    if (tid < EE) simp[tid] = 0.0f;
    __syncthreads();

    int t = blockIdx.x * 8 + w;
    const float* xr = x + (size_t)t * HH;
    float acc[EE] = {};
#pragma unroll
    for (int i = 0; i < HH / 128; i++) {            // 6 iterations
        int j = i * 128 + lane * 4;
        float4 xv = *(const float4*)(xr + j);
        __half2 hx0 = __floats2half2_rn(xv.x, xv.y);
        __half2 hx1 = __floats2half2_rn(xv.z, xv.w);
        *(__half2*)&g_xh[(size_t)t * HH + j]     = hx0;
        *(__half2*)&g_xh[(size_t)t * HH + j + 2] = hx1;
        const float* wr = wg + j * EE;
#pragma unroll
        for (int q = 0; q < 4; q++) {
            float xs = (q == 0) ? xv.x : (q == 1) ? xv.y : (q == 2) ? xv.z : xv.w;
            float4 wa = *(const float4*)(wr + q * EE);
            float4 wb = *(const float4*)(wr + q * EE + 4);
            acc[0] += xs * wa.x; acc[1] += xs * wa.y;
            acc[2] += xs * wa.z; acc[3] += xs * wa.w;
            acc[4] += xs * wb.x; acc[5] += xs * wb.y;
            acc[6] += xs * wb.z; acc[7] += xs * wb.w;
        }
    }
#pragma unroll
    for (int o = 16; o; o >>= 1)
#pragma unroll
        for (int e = 0; e < EE; e++) acc[e] += __shfl_xor_sync(0xffffffffu, acc[e], o);

    if (lane == 0) {
        float mx = acc[0];
        for (int e = 1; e < EE; e++) mx = fmaxf(mx, acc[e]);
        float p[EE], s = 0.0f;
        for (int e = 0; e < EE; e++) { p[e] = expf(acc[e] - mx); s += p[e]; }
        for (int e = 0; e < EE; e++) p[e] /= s;
        int e0 = 0;
        for (int e = 1; e < EE; e++) if (p[e] > p[e0]) e0 = e;
        int e1 = -1;
        for (int e = 0; e < EE; e++) {
            if (e == e0) continue;
            if (e1 < 0 || p[e] > p[e1]) e1 = e;
        }
        float ps = p[e0] + p[e1] + 1e-8f;
        float w0 = fminf(fmaxf(p[e0] / ps, 1e-8f), 10.0f);
        float w1 = fminf(fmaxf(p[e1] / ps, 1e-8f), 10.0f);
        g_topk_idx[t * 2 + 0] = e0;
        g_topk_idx[t * 2 + 1] = e1;
        g_topk_w[t * 2 + 0] = w0;
        g_topk_w[t * 2 + 1] = w1;
        for (int e = 0; e < EE; e++) atomicAdd(&simp[e], p[e]);
    }
    __syncthreads();
    if (tid < EE) atomicAdd(&g_importance[tid], simp[tid]);
}

// ---------------- scan ----------------
__global__ void scan_kernel() {
    __shared__ int warp_cnt[32][EE];
    __shared__ int warp_pref[32][EE];
    __shared__ int running[EE];
    __shared__ int chunk_tot[EE];
    __shared__ int tot[KK][EE];
    int tid = threadIdx.x, lane = tid & 31, warp = tid >> 5;

    for (int k = 0; k < KK; k++) {
        if (tid < EE) running[tid] = 0;
        __syncthreads();
        for (int chunk = 0; chunk < TT / 1024; chunk++) {
            int t = chunk * 1024 + tid;
            int e = g_topk_idx[t * 2 + k];
            unsigned mask = __match_any_sync(0xffffffffu, e);
            int lane_pref = __popc(mask & ((1u << lane) - 1));
            int warp_total = __popc(mask);
            if (tid < 32 * EE) warp_cnt[tid / EE][tid % EE] = 0;
            __syncthreads();
            if (lane_pref == 0) warp_cnt[warp][e] = warp_total;
            __syncthreads();
            if (tid < 32 * EE) {
                int w = tid / EE, ee = tid % EE;
                int p = 0;
                for (int ww = 0; ww < w; ww++) p += warp_cnt[ww][ee];
                warp_pref[w][ee] = p;
                if (w == 31) chunk_tot[ee] = p + warp_cnt[31][ee];
            }
            __syncthreads();
            int rank = running[e] + warp_pref[warp][e] + lane_pref + 1;
            bool kept = (rank <= CAP);
            int slot = kept ? (k * CAP + rank - 1) : -1;
            g_slot[t * 2 + k] = slot;
            if (kept) {
                g_list[e * SLOTS + slot] = t;
                g_wslot[e * SLOTS + slot] = g_topk_w[t * 2 + k];
            }
            __syncthreads();
            if (tid < EE) running[tid] += chunk_tot[tid];
            __syncthreads();
        }
        if (tid < EE) tot[k][tid] = running[tid];
        __syncthreads();
    }
    if (tid == 0) {
        int drop = 0;
        for (int e = 0; e < EE; e++) {
            int c0 = min(tot[0][e], CAP), c1 = min(tot[1][e], CAP);
            g_cnt[0 * EE + e] = c0;
            g_cnt[1 * EE + e] = c1;
            g_keptcnt[e] = c0 + c1;
            drop += (tot[0][e] - c0) + (tot[1][e] - c1);
        }
        g_dropped = (float)drop;
    }
}

// ================ GEMM1: fp16 mma + ldmatrix, KC=64, 3-stage, 2 CTAs/SM ====
// CTA: M=128 slots x N=128 (64 w1-cols + 64 w3-cols). 256 threads, 8 warps.
#define KC 64                   // K elements per chunk
#define APITCH 72               // halves per A row (64 data + 8 pad) = 144B
#define BPITCH 136              // halves per B k-row (128 data + 8 pad) = 272B
#define ABUF (128*APITCH)       // halves
#define BBUF (KC*BPITCH)        // halves
#define G1_SMEM ((3*ABUF + 3*BBUF) * 2 + 512)
__global__ void __launch_bounds__(256, 2) gemm1_mma() {
    extern __shared__ __half sh[];
    __half* Ash = sh;                 // 3 x ABUF
    __half* Bsh = sh + 3 * ABUF;      // 3 x BBUF
    int* stok = (int*)(Bsh + 3 * BBUF);

    int e = blockIdx.z, by = blockIdx.y, bx = blockIdx.x; // bx 0..23
    int kslot = (by >= 6) ? 1 : 0;
    int cnt = g_cnt[kslot * EE + e];
    int tile0 = (by - kslot * 6) * 128;
    if (tile0 >= cnt) return;
    int valid = min(128, cnt - tile0);
    int slot0 = by * 128;
    int tid = threadIdx.x;
    int lane = tid & 31, w = tid >> 5;
    int warpM = w >> 2, warpN = w & 3;

    if (tid < 128)
        stok[tid] = (tid < valid) ? g_list[e * SLOTS + slot0 + tid]
                                  : g_list[e * SLOTS + slot0];
    __syncthreads();

    const __half* w1b = g_w1h + (size_t)e * HH * II + bx * 64;
    const __half* w3b = g_w3h + (size_t)e * HH * II + bx * 64;

    auto fill = [&](int buf, int c) {
        uint32_t au = s2u(Ash + buf * ABUF);
        uint32_t bu_ = s2u(Bsh + buf * BBUF);
        int k0 = c * KC;
#pragma unroll
        for (int i = tid; i < 1024; i += 256) {   // A: 128 rows x 64 halves
            int row = i >> 3, seg = i & 7;
            cpa16(au + (uint32_t)(row * APITCH + seg * 8) * 2,
                  g_xh + (size_t)stok[row] * HH + k0 + seg * 8);
        }
#pragma unroll
        for (int i = tid; i < 1024; i += 256) {   // B: 64 k-rows x (64 G + 64 U)
            int k = i >> 4, seg = i & 15;
            const __half* src = (seg < 8) ? (w1b + (size_t)(k0 + k) * II + seg * 8)
                                          : (w3b + (size_t)(k0 + k) * II + (seg - 8) * 8);
            int dc = (seg < 8) ? seg * 8 : 64 + (seg - 8) * 8;
            cpa16(bu_ + (uint32_t)(k * BPITCH + dc) * 2, src);
        }
        cpa_commit();
    };

    const int NC = HH / KC; // 12
    fill(0, 0);
    fill(1, 1);

    float accG[4][2][4] = {}, accU[4][2][4] = {};
    int l15 = lane & 15;
    int lhi = (lane & 16) ? 8 : 0;

    for (int c = 0; c < NC; c++) {
        if (c + 1 < NC) cpa_wait<1>(); else cpa_wait<0>();
        __syncthreads();                // fill(c) visible; compute(c-1) done
        if (c + 2 < NC) fill((c + 2) % 3, c + 2);

        uint32_t au = s2u(Ash + (c % 3) * ABUF);
        uint32_t bu_ = s2u(Bsh + (c % 3) * BBUF);
#pragma unroll
        for (int ks = 0; ks < KC / 16; ks++) {
            uint32_t af[4][4];
#pragma unroll
            for (int mf = 0; mf < 4; mf++) {
                int row = warpM * 64 + mf * 16 + l15;
                int col = ks * 16 + lhi;
                ldsm4(af[mf], au + (uint32_t)(row * APITCH + col) * 2);
            }
            int k = ks * 16 + l15;
            int nG = warpN * 16 + lhi;
            uint32_t bg[4], bu2[4];
            ldsm4t(bg,  bu_ + (uint32_t)(k * BPITCH + nG) * 2);
            ldsm4t(bu2, bu_ + (uint32_t)(k * BPITCH + 64 + nG) * 2);
#pragma unroll
            for (int mf = 0; mf < 4; mf++) {
                mma16(accG[mf][0], af[mf], bg);
                mma16(accG[mf][1], af[mf], bg + 2);
                mma16(accU[mf][0], af[mf], bu2);
                mma16(accU[mf][1], af[mf], bu2 + 2);
            }
        }
    }

    // epilogue: SwiGLU, write hbuf as fp16
#pragma unroll
    for (int mf = 0; mf < 4; mf++) {
        int rbase = warpM * 64 + mf * 16 + (lane >> 2);
#pragma unroll
        for (int nf = 0; nf < 2; nf++) {
            int col = bx * 64 + warpN * 16 + nf * 8 + 2 * (lane & 3);
#pragma unroll
            for (int h = 0; h < 2; h++) {
                int r = rbase + h * 8;
                if (r < valid) {
                    float g0 = accG[mf][nf][h * 2 + 0], g1 = accG[mf][nf][h * 2 + 1];
                    float u0 = accU[mf][nf][h * 2 + 0], u1 = accU[mf][nf][h * 2 + 1];
                    __half2 hv = __floats2half2_rn(g0 / (1.0f + expf(-g0)) * u0,
                                                   g1 / (1.0f + expf(-g1)) * u1);
                    *(__half2*)&g_hbufh[((size_t)e * SLOTS + slot0 + r) * II + col] = hv;
                }
            }
        }
    }
}

// ================ GEMM2: fp16 mma + ldmatrix, KC=64, 3-stage, fused combine
// CTA: M=128 slots x N=128 H-cols. 256 threads. warp: 64 x 32.
#define G2_SMEM ((3*ABUF + 3*BBUF) * 2 + 128*4 + 128*4)
__global__ void __launch_bounds__(256, 2) gemm2_mma(float* __restrict__ out) {
    extern __shared__ __half sh[];
    __half* Ash = sh;
    __half* Bsh = sh + 3 * ABUF;
    int* tok2 = (int*)(Bsh + 3 * BBUF);
    float* wt2 = (float*)(tok2 + 128);

    int e = blockIdx.z, by = blockIdx.y, bx = blockIdx.x; // bx 0..5
    int kslot = (by >= 6) ? 1 : 0;
    int cnt = g_cnt[kslot * EE + e];
    int tile0 = (by - kslot * 6) * 128;
    if (tile0 >= cnt) return;
    int valid = min(128, cnt - tile0);
    int slot0 = by * 128;
    int tid = threadIdx.x;
    int lane = tid & 31, w = tid >> 5;
    int warpM = w >> 2, warpN = w & 3;

    if (tid < 128) {
        bool v = tid < valid;
        tok2[tid] = v ? g_list[e * SLOTS + slot0 + tid] : 0;
        wt2[tid]  = v ? g_wslot[e * SLOTS + slot0 + tid] : 0.0f;
    }
    __syncthreads();

    const __half* Ab = g_hbufh + ((size_t)e * SLOTS + slot0) * II;
    const __half* Bb = g_w2h + (size_t)e * II * HH + bx * 128;

    auto fill = [&](int buf, int c) {
        uint32_t au = s2u(Ash + buf * ABUF);
        uint32_t bu_ = s2u(Bsh + buf * BBUF);
        int k0 = c * KC;
#pragma unroll
        for (int i = tid; i < 1024; i += 256) {
            int row = i >> 3, seg = i & 7;
            cpa16(au + (uint32_t)(row * APITCH + seg * 8) * 2,
                  Ab + (size_t)row * II + k0 + seg * 8);
        }
#pragma unroll
        for (int i = tid; i < 1024; i += 256) {
            int k = i >> 4, seg = i & 15;
            cpa16(bu_ + (uint32_t)(k * BPITCH + seg * 8) * 2,
                  Bb + (size_t)(k0 + k) * HH + seg * 8);
        }
        cpa_commit();
    };

    const int NC = II / KC; // 24
    fill(0, 0);
    fill(1, 1);

    float acc[4][4][4] = {};
    int l15 = lane & 15;
    int lhi = (lane & 16) ? 8 : 0;

    for (int c = 0; c < NC; c++) {
        if (c + 1 < NC) cpa_wait<1>(); else cpa_wait<0>();
        __syncthreads();
        if (c + 2 < NC) fill((c + 2) % 3, c + 2);

        uint32_t au = s2u(Ash + (c % 3) * ABUF);
        uint32_t bu_ = s2u(Bsh + (c % 3) * BBUF);
#pragma unroll
        for (int ks = 0; ks < KC / 16; ks++) {
            uint32_t af[4][4];
#pragma unroll
            for (int mf = 0; mf < 4; mf++) {
                int row = warpM * 64 + mf * 16 + l15;
                int col = ks * 16 + lhi;
                ldsm4(af[mf], au + (uint32_t)(row * APITCH + col) * 2);
            }
            int k = ks * 16 + l15;
            int nB = warpN * 32 + lhi;
            uint32_t bf[8];
            ldsm4t(bf,     bu_ + (uint32_t)(k * BPITCH + nB) * 2);
            ldsm4t(bf + 4, bu_ + (uint32_t)(k * BPITCH + nB + 16) * 2);
#pragma unroll
            for (int mf = 0; mf < 4; mf++) {
                mma16(acc[mf][0], af[mf], bf);
                mma16(acc[mf][1], af[mf], bf + 2);
                mma16(acc[mf][2], af[mf], bf + 4);
                mma16(acc[mf][3], af[mf], bf + 6);
            }
        }
    }

    // fused combine: out[token] += w * acc
#pragma unroll
    for (int mf = 0; mf < 4; mf++) {
        int rbase = warpM * 64 + mf * 16 + (lane >> 2);
#pragma unroll
        for (int nf = 0; nf < 4; nf++) {
            int col = bx * 128 + warpN * 32 + nf * 8 + 2 * (lane & 3);
#pragma unroll
            for (int h = 0; h < 2; h++) {
                int r = rbase + h * 8;
                if (r < valid) {
                    float wv = wt2[r];
                    float* op = out + (size_t)tok2[r] * HH + col;
                    atomicAdd(op,     wv * acc[mf][nf][h * 2 + 0]);
                    atomicAdd(op + 1, wv * acc[mf][nf][h * 2 + 1]);
                }
            }
        }
    }
}

// ---------------- aux ----------------
__global__ void aux_kernel(float* __restrict__ out, int out_size) {
    if (out_size < TT * HH + 1) return;
    float a = 0.0f;
    for (int e = 0; e < EE; e++) {
        float usage = (float)g_keptcnt[e] / (float)(TT * KK);
        float imp = g_importance[e] / (float)TT;
        a += usage * imp;
    }
    a *= (float)EE;
    if (g_dropped > 0.0f) a += g_dropped / (float)TT * 0.1f;
    a = fminf(a, 1.0f) * 0.001f;
    out[TT * HH] = a;
}

// ---------------- launch ----------------
extern "C" void kernel_launch(void* const* d_in, const int* in_sizes, int n_in,
                              void* d_out, int out_size) {
    const float* x      = (const float*)d_in[0];
    const float* w_gate = (const float*)d_in[1];
    const float* w1     = (const float*)d_in[2];
    const float* w3     = (const float*)d_in[3];
    const float* w2     = (const float*)d_in[4];
    float* out = (float*)d_out;

    cudaFuncSetAttribute(gemm1_mma, cudaFuncAttributeMaxDynamicSharedMemorySize, G1_SMEM);
    cudaFuncSetAttribute(gemm2_mma, cudaFuncAttributeMaxDynamicSharedMemorySize, G2_SMEM);

    __half* w1h_p; cudaGetSymbolAddress((void**)&w1h_p, g_w1h);
    __half* w3h_p; cudaGetSymbolAddress((void**)&w3h_p, g_w3h);
    __half* w2h_p; cudaGetSymbolAddress((void**)&w2h_p, g_w2h);

    const int NW8 = (EE * HH * II) / 8;   // 1179648

    zero_kernel<<<1, 32>>>();
    zero_out_kernel<<<(out_size + 255) / 256, 256>>>(out, out_size);
    cvth3_kernel<<<dim3((NW8 + 255) / 256, 3), 256>>>(
        (const float4*)w1, (const float4*)w3, (const float4*)w2,
        (uint4*)w1h_p, (uint4*)w3h_p, (uint4*)w2h_p, NW8);
    routing_kernel<<<TT / 8, 256>>>(x, w_gate);
    scan_kernel<<<1, 1024>>>();
    gemm1_mma<<<dim3(II / 64, SLOTS / 128, EE), 256, G1_SMEM>>>();
    gemm2_mma<<<dim3(HH / 128, SLOTS / 128, EE), 256, G2_SMEM>>>(out);
    aux_kernel<<<1, 1>>>(out, out_size);
}

// round 15
// speedup vs baseline: 2.0810x; 1.0215x over previous
#include <cuda_runtime.h>
#include <cuda_bf16.h>
#include <cuda_fp16.h>
#include <stdint.h>
#include <math.h>

// Problem constants
#define TT 2048      // tokens (B*S)
#define HH 768       // hidden
#define II 1536      // intermediate
#define EE 8         // experts
#define KK 2         // top-k
#define CAP 768      // capacity
#define SLOTS (KK*CAP)   // 1536 slot rows per expert

// ---------------- scratch (device globals; allocation-free) ----------------
__device__ float g_probs[TT * EE];                // full softmax probs (64KB)
__device__ int   g_topk_idx[TT * KK];
__device__ float g_topk_w[TT * KK];
__device__ int   g_slot[TT * KK];
__device__ int   g_list[EE * SLOTS];
__device__ float g_wslot[EE * SLOTS];             // combine weight per (e,slot)
__device__ int   g_cnt[KK * EE];
__device__ int   g_keptcnt[EE];
__device__ float g_dropped;
__device__ __half g_xh[TT * HH];                  // x as fp16 (3MB)
__device__ __half g_w1h[EE * HH * II];            // w1 fp16 (~19MB)
__device__ __half g_w3h[EE * HH * II];            // w3 fp16 (~19MB)
__device__ __half g_w2h[EE * II * HH];            // w2 fp16 (~19MB)
__device__ __half g_hbufh[EE * SLOTS * II];       // SwiGLU intermediate fp16 (~38MB)

// ---------------- PTX helpers ----------------
__device__ __forceinline__ uint32_t s2u(const void* p) {
    uint32_t a;
    asm("{ .reg .u64 t; cvta.to.shared.u64 t, %1; cvt.u32.u64 %0, t; }" : "=r"(a) : "l"(p));
    return a;
}
__device__ __forceinline__ void cpa16(uint32_t dst, const void* src) {
    asm volatile("cp.async.cg.shared.global [%0], [%1], 16;" :: "r"(dst), "l"(src));
}
__device__ __forceinline__ void cpa_commit() { asm volatile("cp.async.commit_group;" ::: "memory"); }
template<int N> __device__ __forceinline__ void cpa_wait() {
    asm volatile("cp.async.wait_group %0;" :: "n"(N) : "memory");
}
__device__ __forceinline__ void ldsm4(uint32_t* r, uint32_t addr) {
    asm volatile("ldmatrix.sync.aligned.m8n8.x4.shared.b16 {%0,%1,%2,%3}, [%4];"
        : "=r"(r[0]), "=r"(r[1]), "=r"(r[2]), "=r"(r[3]) : "r"(addr));
}
__device__ __forceinline__ void ldsm4t(uint32_t* r, uint32_t addr) {
    asm volatile("ldmatrix.sync.aligned.m8n8.x4.trans.shared.b16 {%0,%1,%2,%3}, [%4];"
        : "=r"(r[0]), "=r"(r[1]), "=r"(r[2]), "=r"(r[3]) : "r"(addr));
}
__device__ __forceinline__ void mma16(float* d, const uint32_t* a, const uint32_t* b) {
    asm volatile(
        "mma.sync.aligned.m16n8k16.row.col.f32.f16.f16.f32 "
        "{%0,%1,%2,%3}, {%4,%5,%6,%7}, {%8,%9}, {%0,%1,%2,%3};"
        : "+f"(d[0]), "+f"(d[1]), "+f"(d[2]), "+f"(d[3])
        : "r"(a[0]), "r"(a[1]), "r"(a[2]), "r"(a[3]), "r"(b[0]), "r"(b[1]));
}

// ---------------- fp16 pre-convert: 8 floats/thread, uint4 store ----------
__global__ void cvth3_kernel(const float4* __restrict__ w1,
                             const float4* __restrict__ w3,
                             const float4* __restrict__ w2,
                             uint4* __restrict__ d1,
                             uint4* __restrict__ d3,
                             uint4* __restrict__ d2, int n8) {
    int i = blockIdx.x * blockDim.x + threadIdx.x;
    if (i >= n8) return;
    const float4* src = (blockIdx.y == 0) ? w1 : (blockIdx.y == 1) ? w3 : w2;
    uint4* dst = (blockIdx.y == 0) ? d1 : (blockIdx.y == 1) ? d3 : d2;
    float4 v0 = src[2 * i];
    float4 v1 = src[2 * i + 1];
    __half2 h0 = __floats2half2_rn(v0.x, v0.y);
    __half2 h1 = __floats2half2_rn(v0.z, v0.w);
    __half2 h2 = __floats2half2_rn(v1.x, v1.y);
    __half2 h3 = __floats2half2_rn(v1.z, v1.w);
    uint4 o;
    o.x = *(uint32_t*)&h0; o.y = *(uint32_t*)&h1;
    o.z = *(uint32_t*)&h2; o.w = *(uint32_t*)&h3;
    dst[i] = o;
}

// ---------------- zero out ----------------
__global__ void zero_out_kernel(float* __restrict__ out, int n) {
    int i = blockIdx.x * blockDim.x + threadIdx.x;
    if (i < n) out[i] = 0.0f;
}

// ---------------- routing: warp-per-token, wg staged in SMEM ---------------
// 512 threads = 16 tokens/block, 128 blocks. wg transposed to swgT[8][776]
// so each lane does conflict-free LDS.128 per expert.
__global__ void __launch_bounds__(512) routing_kernel(const float* __restrict__ x,
                                                      const float* __restrict__ wg) {
    __shared__ float swgT[EE][HH + 8];
    int tid = threadIdx.x;
    for (int i = tid; i < HH * EE; i += 512) {
        int j = i >> 3, e = i & 7;
        swgT[e][j] = wg[i];
    }
    __syncthreads();

    int lane = tid & 31, w = tid >> 5;
    int t = blockIdx.x * 16 + w;
    const float* xr = x + (size_t)t * HH;
    float acc[EE] = {};
#pragma unroll
    for (int i = 0; i < HH / 128; i++) {            // 6 iterations
        int j = i * 128 + lane * 4;
        float4 xv = *(const float4*)(xr + j);
        __half2 hx0 = __floats2half2_rn(xv.x, xv.y);
        __half2 hx1 = __floats2half2_rn(xv.z, xv.w);
        *(__half2*)&g_xh[(size_t)t * HH + j]     = hx0;
        *(__half2*)&g_xh[(size_t)t * HH + j + 2] = hx1;
#pragma unroll
        for (int e = 0; e < EE; e++) {
            float4 wv = *(const float4*)&swgT[e][j];
            acc[e] += xv.x * wv.x + xv.y * wv.y + xv.z * wv.z + xv.w * wv.w;
        }
    }
#pragma unroll
    for (int o = 16; o; o >>= 1)
#pragma unroll
        for (int e = 0; e < EE; e++) acc[e] += __shfl_xor_sync(0xffffffffu, acc[e], o);

    if (lane == 0) {
        float mx = acc[0];
        for (int e = 1; e < EE; e++) mx = fmaxf(mx, acc[e]);
        float p[EE], s = 0.0f;
        for (int e = 0; e < EE; e++) { p[e] = expf(acc[e] - mx); s += p[e]; }
        for (int e = 0; e < EE; e++) p[e] /= s;
        for (int e = 0; e < EE; e++) g_probs[t * EE + e] = p[e];
        int e0 = 0;
        for (int e = 1; e < EE; e++) if (p[e] > p[e0]) e0 = e;
        int e1 = -1;
        for (int e = 0; e < EE; e++) {
            if (e == e0) continue;
            if (e1 < 0 || p[e] > p[e1]) e1 = e;
        }
        float ps = p[e0] + p[e1] + 1e-8f;
        float w0 = fminf(fmaxf(p[e0] / ps, 1e-8f), 10.0f);
        float w1 = fminf(fmaxf(p[e1] / ps, 1e-8f), 10.0f);
        g_topk_idx[t * 2 + 0] = e0;
        g_topk_idx[t * 2 + 1] = e1;
        g_topk_w[t * 2 + 0] = w0;
        g_topk_w[t * 2 + 1] = w1;
    }
}

// ---------------- scan ----------------
__global__ void scan_kernel() {
    __shared__ int warp_cnt[32][EE];
    __shared__ int warp_pref[32][EE];
    __shared__ int running[EE];
    __shared__ int chunk_tot[EE];
    __shared__ int tot[KK][EE];
    int tid = threadIdx.x, lane = tid & 31, warp = tid >> 5;

    for (int k = 0; k < KK; k++) {
        if (tid < EE) running[tid] = 0;
        __syncthreads();
        for (int chunk = 0; chunk < TT / 1024; chunk++) {
            int t = chunk * 1024 + tid;
            int e = g_topk_idx[t * 2 + k];
            unsigned mask = __match_any_sync(0xffffffffu, e);
            int lane_pref = __popc(mask & ((1u << lane) - 1));
            int warp_total = __popc(mask);
            if (tid < 32 * EE) warp_cnt[tid / EE][tid % EE] = 0;
            __syncthreads();
            if (lane_pref == 0) warp_cnt[warp][e] = warp_total;
            __syncthreads();
            if (tid < 32 * EE) {
                int w = tid / EE, ee = tid % EE;
                int p = 0;
                for (int ww = 0; ww < w; ww++) p += warp_cnt[ww][ee];
                warp_pref[w][ee] = p;
                if (w == 31) chunk_tot[ee] = p + warp_cnt[31][ee];
            }
            __syncthreads();
            int rank = running[e] + warp_pref[warp][e] + lane_pref + 1;
            bool kept = (rank <= CAP);
            int slot = kept ? (k * CAP + rank - 1) : -1;
            g_slot[t * 2 + k] = slot;
            if (kept) {
                g_list[e * SLOTS + slot] = t;
                g_wslot[e * SLOTS + slot] = g_topk_w[t * 2 + k];
            }
            __syncthreads();
            if (tid < EE) running[tid] += chunk_tot[tid];
            __syncthreads();
        }
        if (tid < EE) tot[k][tid] = running[tid];
        __syncthreads();
    }
    if (tid == 0) {
        int drop = 0;
        for (int e = 0; e < EE; e++) {
            int c0 = min(tot[0][e], CAP), c1 = min(tot[1][e], CAP);
            g_cnt[0 * EE + e] = c0;
            g_cnt[1 * EE + e] = c1;
            g_keptcnt[e] = c0 + c1;
            drop += (tot[0][e] - c0) + (tot[1][e] - c1);
        }
        g_dropped = (float)drop;
    }
}

// ================ GEMM1: fp16 mma + ldmatrix, KC=64, 3-stage, 2 CTAs/SM ====
// CTA: M=128 slots x N=128 (64 w1-cols + 64 w3-cols). 256 threads, 8 warps.
#define KC 64                   // K elements per chunk
#define APITCH 72               // halves per A row (64 data + 8 pad) = 144B
#define BPITCH 136              // halves per B k-row (128 data + 8 pad) = 272B
#define ABUF (128*APITCH)       // halves
#define BBUF (KC*BPITCH)        // halves
#define G1_SMEM ((3*ABUF + 3*BBUF) * 2 + 512)
__global__ void __launch_bounds__(256, 2) gemm1_mma() {
    extern __shared__ __half sh[];
    __half* Ash = sh;                 // 3 x ABUF
    __half* Bsh = sh + 3 * ABUF;      // 3 x BBUF
    int* stok = (int*)(Bsh + 3 * BBUF);

    int e = blockIdx.z, by = blockIdx.y, bx = blockIdx.x; // bx 0..23
    int kslot = (by >= 6) ? 1 : 0;
    int cnt = g_cnt[kslot * EE + e];
    int tile0 = (by - kslot * 6) * 128;
    if (tile0 >= cnt) return;
    int valid = min(128, cnt - tile0);
    int slot0 = by * 128;
    int tid = threadIdx.x;
    int lane = tid & 31, w = tid >> 5;
    int warpM = w >> 2, warpN = w & 3;

    if (tid < 128)
        stok[tid] = (tid < valid) ? g_list[e * SLOTS + slot0 + tid]
                                  : g_list[e * SLOTS + slot0];
    __syncthreads();

    const __half* w1b = g_w1h + (size_t)e * HH * II + bx * 64;
    const __half* w3b = g_w3h + (size_t)e * HH * II + bx * 64;

    auto fill = [&](int buf, int c) {
        uint32_t au = s2u(Ash + buf * ABUF);
        uint32_t bu_ = s2u(Bsh + buf * BBUF);
        int k0 = c * KC;
#pragma unroll
        for (int i = tid; i < 1024; i += 256) {   // A: 128 rows x 64 halves
            int row = i >> 3, seg = i & 7;
            cpa16(au + (uint32_t)(row * APITCH + seg * 8) * 2,
                  g_xh + (size_t)stok[row] * HH + k0 + seg * 8);
        }
#pragma unroll
        for (int i = tid; i < 1024; i += 256) {   // B: 64 k-rows x (64 G + 64 U)
            int k = i >> 4, seg = i & 15;
            const __half* src = (seg < 8) ? (w1b + (size_t)(k0 + k) * II + seg * 8)
                                          : (w3b + (size_t)(k0 + k) * II + (seg - 8) * 8);
            int dc = (seg < 8) ? seg * 8 : 64 + (seg - 8) * 8;
            cpa16(bu_ + (uint32_t)(k * BPITCH + dc) * 2, src);
        }
        cpa_commit();
    };

    const int NC = HH / KC; // 12
    fill(0, 0);
    fill(1, 1);

    float accG[4][2][4] = {}, accU[4][2][4] = {};
    int l15 = lane & 15;
    int lhi = (lane & 16) ? 8 : 0;

    for (int c = 0; c < NC; c++) {
        if (c + 1 < NC) cpa_wait<1>(); else cpa_wait<0>();
        __syncthreads();                // fill(c) visible; compute(c-1) done
        if (c + 2 < NC) fill((c + 2) % 3, c + 2);

        uint32_t au = s2u(Ash + (c % 3) * ABUF);
        uint32_t bu_ = s2u(Bsh + (c % 3) * BBUF);
#pragma unroll
        for (int ks = 0; ks < KC / 16; ks++) {
            uint32_t af[4][4];
#pragma unroll
            for (int mf = 0; mf < 4; mf++) {
                int row = warpM * 64 + mf * 16 + l15;
                int col = ks * 16 + lhi;
                ldsm4(af[mf], au + (uint32_t)(row * APITCH + col) * 2);
            }
            int k = ks * 16 + l15;
            int nG = warpN * 16 + lhi;
            uint32_t bg[4], bu2[4];
            ldsm4t(bg,  bu_ + (uint32_t)(k * BPITCH + nG) * 2);
            ldsm4t(bu2, bu_ + (uint32_t)(k * BPITCH + 64 + nG) * 2);
#pragma unroll
            for (int mf = 0; mf < 4; mf++) {
                mma16(accG[mf][0], af[mf], bg);
                mma16(accG[mf][1], af[mf], bg + 2);
                mma16(accU[mf][0], af[mf], bu2);
                mma16(accU[mf][1], af[mf], bu2 + 2);
            }
        }
    }

    // epilogue: SwiGLU, write hbuf as fp16
#pragma unroll
    for (int mf = 0; mf < 4; mf++) {
        int rbase = warpM * 64 + mf * 16 + (lane >> 2);
#pragma unroll
        for (int nf = 0; nf < 2; nf++) {
            int col = bx * 64 + warpN * 16 + nf * 8 + 2 * (lane & 3);
#pragma unroll
            for (int h = 0; h < 2; h++) {
                int r = rbase + h * 8;
                if (r < valid) {
                    float g0 = accG[mf][nf][h * 2 + 0], g1 = accG[mf][nf][h * 2 + 1];
                    float u0 = accU[mf][nf][h * 2 + 0], u1 = accU[mf][nf][h * 2 + 1];
                    __half2 hv = __floats2half2_rn(g0 / (1.0f + expf(-g0)) * u0,
                                                   g1 / (1.0f + expf(-g1)) * u1);
                    *(__half2*)&g_hbufh[((size_t)e * SLOTS + slot0 + r) * II + col] = hv;
                }
            }
        }
    }
}

// ================ GEMM2: fp16 mma + ldmatrix, KC=64, 3-stage, fused combine
// CTA: M=128 slots x N=128 H-cols. 256 threads. warp: 64 x 32.
#define G2_SMEM ((3*ABUF + 3*BBUF) * 2 + 128*4 + 128*4)
__global__ void __launch_bounds__(256, 2) gemm2_mma(float* __restrict__ out) {
    extern __shared__ __half sh[];
    __half* Ash = sh;
    __half* Bsh = sh + 3 * ABUF;
    int* tok2 = (int*)(Bsh + 3 * BBUF);
    float* wt2 = (float*)(tok2 + 128);

    int e = blockIdx.z, by = blockIdx.y, bx = blockIdx.x; // bx 0..5
    int kslot = (by >= 6) ? 1 : 0;
    int cnt = g_cnt[kslot * EE + e];
    int tile0 = (by - kslot * 6) * 128;
    if (tile0 >= cnt) return;
    int valid = min(128, cnt - tile0);
    int slot0 = by * 128;
    int tid = threadIdx.x;
    int lane = tid & 31, w = tid >> 5;
    int warpM = w >> 2, warpN = w & 3;

    if (tid < 128) {
        bool v = tid < valid;
        tok2[tid] = v ? g_list[e * SLOTS + slot0 + tid] : 0;
        wt2[tid]  = v ? g_wslot[e * SLOTS + slot0 + tid] : 0.0f;
    }
    __syncthreads();

    const __half* Ab = g_hbufh + ((size_t)e * SLOTS + slot0) * II;
    const __half* Bb = g_w2h + (size_t)e * II * HH + bx * 128;

    auto fill = [&](int buf, int c) {
        uint32_t au = s2u(Ash + buf * ABUF);
        uint32_t bu_ = s2u(Bsh + buf * BBUF);
        int k0 = c * KC;
#pragma unroll
        for (int i = tid; i < 1024; i += 256) {
            int row = i >> 3, seg = i & 7;
            cpa16(au + (uint32_t)(row * APITCH + seg * 8) * 2,
                  Ab + (size_t)row * II + k0 + seg * 8);
        }
#pragma unroll
        for (int i = tid; i < 1024; i += 256) {
            int k = i >> 4, seg = i & 15;
            cpa16(bu_ + (uint32_t)(k * BPITCH + seg * 8) * 2,
                  Bb + (size_t)(k0 + k) * HH + seg * 8);
        }
        cpa_commit();
    };

    const int NC = II / KC; // 24
    fill(0, 0);
    fill(1, 1);

    float acc[4][4][4] = {};
    int l15 = lane & 15;
    int lhi = (lane & 16) ? 8 : 0;

    for (int c = 0; c < NC; c++) {
        if (c + 1 < NC) cpa_wait<1>(); else cpa_wait<0>();
        __syncthreads();
        if (c + 2 < NC) fill((c + 2) % 3, c + 2);

        uint32_t au = s2u(Ash + (c % 3) * ABUF);
        uint32_t bu_ = s2u(Bsh + (c % 3) * BBUF);
#pragma unroll
        for (int ks = 0; ks < KC / 16; ks++) {
            uint32_t af[4][4];
#pragma unroll
            for (int mf = 0; mf < 4; mf++) {
                int row = warpM * 64 + mf * 16 + l15;
                int col = ks * 16 + lhi;
                ldsm4(af[mf], au + (uint32_t)(row * APITCH + col) * 2);
            }
            int k = ks * 16 + l15;
            int nB = warpN * 32 + lhi;
            uint32_t bf[8];
            ldsm4t(bf,     bu_ + (uint32_t)(k * BPITCH + nB) * 2);
            ldsm4t(bf + 4, bu_ + (uint32_t)(k * BPITCH + nB + 16) * 2);
#pragma unroll
            for (int mf = 0; mf < 4; mf++) {
                mma16(acc[mf][0], af[mf], bf);
                mma16(acc[mf][1], af[mf], bf + 2);
                mma16(acc[mf][2], af[mf], bf + 4);
                mma16(acc[mf][3], af[mf], bf + 6);
            }
        }
    }

    // fused combine: out[token] += w * acc
#pragma unroll
    for (int mf = 0; mf < 4; mf++) {
        int rbase = warpM * 64 + mf * 16 + (lane >> 2);
#pragma unroll
        for (int nf = 0; nf < 4; nf++) {
            int col = bx * 128 + warpN * 32 + nf * 8 + 2 * (lane & 3);
#pragma unroll
            for (int h = 0; h < 2; h++) {
                int r = rbase + h * 8;
                if (r < valid) {
                    float wv = wt2[r];
                    float* op = out + (size_t)tok2[r] * HH + col;
                    atomicAdd(op,     wv * acc[mf][nf][h * 2 + 0]);
                    atomicAdd(op + 1, wv * acc[mf][nf][h * 2 + 1]);
                }
            }
        }
    }
}

// ---------------- aux: importance reduction + scalar ----------------
__global__ void aux_kernel(float* __restrict__ out, int out_size) {
    __shared__ float simp[EE];
    int tid = threadIdx.x, lane = tid & 31, w = tid >> 5;   // 256 thr, 8 warps
    // warp w reduces expert w over all tokens
    float s = 0.0f;
    for (int t = lane; t < TT; t += 32) s += g_probs[t * EE + w];
#pragma unroll
    for (int o = 16; o; o >>= 1) s += __shfl_xor_sync(0xffffffffu, s, o);
    if (lane == 0) simp[w] = s;
    __syncthreads();
    if (tid == 0 && out_size >= TT * HH + 1) {
        float a = 0.0f;
        for (int e = 0; e < EE; e++) {
            float usage = (float)g_keptcnt[e] / (float)(TT * KK);
            float imp = simp[e] / (float)TT;
            a += usage * imp;
        }
        a *= (float)EE;
        if (g_dropped > 0.0f) a += g_dropped / (float)TT * 0.1f;
        a = fminf(a, 1.0f) * 0.001f;
        out[TT * HH] = a;
    }
}

// ---------------- launch ----------------
extern "C" void kernel_launch(void* const* d_in, const int* in_sizes, int n_in,
                              void* d_out, int out_size) {
    const float* x      = (const float*)d_in[0];
    const float* w_gate = (const float*)d_in[1];
    const float* w1     = (const float*)d_in[2];
    const float* w3     = (const float*)d_in[3];
    const float* w2     = (const float*)d_in[4];
    float* out = (float*)d_out;

    cudaFuncSetAttribute(gemm1_mma, cudaFuncAttributeMaxDynamicSharedMemorySize, G1_SMEM);
    cudaFuncSetAttribute(gemm2_mma, cudaFuncAttributeMaxDynamicSharedMemorySize, G2_SMEM);

    __half* w1h_p; cudaGetSymbolAddress((void**)&w1h_p, g_w1h);
    __half* w3h_p; cudaGetSymbolAddress((void**)&w3h_p, g_w3h);
    __half* w2h_p; cudaGetSymbolAddress((void**)&w2h_p, g_w2h);

    const int NW8 = (EE * HH * II) / 8;   // 1179648

    zero_out_kernel<<<(out_size + 255) / 256, 256>>>(out, out_size);
    cvth3_kernel<<<dim3((NW8 + 255) / 256, 3), 256>>>(
        (const float4*)w1, (const float4*)w3, (const float4*)w2,
        (uint4*)w1h_p, (uint4*)w3h_p, (uint4*)w2h_p, NW8);
    routing_kernel<<<TT / 16, 512>>>(x, w_gate);
    scan_kernel<<<1, 1024>>>();
    gemm1_mma<<<dim3(II / 64, SLOTS / 128, EE), 256, G1_SMEM>>>();
    gemm2_mma<<<dim3(HH / 128, SLOTS / 128, EE), 256, G2_SMEM>>>(out);
    aux_kernel<<<1, 256>>>(out, out_size);
}